// round 1
// baseline (speedup 1.0000x reference)
#include <cuda_runtime.h>

// ---------------------------------------------------------------------------
// Problem constants
// ---------------------------------------------------------------------------
#define HH      128
#define WW      128
#define MM      16
#define CIN     128
#define NC      7
#define HID     256
#define STY     256
#define COL     64
#define HWPIX   (HH * WW)            // 16384
#define S_TOT   (HWPIX * MM)         // 262144

// ---------------------------------------------------------------------------
// Scratch (device globals; no runtime allocation allowed)
// ---------------------------------------------------------------------------
__device__ float d_fa[(size_t)S_TOT * HID];        // 256 MB
__device__ float d_fb[(size_t)S_TOT * HID];        // 256 MB
__device__ float d_sig[S_TOT];
__device__ float d_cbuf[(size_t)S_TOT * COL];      // 64 MB
__device__ float d_feat[COL * HWPIX];              // 4 MB
__device__ float d_cnn_a[HID * HWPIX];             // 16 MB
__device__ float d_cnn_b[HID * HWPIX];
__device__ float d_cnn_c[HID * HWPIX];
__device__ float d_alpha[5 * HID];
__device__ float d_beta[5 * HID];
__device__ float d_zc[4 * HID];
__device__ float d_wmod[5 * HID * HID];            // alpha-folded ModLinear weights
__device__ float d_wt3[4 * 9 * HID * HID];         // transposed conv3x3 weights [conv][tap][O][K]

static __device__ __forceinline__ float lrelu(float v) {
    return v > 0.f ? v : 0.2f * v;
}

// ---------------------------------------------------------------------------
// Prep 1: alpha[5][256], beta[5][256], zc[1024] — one warp per 256-dot
// ---------------------------------------------------------------------------
__global__ void prep_vec(const float* __restrict__ z,
                         const float* __restrict__ wa, const float* __restrict__ ba,
                         const float* __restrict__ wb, const float* __restrict__ bb,
                         const float* __restrict__ wz, const float* __restrict__ bz) {
    int warp = (blockIdx.x * blockDim.x + threadIdx.x) >> 5;
    int lane = threadIdx.x & 31;
    if (warp >= 3584) return;
    const float* row;
    float bias;
    float* out;
    if (warp < 1280)      { row = wa + (size_t)warp * STY;          bias = ba[warp];      out = d_alpha + warp; }
    else if (warp < 2560) { int i = warp - 1280; row = wb + (size_t)i * STY; bias = bb[i]; out = d_beta + i; }
    else                  { int i = warp - 2560; row = wz + (size_t)i * STY; bias = bz[i]; out = d_zc + i; }
    float acc = 0.f;
    #pragma unroll
    for (int t = 0; t < 8; t++) acc += z[lane + 32 * t] * row[lane + 32 * t];
    #pragma unroll
    for (int off = 16; off; off >>= 1) acc += __shfl_xor_sync(0xFFFFFFFFu, acc, off);
    if (lane == 0) *out = acc + bias;
}

// Prep 2: wmod[i][o][k] = ml_w[i][o][k] * alpha[i][k]
__global__ void prep_fold(const float* __restrict__ mlw) {
    int idx = blockIdx.x * blockDim.x + threadIdx.x;
    if (idx >= 5 * HID * HID) return;
    int k = idx & (HID - 1);
    int i = idx >> 16;                 // idx / (256*256)
    d_wmod[idx] = mlw[idx] * d_alpha[i * HID + k];
}

// Prep 3: transpose [O][K][9] -> [9][O][K]
__global__ void prep_tw(const float* __restrict__ w, float* __restrict__ out) {
    int idx = blockIdx.x * blockDim.x + threadIdx.x;
    if (idx >= 9 * HID * HID) return;
    int tap = idx / (HID * HID);
    int ok  = idx - tap * (HID * HID);
    out[idx] = w[(size_t)ok * 9 + tap];
}

// ---------------------------------------------------------------------------
// MLP GEMM: C[s][o] = act( sum_k A[s][k]*W[o][k] + bias[o] (+ m-term) )
// 64x64 tile, BK=16, 256 threads, 4x4 microtile.
// ---------------------------------------------------------------------------
template<bool DO_LRELU, bool ADD_M>
__global__ void mlp_gemm(const float* __restrict__ A, const float* __restrict__ W,
                         const float* __restrict__ bias, float* __restrict__ C,
                         int K, int O,
                         const float* __restrict__ Mm, const float* __restrict__ Wma) {
    __shared__ float As[16][64];
    __shared__ float Ws[16][64];
    const int tid = threadIdx.x;
    const int s0 = blockIdx.x * 64;
    const int o0 = blockIdx.y * 64;
    const int tx = tid & 15, ty = tid >> 4;
    const int lr = tid >> 2, lc = (tid & 3) << 2;
    const float* Ap = A + (size_t)(s0 + lr) * K + lc;
    const float* Wp = W + (size_t)(o0 + lr) * K + lc;
    float acc[4][4] = {};
    for (int k0 = 0; k0 < K; k0 += 16) {
        float4 av = *reinterpret_cast<const float4*>(Ap + k0);
        float4 wv = *reinterpret_cast<const float4*>(Wp + k0);
        As[lc + 0][lr] = av.x; As[lc + 1][lr] = av.y; As[lc + 2][lr] = av.z; As[lc + 3][lr] = av.w;
        Ws[lc + 0][lr] = wv.x; Ws[lc + 1][lr] = wv.y; Ws[lc + 2][lr] = wv.z; Ws[lc + 3][lr] = wv.w;
        __syncthreads();
        #pragma unroll
        for (int kk = 0; kk < 16; kk++) {
            float4 a4 = *reinterpret_cast<const float4*>(&As[kk][ty << 2]);
            float4 b4 = *reinterpret_cast<const float4*>(&Ws[kk][tx << 2]);
            float ar[4] = {a4.x, a4.y, a4.z, a4.w};
            float br[4] = {b4.x, b4.y, b4.z, b4.w};
            #pragma unroll
            for (int i = 0; i < 4; i++)
                #pragma unroll
                for (int j = 0; j < 4; j++)
                    acc[i][j] += ar[i] * br[j];
        }
        __syncthreads();
    }
    float bj[4];
    #pragma unroll
    for (int j = 0; j < 4; j++) bj[j] = bias[o0 + (tx << 2) + j];
    #pragma unroll
    for (int i = 0; i < 4; i++) {
        int s = s0 + (ty << 2) + i;
        float v[4];
        #pragma unroll
        for (int j = 0; j < 4; j++) v[j] = acc[i][j] + bj[j];
        if (ADD_M) {
            float mr[NC];
            #pragma unroll
            for (int t = 0; t < NC; t++) mr[t] = Mm[(size_t)s * NC + t];
            #pragma unroll
            for (int j = 0; j < 4; j++) {
                int o = o0 + (tx << 2) + j;
                float e = 0.f;
                #pragma unroll
                for (int t = 0; t < NC; t++) e += mr[t] * Wma[(size_t)o * NC + t];
                v[j] += e;
            }
        }
        if (DO_LRELU) {
            #pragma unroll
            for (int j = 0; j < 4; j++) v[j] = lrelu(v[j]);
        }
        float4 o4 = {v[0], v[1], v[2], v[3]};
        *reinterpret_cast<float4*>(&C[(size_t)s * O + o0 + (tx << 2)]) = o4;
    }
}

// ---------------------------------------------------------------------------
// sigma[s] = wsig . f[s] + bsig  (one warp per s)
// ---------------------------------------------------------------------------
__global__ void sigma_kernel(const float* __restrict__ f, const float* __restrict__ wsig,
                             const float* __restrict__ bsig, float* __restrict__ out) {
    int warp = (blockIdx.x * blockDim.x + threadIdx.x) >> 5;
    int lane = threadIdx.x & 31;
    if (warp >= S_TOT) return;
    const float* fr = f + (size_t)warp * HID;
    float acc = 0.f;
    #pragma unroll
    for (int t = 0; t < 8; t++) acc += fr[lane + 32 * t] * wsig[lane + 32 * t];
    #pragma unroll
    for (int off = 16; off; off >>= 1) acc += __shfl_xor_sync(0xFFFFFFFFu, acc, off);
    if (lane == 0) out[warp] = acc + bsig[0];
}

// ---------------------------------------------------------------------------
// Volumetric compositing: feat[c][pix] = sum_m wgt[m] * cbuf[pix*16+m][c]
// ---------------------------------------------------------------------------
__global__ void composite_kernel(const float* __restrict__ sigma, const float* __restrict__ dists,
                                 const float* __restrict__ cbuf, float* __restrict__ feat) {
    int pix = blockIdx.x;
    int t = threadIdx.x;  // channel 0..63
    __shared__ float wgt[MM];
    if (t == 0) {
        float T = 1.f;
        #pragma unroll
        for (int m = 0; m < MM; m++) {
            float sg = sigma[pix * MM + m];
            sg = sg > 0.f ? sg : 0.f;
            float a = 1.f - expf(-sg * dists[pix * MM + m]);
            wgt[m] = a * T;
            T *= (1.f - a + 1e-10f);
        }
    }
    __syncthreads();
    float acc = 0.f;
    #pragma unroll
    for (int m = 0; m < MM; m++)
        acc += wgt[m] * cbuf[(size_t)(pix * MM + m) * COL + t];
    feat[t * HWPIX + pix] = acc;
}

// ---------------------------------------------------------------------------
// CNN conv (1x1 or 3x3 via 9 shifted taps). NCHW in/out [O or K][HWPIX].
// Out[o][p] = epi( sum_tap sum_k Wt[tap][o][k] * In[k][shift(p,tap)] )
// ---------------------------------------------------------------------------
template<int TAPS, int K, bool HAS_BIAS, bool HAS_RES, bool HAS_MOD, bool DO_LRELU>
__global__ void conv_kernel(const float* __restrict__ In, const float* __restrict__ Wt,
                            const float* __restrict__ bias, const float* __restrict__ res,
                            const float* __restrict__ zc, int modoff,
                            float* __restrict__ Out) {
    __shared__ float Ws[16][64];   // weights [kk][o]
    __shared__ float Is[16][64];   // input   [kk][p]
    const int tid = threadIdx.x;
    const int p0 = blockIdx.x * 64;
    const int o0 = blockIdx.y * 64;
    const int tx = tid & 15, ty = tid >> 4;
    const int wlr = tid >> 2, wlc = (tid & 3) << 2;
    const int ikk = tid >> 4, ic = (tid & 15) << 2;
    const int ybase = p0 >> 7;
    const int x0 = p0 & 127;
    float acc[4][4] = {};
    #pragma unroll 1
    for (int tap = 0; tap < TAPS; tap++) {
        const int dy = (TAPS == 9) ? (tap / 3 - 1) : 0;
        const int dx = (TAPS == 9) ? (tap % 3 - 1) : 0;
        const int yy = ybase + dy;
        const bool yok = (yy >= 0 && yy < HH);
        const float* Wp = Wt + (size_t)tap * (HID * K) + (size_t)(o0 + wlr) * K + wlc;
        for (int k0 = 0; k0 < K; k0 += 16) {
            float4 wv = *reinterpret_cast<const float4*>(Wp + k0);
            Ws[wlc + 0][wlr] = wv.x; Ws[wlc + 1][wlr] = wv.y;
            Ws[wlc + 2][wlr] = wv.z; Ws[wlc + 3][wlr] = wv.w;
            #pragma unroll
            for (int j = 0; j < 4; j++) {
                int xx = x0 + ic + j + dx;
                float v = 0.f;
                if (yok && xx >= 0 && xx < WW)
                    v = In[(size_t)(k0 + ikk) * HWPIX + yy * WW + xx];
                Is[ikk][ic + j] = v;
            }
            __syncthreads();
            #pragma unroll
            for (int kk = 0; kk < 16; kk++) {
                float4 a4 = *reinterpret_cast<const float4*>(&Ws[kk][ty << 2]);
                float4 b4 = *reinterpret_cast<const float4*>(&Is[kk][tx << 2]);
                float ar[4] = {a4.x, a4.y, a4.z, a4.w};
                float br[4] = {b4.x, b4.y, b4.z, b4.w};
                #pragma unroll
                for (int i = 0; i < 4; i++)
                    #pragma unroll
                    for (int j = 0; j < 4; j++)
                        acc[i][j] += ar[i] * br[j];
            }
            __syncthreads();
        }
    }
    #pragma unroll
    for (int i = 0; i < 4; i++) {
        int o = o0 + (ty << 2) + i;
        float b0 = HAS_BIAS ? bias[o] : 0.f;
        float sc = HAS_MOD ? (zc[modoff + o] + 1.f) : 1.f;
        float sh = HAS_MOD ? zc[modoff + HID + o] : 0.f;
        float v[4];
        #pragma unroll
        for (int j = 0; j < 4; j++) v[j] = acc[i][j] + b0;
        if (HAS_RES) {
            float4 r = *reinterpret_cast<const float4*>(&res[(size_t)o * HWPIX + p0 + (tx << 2)]);
            v[0] += r.x; v[1] += r.y; v[2] += r.z; v[3] += r.w;
        }
        if (HAS_MOD) {
            #pragma unroll
            for (int j = 0; j < 4; j++) v[j] = v[j] * sc + sh;
        }
        if (DO_LRELU) {
            #pragma unroll
            for (int j = 0; j < 4; j++) v[j] = lrelu(v[j]);
        }
        float4 o4 = {v[0], v[1], v[2], v[3]};
        *reinterpret_cast<float4*>(&Out[(size_t)o * HWPIX + p0 + (tx << 2)]) = o4;
    }
}

// ---------------------------------------------------------------------------
// Final 1x1 conv to 3 channels
// ---------------------------------------------------------------------------
__global__ void final_conv(const float* __restrict__ In, const float* __restrict__ w,
                           const float* __restrict__ b, float* __restrict__ out) {
    __shared__ float ws[3 * HID];
    for (int i = threadIdx.x; i < 3 * HID; i += blockDim.x) ws[i] = w[i];
    __syncthreads();
    int p = blockIdx.x * blockDim.x + threadIdx.x;
    if (p >= HWPIX) return;
    float a0 = 0.f, a1 = 0.f, a2 = 0.f;
    for (int k = 0; k < HID; k++) {
        float v = In[(size_t)k * HWPIX + p];
        a0 += v * ws[k];
        a1 += v * ws[HID + k];
        a2 += v * ws[2 * HID + k];
    }
    out[p]             = a0 + b[0];
    out[HWPIX + p]     = a1 + b[1];
    out[2 * HWPIX + p] = a2 + b[2];
}

// ---------------------------------------------------------------------------
// Launch
// ---------------------------------------------------------------------------
extern "C" void kernel_launch(void* const* d_in, const int* in_sizes, int n_in,
                              void* d_out, int out_size) {
    const float* x     = (const float*)d_in[0];
    const float* m     = (const float*)d_in[1];
    const float* z     = (const float*)d_in[2];
    const float* dists = (const float*)d_in[3];
    const float* w1    = (const float*)d_in[4];
    const float* b1    = (const float*)d_in[5];
    const float* wma   = (const float*)d_in[6];
    const float* ml_w  = (const float*)d_in[7];
    const float* ml_wa = (const float*)d_in[8];
    const float* ml_ba = (const float*)d_in[9];
    const float* ml_wb = (const float*)d_in[10];
    const float* ml_bb = (const float*)d_in[11];
    const float* wsig  = (const float*)d_in[12];
    const float* bsig  = (const float*)d_in[13];
    const float* wc    = (const float*)d_in[14];
    const float* bc    = (const float*)d_in[15];
    const float* wz    = (const float*)d_in[16];
    const float* bz    = (const float*)d_in[17];
    const float* c1_w  = (const float*)d_in[18];
    const float* c1_b  = (const float*)d_in[19];
    const float* c2a_w = (const float*)d_in[20];
    const float* c2a_b = (const float*)d_in[21];
    const float* c2b_w = (const float*)d_in[22];
    const float* c3a_w = (const float*)d_in[23];
    const float* c3a_b = (const float*)d_in[24];
    const float* c3b_w = (const float*)d_in[25];
    const float* c4a_w = (const float*)d_in[26];
    const float* c4a_b = (const float*)d_in[27];
    const float* c4b_w = (const float*)d_in[28];
    const float* c4b_b = (const float*)d_in[29];
    const float* c4_w  = (const float*)d_in[30];
    const float* c4_b  = (const float*)d_in[31];
    float* out = (float*)d_out;

    float *fa, *fb, *sig, *cb, *feat, *ca, *cbn, *cc, *zcv, *wm, *wt;
    cudaGetSymbolAddress((void**)&fa,   d_fa);
    cudaGetSymbolAddress((void**)&fb,   d_fb);
    cudaGetSymbolAddress((void**)&sig,  d_sig);
    cudaGetSymbolAddress((void**)&cb,   d_cbuf);
    cudaGetSymbolAddress((void**)&feat, d_feat);
    cudaGetSymbolAddress((void**)&ca,   d_cnn_a);
    cudaGetSymbolAddress((void**)&cbn,  d_cnn_b);
    cudaGetSymbolAddress((void**)&cc,   d_cnn_c);
    cudaGetSymbolAddress((void**)&zcv,  d_zc);
    cudaGetSymbolAddress((void**)&wm,   d_wmod);
    cudaGetSymbolAddress((void**)&wt,   d_wt3);
    float* be;
    cudaGetSymbolAddress((void**)&be,   d_beta);

    const int TW = 9 * HID * HID;  // 589824

    // --- prep ---
    prep_vec<<<448, 256>>>(z, ml_wa, ml_ba, ml_wb, ml_bb, wz, bz);
    prep_fold<<<(5 * HID * HID + 255) / 256, 256>>>(ml_w);
    prep_tw<<<(TW + 255) / 256, 256>>>(c2a_w, wt + 0 * TW);
    prep_tw<<<(TW + 255) / 256, 256>>>(c2b_w, wt + 1 * TW);
    prep_tw<<<(TW + 255) / 256, 256>>>(c3a_w, wt + 2 * TW);
    prep_tw<<<(TW + 255) / 256, 256>>>(c3b_w, wt + 3 * TW);

    // --- MLP ---
    dim3 gM(S_TOT / 64, HID / 64);
    mlp_gemm<true, true ><<<gM, 256>>>(x,  w1,            b1,        fa, CIN, HID, m, wma);
    mlp_gemm<true, false><<<gM, 256>>>(fa, wm + 0 * 65536, be + 0,    fb, HID, HID, nullptr, nullptr);
    mlp_gemm<true, false><<<gM, 256>>>(fb, wm + 1 * 65536, be + 256,  fa, HID, HID, nullptr, nullptr);
    mlp_gemm<true, false><<<gM, 256>>>(fa, wm + 2 * 65536, be + 512,  fb, HID, HID, nullptr, nullptr);
    sigma_kernel<<<S_TOT / 8, 256>>>(fb, wsig, bsig, sig);
    mlp_gemm<true, false><<<gM, 256>>>(fb, wm + 3 * 65536, be + 768,  fa, HID, HID, nullptr, nullptr);
    mlp_gemm<true, false><<<gM, 256>>>(fa, wm + 4 * 65536, be + 1024, fb, HID, HID, nullptr, nullptr);
    mlp_gemm<false, false><<<dim3(S_TOT / 64, 1), 256>>>(fb, wc, bc, cb, HID, COL, nullptr, nullptr);

    // --- compositing ---
    composite_kernel<<<HWPIX, 64>>>(sig, dists, cb, feat);

    // --- CNN ---
    dim3 gC(HWPIX / 64, HID / 64);
    conv_kernel<1, COL, true,  false, false, true><<<gC, 256>>>(feat, c1_w, c1_b, nullptr, nullptr, 0, ca);
    conv_kernel<9, HID, true,  false, false, true><<<gC, 256>>>(ca,  wt + 0 * TW, c2a_b, nullptr, nullptr, 0, cbn);
    conv_kernel<9, HID, false, true,  true,  true><<<gC, 256>>>(cbn, wt + 1 * TW, nullptr, ca, zcv, 0,   cc);
    conv_kernel<9, HID, true,  false, false, true><<<gC, 256>>>(cc,  wt + 2 * TW, c3a_b, nullptr, nullptr, 0, cbn);
    conv_kernel<9, HID, false, true,  true,  true><<<gC, 256>>>(cbn, wt + 3 * TW, nullptr, cc, zcv, 512, ca);
    conv_kernel<1, HID, true,  false, false, true><<<gC, 256>>>(ca,  c4a_w, c4a_b, nullptr, nullptr, 0, cbn);
    conv_kernel<1, HID, true,  true,  false, true><<<gC, 256>>>(cbn, c4b_w, c4b_b, ca, nullptr, 0, cc);
    final_conv<<<HWPIX / 256, 256>>>(cc, c4_w, c4_b, out);

    (void)in_sizes; (void)n_in; (void)out_size;
}

// round 3
// speedup vs baseline: 1.5396x; 1.5396x over previous
#include <cuda_runtime.h>
#include <cuda_bf16.h>
#include <cstdint>

// ---------------------------------------------------------------------------
// Problem constants
// ---------------------------------------------------------------------------
#define HH      128
#define WW      128
#define MM      16
#define CIN     128
#define NC      7
#define HID     256
#define STY     256
#define COL     64
#define HWPIX   (HH * WW)            // 16384
#define S_TOT   (HWPIX * MM)         // 262144
#define KP1     160                  // padded K for layer 1: 128 (x) + 7 (m) + 25 zeros

// ---------------------------------------------------------------------------
// Scratch (device globals; no runtime allocation allowed)
// ---------------------------------------------------------------------------
__device__ __nv_bfloat16 d_xph[(size_t)S_TOT * KP1];
__device__ __nv_bfloat16 d_xpl[(size_t)S_TOT * KP1];
__device__ __nv_bfloat16 d_pah[(size_t)S_TOT * HID];
__device__ __nv_bfloat16 d_pal[(size_t)S_TOT * HID];
__device__ __nv_bfloat16 d_pbh[(size_t)S_TOT * HID];
__device__ __nv_bfloat16 d_pbl[(size_t)S_TOT * HID];
__device__ __nv_bfloat16 d_w1h[HID * KP1];
__device__ __nv_bfloat16 d_w1l[HID * KP1];
__device__ __nv_bfloat16 d_wmh[5 * HID * HID];
__device__ __nv_bfloat16 d_wml[5 * HID * HID];
__device__ __nv_bfloat16 d_wch[COL * HID];
__device__ __nv_bfloat16 d_wcl[COL * HID];
__device__ float d_sig[S_TOT];
__device__ float d_cbuf[(size_t)S_TOT * COL];
__device__ float d_feat[COL * HWPIX];
__device__ float d_cnn_a[HID * HWPIX];
__device__ float d_cnn_b[HID * HWPIX];
__device__ float d_cnn_c[HID * HWPIX];
__device__ float d_alpha[5 * HID];
__device__ float d_beta[5 * HID];
__device__ float d_zc[4 * HID];
__device__ float d_wt3[4 * 9 * HID * HID];

static __device__ __forceinline__ float lrelu(float v) {
    return v > 0.f ? v : 0.2f * v;
}

static __device__ __forceinline__ uint32_t smem_u32(const void* p) {
    uint32_t a;
    asm("{ .reg .u64 t; cvta.to.shared.u64 t, %1; cvt.u32.u64 %0, t; }" : "=r"(a) : "l"(p));
    return a;
}

static __device__ __forceinline__ void cpa16(uint32_t dst, const void* src) {
    asm volatile("cp.async.cg.shared.global [%0], [%1], 16;" :: "r"(dst), "l"(src));
}

static __device__ __forceinline__ uint32_t lds32(uint32_t a) {
    uint32_t v;
    asm volatile("ld.shared.b32 %0, [%1];" : "=r"(v) : "r"(a));
    return v;
}

static __device__ __forceinline__ void mma16816(float* d, const uint32_t* a, const uint32_t* b) {
    asm volatile(
        "mma.sync.aligned.m16n8k16.row.col.f32.bf16.bf16.f32 "
        "{%0,%1,%2,%3}, {%4,%5,%6,%7}, {%8,%9}, {%0,%1,%2,%3};"
        : "+f"(d[0]), "+f"(d[1]), "+f"(d[2]), "+f"(d[3])
        : "r"(a[0]), "r"(a[1]), "r"(a[2]), "r"(a[3]), "r"(b[0]), "r"(b[1]));
}

// ---------------------------------------------------------------------------
// Prep kernels
// ---------------------------------------------------------------------------
__global__ void prep_vec(const float* __restrict__ z,
                         const float* __restrict__ wa, const float* __restrict__ ba,
                         const float* __restrict__ wb, const float* __restrict__ bb,
                         const float* __restrict__ wz, const float* __restrict__ bz) {
    int warp = (blockIdx.x * blockDim.x + threadIdx.x) >> 5;
    int lane = threadIdx.x & 31;
    if (warp >= 3584) return;
    const float* row; float bias; float* out;
    if (warp < 1280)      { row = wa + (size_t)warp * STY; bias = ba[warp]; out = d_alpha + warp; }
    else if (warp < 2560) { int i = warp - 1280; row = wb + (size_t)i * STY; bias = bb[i]; out = d_beta + i; }
    else                  { int i = warp - 2560; row = wz + (size_t)i * STY; bias = bz[i]; out = d_zc + i; }
    float acc = 0.f;
    #pragma unroll
    for (int t = 0; t < 8; t++) acc += z[lane + 32 * t] * row[lane + 32 * t];
    #pragma unroll
    for (int off = 16; off; off >>= 1) acc += __shfl_xor_sync(0xFFFFFFFFu, acc, off);
    if (lane == 0) *out = acc + bias;
}

static __device__ __forceinline__ void split_store(float v, __nv_bfloat16* hi,
                                                   __nv_bfloat16* lo, size_t idx) {
    __nv_bfloat16 h = __float2bfloat16(v);
    hi[idx] = h;
    lo[idx] = __float2bfloat16(v - __bfloat162float(h));
}

__global__ void prep_fold_split(const float* __restrict__ mlw) {
    int idx = blockIdx.x * blockDim.x + threadIdx.x;
    if (idx >= 5 * HID * HID) return;
    int k = idx & (HID - 1);
    int i = idx >> 16;
    float w = mlw[idx] * d_alpha[i * HID + k];
    split_store(w, d_wmh, d_wml, idx);
}

__global__ void prep_w1p(const float* __restrict__ w1, const float* __restrict__ wma) {
    int idx = blockIdx.x * blockDim.x + threadIdx.x;
    if (idx >= HID * KP1) return;
    int o = idx / KP1, c = idx - o * KP1;
    float v = 0.f;
    if (c < CIN)          v = w1[(size_t)o * CIN + c];
    else if (c < CIN + NC) v = wma[(size_t)o * NC + (c - CIN)];
    split_store(v, d_w1h, d_w1l, idx);
}

__global__ void prep_wc_split(const float* __restrict__ wc) {
    int idx = blockIdx.x * blockDim.x + threadIdx.x;
    if (idx >= COL * HID) return;
    split_store(wc[idx], d_wch, d_wcl, idx);
}

__global__ void prep_xm(const float* __restrict__ x, const float* __restrict__ m) {
    size_t idx = (size_t)blockIdx.x * blockDim.x + threadIdx.x;
    if (idx >= (size_t)S_TOT * KP1) return;
    int c = (int)(idx % KP1);
    size_t s = idx / KP1;
    float v = 0.f;
    if (c < CIN)           v = x[s * CIN + c];
    else if (c < CIN + NC) v = m[s * NC + (c - CIN)];
    split_store(v, d_xph, d_xpl, idx);
}

__global__ void prep_tw(const float* __restrict__ w, float* __restrict__ out) {
    int idx = blockIdx.x * blockDim.x + threadIdx.x;
    if (idx >= 9 * HID * HID) return;
    int tap = idx / (HID * HID);
    int ok  = idx - tap * (HID * HID);
    out[idx] = w[(size_t)ok * 9 + tap];
}

// ---------------------------------------------------------------------------
// bf16x3 GEMM via mma.sync.m16n8k16 (sm_80 path — works on sm_100 base target)
// C[s][o] = epi( sum_k (Ah+Al)[s][k] * (Bh+Bl)[o][k] ), drop Al*Bl term.
// Slabs in smem:  A = (Ah, Al, Ah),  B = (Bh, Bh, Bl)  — plain GEMM, K' = 3K.
// CTA: 256 threads, tile M=128 x NT.  Rows padded to 80B (20 words): rows
// 0..7 x words 0..3 hit 32 distinct banks — conflict-free fragment loads.
// ---------------------------------------------------------------------------
template<int K, int NT, bool LRELU, bool SPLIT_OUT>
__global__ void __launch_bounds__(256)
mma_gemm(const __nv_bfloat16* __restrict__ Ahi, const __nv_bfloat16* __restrict__ Alo,
         const __nv_bfloat16* __restrict__ Bhi, const __nv_bfloat16* __restrict__ Blo,
         const float* __restrict__ bias,
         __nv_bfloat16* __restrict__ Chi, __nv_bfloat16* __restrict__ Clo,
         float* __restrict__ Cf, int OC) {
    extern __shared__ char smem[];
    constexpr int ASLAB = 128 * 80;
    constexpr int BSLAB = NT * 80;
    constexpr int BOFF  = 3 * ASLAB;
    constexpr int BUF   = 3 * ASLAB + 3 * BSLAB;
    constexpr int WN    = NT / 32;          // warps along N (4 or 2)
    constexpr int MI    = (128 * WN) / (8 * 16); // m-atoms per warp (4 or 2)
    constexpr int MWT   = MI * 16;          // M rows per warp
    constexpr int NCH   = K / 32;

    const uint32_t sb = smem_u32(smem);
    const int tid = threadIdx.x;
    const int lane = tid & 31, wid = tid >> 5;
    const int wn = wid % WN, wm = wid / WN;
    const int g = lane >> 2, q = lane & 3;
    const int s0 = blockIdx.x * 128;
    const int o0 = blockIdx.y * NT;

    auto load_chunk = [&](int buf, int k0) {
        uint32_t base = sb + buf * BUF;
        for (int idx = tid; idx < 512; idx += 256) {
            int row = idx >> 2, c = idx & 3;
            size_t go = (size_t)(s0 + row) * K + k0 + c * 8;
            uint32_t d = base + row * 80 + c * 16;
            cpa16(d,             Ahi + go);
            cpa16(d + ASLAB,     Alo + go);
            cpa16(d + 2 * ASLAB, Ahi + go);
        }
        for (int idx = tid; idx < NT * 4; idx += 256) {
            int row = idx >> 2, c = idx & 3;
            size_t go = (size_t)(o0 + row) * K + k0 + c * 8;
            uint32_t d = base + BOFF + row * 80 + c * 16;
            cpa16(d,             Bhi + go);
            cpa16(d + BSLAB,     Bhi + go);
            cpa16(d + 2 * BSLAB, Blo + go);
        }
        asm volatile("cp.async.commit_group;" ::: "memory");
    };

    float acc[MI][4][4];
    #pragma unroll
    for (int i = 0; i < MI; i++)
        #pragma unroll
        for (int j = 0; j < 4; j++)
            #pragma unroll
            for (int r = 0; r < 4; r++) acc[i][j][r] = 0.f;

    load_chunk(0, 0);
    for (int cc = 0; cc < NCH; cc++) {
        if (cc + 1 < NCH) {
            load_chunk((cc + 1) & 1, (cc + 1) * 32);
            asm volatile("cp.async.wait_group 1;" ::: "memory");
        } else {
            asm volatile("cp.async.wait_group 0;" ::: "memory");
        }
        __syncthreads();
        const uint32_t Ab = sb + (cc & 1) * BUF;
        const uint32_t Bb = Ab + BOFF;
        #pragma unroll
        for (int kk = 0; kk < 6; kk++) {
            const int slab = kk >> 1, ko = (kk & 1) * 32;
            uint32_t a[MI][4];
            const uint32_t abase = Ab + slab * ASLAB + ko + q * 4 + (wm * MWT + g) * 80;
            #pragma unroll
            for (int i = 0; i < MI; i++) {
                uint32_t r = abase + i * (16 * 80);
                a[i][0] = lds32(r);
                a[i][1] = lds32(r + 8 * 80);
                a[i][2] = lds32(r + 16);
                a[i][3] = lds32(r + 8 * 80 + 16);
            }
            uint32_t b[4][2];
            const uint32_t bbase = Bb + slab * BSLAB + ko + q * 4 + (wn * 32 + g) * 80;
            #pragma unroll
            for (int j = 0; j < 4; j++) {
                uint32_t r = bbase + j * (8 * 80);
                b[j][0] = lds32(r);
                b[j][1] = lds32(r + 16);
            }
            #pragma unroll
            for (int i = 0; i < MI; i++)
                #pragma unroll
                for (int j = 0; j < 4; j++)
                    mma16816(acc[i][j], a[i], b[j]);
        }
        __syncthreads();
    }

    // Epilogue
    #pragma unroll
    for (int j = 0; j < 4; j++) {
        const int col0 = o0 + wn * 32 + j * 8 + q * 2;
        const float b0 = bias[col0], b1 = bias[col0 + 1];
        #pragma unroll
        for (int i = 0; i < MI; i++) {
            #pragma unroll
            for (int h = 0; h < 2; h++) {
                const int row = s0 + wm * MWT + i * 16 + g + h * 8;
                float v0 = acc[i][j][h * 2 + 0] + b0;
                float v1 = acc[i][j][h * 2 + 1] + b1;
                if (LRELU) { v0 = lrelu(v0); v1 = lrelu(v1); }
                if (SPLIT_OUT) {
                    __nv_bfloat162 hp = __floats2bfloat162_rn(v0, v1);
                    float r0 = v0 - __bfloat162float(hp.x);
                    float r1 = v1 - __bfloat162float(hp.y);
                    __nv_bfloat162 lp = __floats2bfloat162_rn(r0, r1);
                    *reinterpret_cast<__nv_bfloat162*>(Chi + (size_t)row * OC + col0) = hp;
                    *reinterpret_cast<__nv_bfloat162*>(Clo + (size_t)row * OC + col0) = lp;
                } else {
                    float2 v = {v0, v1};
                    *reinterpret_cast<float2*>(Cf + (size_t)row * OC + col0) = v;
                }
            }
        }
    }
}

// ---------------------------------------------------------------------------
// sigma[s] = wsig . (fhi+flo)[s] + bsig
// ---------------------------------------------------------------------------
__global__ void sigma_kernel(const __nv_bfloat16* __restrict__ fhi,
                             const __nv_bfloat16* __restrict__ flo,
                             const float* __restrict__ wsig,
                             const float* __restrict__ bsig, float* __restrict__ out) {
    int warp = (blockIdx.x * blockDim.x + threadIdx.x) >> 5;
    int lane = threadIdx.x & 31;
    if (warp >= S_TOT) return;
    const __nv_bfloat16* fh = fhi + (size_t)warp * HID;
    const __nv_bfloat16* fl = flo + (size_t)warp * HID;
    float acc = 0.f;
    #pragma unroll
    for (int t = 0; t < 8; t++) {
        int i = lane + 32 * t;
        acc += (__bfloat162float(fh[i]) + __bfloat162float(fl[i])) * wsig[i];
    }
    #pragma unroll
    for (int off = 16; off; off >>= 1) acc += __shfl_xor_sync(0xFFFFFFFFu, acc, off);
    if (lane == 0) out[warp] = acc + bsig[0];
}

// ---------------------------------------------------------------------------
// Volumetric compositing
// ---------------------------------------------------------------------------
__global__ void composite_kernel(const float* __restrict__ sigma, const float* __restrict__ dists,
                                 const float* __restrict__ cbuf, float* __restrict__ feat) {
    int pix = blockIdx.x;
    int t = threadIdx.x;
    __shared__ float wgt[MM];
    if (t == 0) {
        float T = 1.f;
        #pragma unroll
        for (int m = 0; m < MM; m++) {
            float sg = sigma[pix * MM + m];
            sg = sg > 0.f ? sg : 0.f;
            float a = 1.f - expf(-sg * dists[pix * MM + m]);
            wgt[m] = a * T;
            T *= (1.f - a + 1e-10f);
        }
    }
    __syncthreads();
    float acc = 0.f;
    #pragma unroll
    for (int m = 0; m < MM; m++)
        acc += wgt[m] * cbuf[(size_t)(pix * MM + m) * COL + t];
    feat[t * HWPIX + pix] = acc;
}

// ---------------------------------------------------------------------------
// CNN conv (SIMT, proven in R1)
// ---------------------------------------------------------------------------
template<int TAPS, int K, bool HAS_BIAS, bool HAS_RES, bool HAS_MOD, bool DO_LRELU>
__global__ void conv_kernel(const float* __restrict__ In, const float* __restrict__ Wt,
                            const float* __restrict__ bias, const float* __restrict__ res,
                            const float* __restrict__ zc, int modoff,
                            float* __restrict__ Out) {
    __shared__ float Ws[16][64];
    __shared__ float Is[16][64];
    const int tid = threadIdx.x;
    const int p0 = blockIdx.x * 64;
    const int o0 = blockIdx.y * 64;
    const int tx = tid & 15, ty = tid >> 4;
    const int wlr = tid >> 2, wlc = (tid & 3) << 2;
    const int ikk = tid >> 4, ic = (tid & 15) << 2;
    const int ybase = p0 >> 7;
    const int x0 = p0 & 127;
    float acc[4][4] = {};
    #pragma unroll 1
    for (int tap = 0; tap < TAPS; tap++) {
        const int dy = (TAPS == 9) ? (tap / 3 - 1) : 0;
        const int dx = (TAPS == 9) ? (tap % 3 - 1) : 0;
        const int yy = ybase + dy;
        const bool yok = (yy >= 0 && yy < HH);
        const float* Wp = Wt + (size_t)tap * (HID * K) + (size_t)(o0 + wlr) * K + wlc;
        for (int k0 = 0; k0 < K; k0 += 16) {
            float4 wv = *reinterpret_cast<const float4*>(Wp + k0);
            Ws[wlc + 0][wlr] = wv.x; Ws[wlc + 1][wlr] = wv.y;
            Ws[wlc + 2][wlr] = wv.z; Ws[wlc + 3][wlr] = wv.w;
            #pragma unroll
            for (int j = 0; j < 4; j++) {
                int xx = x0 + ic + j + dx;
                float v = 0.f;
                if (yok && xx >= 0 && xx < WW)
                    v = In[(size_t)(k0 + ikk) * HWPIX + yy * WW + xx];
                Is[ikk][ic + j] = v;
            }
            __syncthreads();
            #pragma unroll
            for (int kk = 0; kk < 16; kk++) {
                float4 a4 = *reinterpret_cast<const float4*>(&Ws[kk][ty << 2]);
                float4 b4 = *reinterpret_cast<const float4*>(&Is[kk][tx << 2]);
                float ar[4] = {a4.x, a4.y, a4.z, a4.w};
                float br[4] = {b4.x, b4.y, b4.z, b4.w};
                #pragma unroll
                for (int i = 0; i < 4; i++)
                    #pragma unroll
                    for (int j = 0; j < 4; j++)
                        acc[i][j] += ar[i] * br[j];
            }
            __syncthreads();
        }
    }
    #pragma unroll
    for (int i = 0; i < 4; i++) {
        int o = o0 + (ty << 2) + i;
        float b0 = HAS_BIAS ? bias[o] : 0.f;
        float sc = HAS_MOD ? (zc[modoff + o] + 1.f) : 1.f;
        float sh = HAS_MOD ? zc[modoff + HID + o] : 0.f;
        float v[4];
        #pragma unroll
        for (int j = 0; j < 4; j++) v[j] = acc[i][j] + b0;
        if (HAS_RES) {
            float4 rr = *reinterpret_cast<const float4*>(&res[(size_t)o * HWPIX + p0 + (tx << 2)]);
            v[0] += rr.x; v[1] += rr.y; v[2] += rr.z; v[3] += rr.w;
        }
        if (HAS_MOD) {
            #pragma unroll
            for (int j = 0; j < 4; j++) v[j] = v[j] * sc + sh;
        }
        if (DO_LRELU) {
            #pragma unroll
            for (int j = 0; j < 4; j++) v[j] = lrelu(v[j]);
        }
        float4 o4 = {v[0], v[1], v[2], v[3]};
        *reinterpret_cast<float4*>(&Out[(size_t)o * HWPIX + p0 + (tx << 2)]) = o4;
    }
}

__global__ void final_conv(const float* __restrict__ In, const float* __restrict__ w,
                           const float* __restrict__ b, float* __restrict__ out) {
    __shared__ float ws[3 * HID];
    for (int i = threadIdx.x; i < 3 * HID; i += blockDim.x) ws[i] = w[i];
    __syncthreads();
    int p = blockIdx.x * blockDim.x + threadIdx.x;
    if (p >= HWPIX) return;
    float a0 = 0.f, a1 = 0.f, a2 = 0.f;
    for (int k = 0; k < HID; k++) {
        float v = In[(size_t)k * HWPIX + p];
        a0 += v * ws[k];
        a1 += v * ws[HID + k];
        a2 += v * ws[2 * HID + k];
    }
    out[p]             = a0 + b[0];
    out[HWPIX + p]     = a1 + b[1];
    out[2 * HWPIX + p] = a2 + b[2];
}

// ---------------------------------------------------------------------------
// Launch
// ---------------------------------------------------------------------------
extern "C" void kernel_launch(void* const* d_in, const int* in_sizes, int n_in,
                              void* d_out, int out_size) {
    const float* x     = (const float*)d_in[0];
    const float* m     = (const float*)d_in[1];
    const float* z     = (const float*)d_in[2];
    const float* dists = (const float*)d_in[3];
    const float* w1    = (const float*)d_in[4];
    const float* b1    = (const float*)d_in[5];
    const float* wma   = (const float*)d_in[6];
    const float* ml_w  = (const float*)d_in[7];
    const float* ml_wa = (const float*)d_in[8];
    const float* ml_ba = (const float*)d_in[9];
    const float* ml_wb = (const float*)d_in[10];
    const float* ml_bb = (const float*)d_in[11];
    const float* wsig  = (const float*)d_in[12];
    const float* bsig  = (const float*)d_in[13];
    const float* wc    = (const float*)d_in[14];
    const float* bc    = (const float*)d_in[15];
    const float* wz    = (const float*)d_in[16];
    const float* bz    = (const float*)d_in[17];
    const float* c1_w  = (const float*)d_in[18];
    const float* c1_b  = (const float*)d_in[19];
    const float* c2a_w = (const float*)d_in[20];
    const float* c2a_b = (const float*)d_in[21];
    const float* c2b_w = (const float*)d_in[22];
    const float* c3a_w = (const float*)d_in[23];
    const float* c3a_b = (const float*)d_in[24];
    const float* c3b_w = (const float*)d_in[25];
    const float* c4a_w = (const float*)d_in[26];
    const float* c4a_b = (const float*)d_in[27];
    const float* c4b_w = (const float*)d_in[28];
    const float* c4b_b = (const float*)d_in[29];
    const float* c4_w  = (const float*)d_in[30];
    const float* c4_b  = (const float*)d_in[31];
    float* out = (float*)d_out;

    __nv_bfloat16 *xph, *xpl, *pah, *pal, *pbh, *pbl, *w1h, *w1l, *wmh, *wml, *wch, *wcl;
    float *sig, *cb, *feat, *ca, *cbn, *cc, *zcv, *wt, *be;
    cudaGetSymbolAddress((void**)&xph, d_xph);
    cudaGetSymbolAddress((void**)&xpl, d_xpl);
    cudaGetSymbolAddress((void**)&pah, d_pah);
    cudaGetSymbolAddress((void**)&pal, d_pal);
    cudaGetSymbolAddress((void**)&pbh, d_pbh);
    cudaGetSymbolAddress((void**)&pbl, d_pbl);
    cudaGetSymbolAddress((void**)&w1h, d_w1h);
    cudaGetSymbolAddress((void**)&w1l, d_w1l);
    cudaGetSymbolAddress((void**)&wmh, d_wmh);
    cudaGetSymbolAddress((void**)&wml, d_wml);
    cudaGetSymbolAddress((void**)&wch, d_wch);
    cudaGetSymbolAddress((void**)&wcl, d_wcl);
    cudaGetSymbolAddress((void**)&sig,  d_sig);
    cudaGetSymbolAddress((void**)&cb,   d_cbuf);
    cudaGetSymbolAddress((void**)&feat, d_feat);
    cudaGetSymbolAddress((void**)&ca,   d_cnn_a);
    cudaGetSymbolAddress((void**)&cbn,  d_cnn_b);
    cudaGetSymbolAddress((void**)&cc,   d_cnn_c);
    cudaGetSymbolAddress((void**)&zcv,  d_zc);
    cudaGetSymbolAddress((void**)&wt,   d_wt3);
    cudaGetSymbolAddress((void**)&be,   d_beta);

    const int TW = 9 * HID * HID;
    const int SM128 = 2 * (3 * 128 * 80 + 3 * 128 * 80);   // 122880
    const int SM64  = 2 * (3 * 128 * 80 + 3 * 64 * 80);    // 92160

    cudaFuncSetAttribute(mma_gemm<KP1, 128, true,  true >, cudaFuncAttributeMaxDynamicSharedMemorySize, SM128);
    cudaFuncSetAttribute(mma_gemm<HID, 128, true,  true >, cudaFuncAttributeMaxDynamicSharedMemorySize, SM128);
    cudaFuncSetAttribute(mma_gemm<HID, 64,  false, false>, cudaFuncAttributeMaxDynamicSharedMemorySize, SM64);

    // --- prep ---
    prep_vec<<<448, 256>>>(z, ml_wa, ml_ba, ml_wb, ml_bb, wz, bz);
    prep_fold_split<<<(5 * HID * HID + 255) / 256, 256>>>(ml_w);
    prep_w1p<<<(HID * KP1 + 255) / 256, 256>>>(w1, wma);
    prep_wc_split<<<(COL * HID + 255) / 256, 256>>>(wc);
    prep_xm<<<(int)(((size_t)S_TOT * KP1 + 255) / 256), 256>>>(x, m);
    prep_tw<<<(TW + 255) / 256, 256>>>(c2a_w, wt + 0 * TW);
    prep_tw<<<(TW + 255) / 256, 256>>>(c2b_w, wt + 1 * TW);
    prep_tw<<<(TW + 255) / 256, 256>>>(c3a_w, wt + 2 * TW);
    prep_tw<<<(TW + 255) / 256, 256>>>(c3b_w, wt + 3 * TW);

    // --- MLP (bf16x3 mma.sync) ---
    dim3 g2(S_TOT / 128, 2);
    mma_gemm<KP1, 128, true, true><<<g2, 256, SM128>>>(xph, xpl, w1h, w1l, b1, pah, pal, nullptr, HID);
    mma_gemm<HID, 128, true, true><<<g2, 256, SM128>>>(pah, pal, wmh + 0 * 65536, wml + 0 * 65536, be + 0,    pbh, pbl, nullptr, HID);
    mma_gemm<HID, 128, true, true><<<g2, 256, SM128>>>(pbh, pbl, wmh + 1 * 65536, wml + 1 * 65536, be + 256,  pah, pal, nullptr, HID);
    mma_gemm<HID, 128, true, true><<<g2, 256, SM128>>>(pah, pal, wmh + 2 * 65536, wml + 2 * 65536, be + 512,  pbh, pbl, nullptr, HID);
    sigma_kernel<<<S_TOT / 8, 256>>>(pbh, pbl, wsig, bsig, sig);
    mma_gemm<HID, 128, true, true><<<g2, 256, SM128>>>(pbh, pbl, wmh + 3 * 65536, wml + 3 * 65536, be + 768,  pah, pal, nullptr, HID);
    mma_gemm<HID, 128, true, true><<<g2, 256, SM128>>>(pah, pal, wmh + 4 * 65536, wml + 4 * 65536, be + 1024, pbh, pbl, nullptr, HID);
    mma_gemm<HID, 64, false, false><<<dim3(S_TOT / 128, 1), 256, SM64>>>(pbh, pbl, wch, wcl, bc, nullptr, nullptr, cb, COL);

    // --- compositing ---
    composite_kernel<<<HWPIX, 64>>>(sig, dists, cb, feat);

    // --- CNN ---
    dim3 gC(HWPIX / 64, HID / 64);
    conv_kernel<1, COL, true,  false, false, true><<<gC, 256>>>(feat, c1_w, c1_b, nullptr, nullptr, 0, ca);
    conv_kernel<9, HID, true,  false, false, true><<<gC, 256>>>(ca,  wt + 0 * TW, c2a_b, nullptr, nullptr, 0, cbn);
    conv_kernel<9, HID, false, true,  true,  true><<<gC, 256>>>(cbn, wt + 1 * TW, nullptr, ca, zcv, 0,   cc);
    conv_kernel<9, HID, true,  false, false, true><<<gC, 256>>>(cc,  wt + 2 * TW, c3a_b, nullptr, nullptr, 0, cbn);
    conv_kernel<9, HID, false, true,  true,  true><<<gC, 256>>>(cbn, wt + 3 * TW, nullptr, cc, zcv, 512, ca);
    conv_kernel<1, HID, true,  false, false, true><<<gC, 256>>>(ca,  c4a_w, c4a_b, nullptr, nullptr, 0, cbn);
    conv_kernel<1, HID, true,  true,  false, true><<<gC, 256>>>(cbn, c4b_w, c4b_b, ca, nullptr, 0, cc);
    final_conv<<<HWPIX / 256, 256>>>(cc, c4_w, c4_b, out);

    (void)in_sizes; (void)n_in; (void)out_size;
}

// round 4
// speedup vs baseline: 2.7639x; 1.7953x over previous
#include <cuda_runtime.h>
#include <cuda_bf16.h>
#include <cstdint>

// ---------------------------------------------------------------------------
// Problem constants
// ---------------------------------------------------------------------------
#define HH      128
#define WW      128
#define MM      16
#define CIN     128
#define NC      7
#define HID     256
#define STY     256
#define COL     64
#define HWPIX   (HH * WW)            // 16384
#define S_TOT   (HWPIX * MM)         // 262144
#define KP1     160                  // padded K for layer 1: 128 (x) + 7 (m) + 25 zeros

// ---------------------------------------------------------------------------
// Scratch (device globals; no runtime allocation allowed)
// ---------------------------------------------------------------------------
__device__ __nv_bfloat16 d_xph[(size_t)S_TOT * KP1];
__device__ __nv_bfloat16 d_xpl[(size_t)S_TOT * KP1];
__device__ __nv_bfloat16 d_pah[(size_t)S_TOT * HID];
__device__ __nv_bfloat16 d_pal[(size_t)S_TOT * HID];
__device__ __nv_bfloat16 d_pbh[(size_t)S_TOT * HID];
__device__ __nv_bfloat16 d_pbl[(size_t)S_TOT * HID];
__device__ __nv_bfloat16 d_w1h[HID * KP1];
__device__ __nv_bfloat16 d_w1l[HID * KP1];
__device__ __nv_bfloat16 d_wmh[5 * HID * HID];
__device__ __nv_bfloat16 d_wml[5 * HID * HID];
__device__ __nv_bfloat16 d_wch[COL * HID];
__device__ __nv_bfloat16 d_wcl[COL * HID];
// CNN weights (bf16 hi/lo)
__device__ __nv_bfloat16 d_c3h[4 * 9 * HID * HID];
__device__ __nv_bfloat16 d_c3l[4 * 9 * HID * HID];
__device__ __nv_bfloat16 d_c1h[HID * COL];
__device__ __nv_bfloat16 d_c1l[HID * COL];
__device__ __nv_bfloat16 d_c4ah[HID * HID];
__device__ __nv_bfloat16 d_c4al[HID * HID];
__device__ __nv_bfloat16 d_c4bh[HID * HID];
__device__ __nv_bfloat16 d_c4bl[HID * HID];
// CNN activations: pixel-major [pix][chan], bf16 hi/lo
__device__ __nv_bfloat16 d_yah[HWPIX * HID];
__device__ __nv_bfloat16 d_yal[HWPIX * HID];
__device__ __nv_bfloat16 d_ybh[HWPIX * HID];
__device__ __nv_bfloat16 d_ybl[HWPIX * HID];
__device__ __nv_bfloat16 d_ych[HWPIX * HID];
__device__ __nv_bfloat16 d_ycl[HWPIX * HID];
__device__ __nv_bfloat16 d_feath[HWPIX * COL];
__device__ __nv_bfloat16 d_featl[HWPIX * COL];
__device__ float d_sig[S_TOT];
__device__ float d_cbuf[(size_t)S_TOT * COL];
__device__ float d_alpha[5 * HID];
__device__ float d_beta[5 * HID];
__device__ float d_zc[4 * HID];

static __device__ __forceinline__ float lrelu(float v) {
    return v > 0.f ? v : 0.2f * v;
}

static __device__ __forceinline__ uint32_t smem_u32(const void* p) {
    uint32_t a;
    asm("{ .reg .u64 t; cvta.to.shared.u64 t, %1; cvt.u32.u64 %0, t; }" : "=r"(a) : "l"(p));
    return a;
}

static __device__ __forceinline__ void cpa16z(uint32_t dst, const void* src, uint32_t sz) {
    asm volatile("cp.async.cg.shared.global [%0], [%1], 16, %2;"
                 :: "r"(dst), "l"(src), "r"(sz));
}

static __device__ __forceinline__ uint32_t lds32(uint32_t a) {
    uint32_t v;
    asm volatile("ld.shared.b32 %0, [%1];" : "=r"(v) : "r"(a));
    return v;
}

static __device__ __forceinline__ void mma16816(float* d, const uint32_t* a, const uint32_t* b) {
    asm volatile(
        "mma.sync.aligned.m16n8k16.row.col.f32.bf16.bf16.f32 "
        "{%0,%1,%2,%3}, {%4,%5,%6,%7}, {%8,%9}, {%0,%1,%2,%3};"
        : "+f"(d[0]), "+f"(d[1]), "+f"(d[2]), "+f"(d[3])
        : "r"(a[0]), "r"(a[1]), "r"(a[2]), "r"(a[3]), "r"(b[0]), "r"(b[1]));
}

// ---------------------------------------------------------------------------
// Prep kernels
// ---------------------------------------------------------------------------
__global__ void prep_vec(const float* __restrict__ z,
                         const float* __restrict__ wa, const float* __restrict__ ba,
                         const float* __restrict__ wb, const float* __restrict__ bb,
                         const float* __restrict__ wz, const float* __restrict__ bz) {
    int warp = (blockIdx.x * blockDim.x + threadIdx.x) >> 5;
    int lane = threadIdx.x & 31;
    if (warp >= 3584) return;
    const float* row; float bias; float* out;
    if (warp < 1280)      { row = wa + (size_t)warp * STY; bias = ba[warp]; out = d_alpha + warp; }
    else if (warp < 2560) { int i = warp - 1280; row = wb + (size_t)i * STY; bias = bb[i]; out = d_beta + i; }
    else                  { int i = warp - 2560; row = wz + (size_t)i * STY; bias = bz[i]; out = d_zc + i; }
    float acc = 0.f;
    #pragma unroll
    for (int t = 0; t < 8; t++) acc += z[lane + 32 * t] * row[lane + 32 * t];
    #pragma unroll
    for (int off = 16; off; off >>= 1) acc += __shfl_xor_sync(0xFFFFFFFFu, acc, off);
    if (lane == 0) *out = acc + bias;
}

static __device__ __forceinline__ void split_store(float v, __nv_bfloat16* hi,
                                                   __nv_bfloat16* lo, size_t idx) {
    __nv_bfloat16 h = __float2bfloat16(v);
    hi[idx] = h;
    lo[idx] = __float2bfloat16(v - __bfloat162float(h));
}

__global__ void prep_fold_split(const float* __restrict__ mlw) {
    int idx = blockIdx.x * blockDim.x + threadIdx.x;
    if (idx >= 5 * HID * HID) return;
    int k = idx & (HID - 1);
    int i = idx >> 16;
    float w = mlw[idx] * d_alpha[i * HID + k];
    split_store(w, d_wmh, d_wml, idx);
}

__global__ void prep_w1p(const float* __restrict__ w1, const float* __restrict__ wma) {
    int idx = blockIdx.x * blockDim.x + threadIdx.x;
    if (idx >= HID * KP1) return;
    int o = idx / KP1, c = idx - o * KP1;
    float v = 0.f;
    if (c < CIN)           v = w1[(size_t)o * CIN + c];
    else if (c < CIN + NC) v = wma[(size_t)o * NC + (c - CIN)];
    split_store(v, d_w1h, d_w1l, idx);
}

__global__ void prep_pair(const float* __restrict__ w, __nv_bfloat16* __restrict__ hi,
                          __nv_bfloat16* __restrict__ lo, int n) {
    int idx = blockIdx.x * blockDim.x + threadIdx.x;
    if (idx >= n) return;
    split_store(w[idx], hi, lo, idx);
}

__global__ void prep_xm(const float* __restrict__ x, const float* __restrict__ m) {
    size_t idx = (size_t)blockIdx.x * blockDim.x + threadIdx.x;
    if (idx >= (size_t)S_TOT * KP1) return;
    int c = (int)(idx % KP1);
    size_t s = idx / KP1;
    float v = 0.f;
    if (c < CIN)           v = x[s * CIN + c];
    else if (c < CIN + NC) v = m[s * NC + (c - CIN)];
    split_store(v, d_xph, d_xpl, idx);
}

// [O][K][9] -> [tap][O][K], bf16 hi/lo
__global__ void prep_tw_split(const float* __restrict__ w, __nv_bfloat16* __restrict__ hi,
                              __nv_bfloat16* __restrict__ lo) {
    int idx = blockIdx.x * blockDim.x + threadIdx.x;
    if (idx >= 9 * HID * HID) return;
    int tap = idx / (HID * HID);
    int ok  = idx - tap * (HID * HID);
    split_store(w[(size_t)ok * 9 + tap], hi, lo, idx);
}

// ---------------------------------------------------------------------------
// Unified bf16x3 GEMM / implicit-GEMM conv via mma.sync.m16n8k16.
// C[r][o] = epi( sum_tap sum_k (Ah+Al)[shift(r,tap)][k] * (Bh+Bl)[tap][o][k] )
// products kept: AhBh + AlBh + AhBl (AlBl dropped, ~2^-16 rel).
// smem: 4 slabs (Ah, Al, Bh, Bl) per stage; fragments reused across 3 MMAs.
// CTA 256 threads, tile M=128 x NT. 80B-padded rows: conflict-free.
// For TAPS==9: M-tile == one image row (W==128); tap shifts are row shifts
// with cp.async zero-fill at borders.
// ---------------------------------------------------------------------------
template<int TAPS, int K, int NT, bool LRELU_, bool SPLIT_OUT, bool HAS_BIAS,
         bool HAS_RES, bool HAS_MOD>
__global__ void __launch_bounds__(256)
mma_gemm(const __nv_bfloat16* __restrict__ Ahi, const __nv_bfloat16* __restrict__ Alo,
         const __nv_bfloat16* __restrict__ Bhi, const __nv_bfloat16* __restrict__ Blo,
         const float* __restrict__ bias,
         const __nv_bfloat16* __restrict__ ResH, const __nv_bfloat16* __restrict__ ResL,
         const float* __restrict__ zc, int modoff,
         __nv_bfloat16* __restrict__ Chi, __nv_bfloat16* __restrict__ Clo,
         float* __restrict__ Cf, int OC) {
    extern __shared__ char smem[];
    constexpr int KCH    = K / 32;
    constexpr int NCHUNK = TAPS * KCH;
    constexpr int ASLAB  = 128 * 80;
    constexpr int BSLAB  = NT * 80;
    constexpr int BOFF   = 2 * ASLAB;
    constexpr int BUF    = 2 * ASLAB + 2 * BSLAB;
    constexpr int WN     = NT / 32;       // warps along N
    constexpr int MI     = WN;            // m16-atoms per warp
    constexpr int MWT    = 16 * MI;       // M rows per warp
    constexpr size_t BTAP = (TAPS == 9) ? (size_t)HID * K : 0;

    const uint32_t sb = smem_u32(smem);
    const int tid = threadIdx.x;
    const int lane = tid & 31, wid = tid >> 5;
    const int wn = wid % WN, wm = wid / WN;
    const int g = lane >> 2, q = lane & 3;
    const int o0 = blockIdx.y * NT;
    const int rbase = blockIdx.x * 128;

    auto load_chunk = [&](int buf, int chunk) {
        const int tap = (TAPS == 9) ? (chunk / KCH) : 0;
        const int k0  = ((TAPS == 9) ? (chunk - tap * KCH) : chunk) * 32;
        const uint32_t base = sb + buf * BUF;
        #pragma unroll
        for (int t = 0; t < 2; t++) {
            const int idx = tid + t * 256;
            const int row = idx >> 2, c = idx & 3;
            uint32_t sz = 16;
            size_t grow;
            if (TAPS == 9) {
                const int dy = tap / 3 - 1, dx = tap % 3 - 1;
                const int py = (int)blockIdx.x + dy, px = row + dx;
                const bool ok = (py >= 0) && (py < HH) && (px >= 0) && (px < WW);
                sz = ok ? 16u : 0u;
                grow = ok ? (size_t)(py * WW + px) : 0;
            } else {
                grow = (size_t)(rbase + row);
            }
            const size_t go = grow * K + k0 + c * 8;
            const uint32_t d = base + row * 80 + c * 16;
            cpa16z(d,         Ahi + go, sz);
            cpa16z(d + ASLAB, Alo + go, sz);
        }
        const __nv_bfloat16* bh = Bhi + (size_t)tap * BTAP;
        const __nv_bfloat16* bl = Blo + (size_t)tap * BTAP;
        for (int idx = tid; idx < NT * 4; idx += 256) {
            const int row = idx >> 2, c = idx & 3;
            const size_t go = (size_t)(o0 + row) * K + k0 + c * 8;
            const uint32_t d = base + BOFF + row * 80 + c * 16;
            cpa16z(d,         bh + go, 16);
            cpa16z(d + BSLAB, bl + go, 16);
        }
        asm volatile("cp.async.commit_group;" ::: "memory");
    };

    float acc[MI][4][4];
    #pragma unroll
    for (int i = 0; i < MI; i++)
        #pragma unroll
        for (int j = 0; j < 4; j++)
            #pragma unroll
            for (int r = 0; r < 4; r++) acc[i][j][r] = 0.f;

    load_chunk(0, 0);
    for (int cc = 0; cc < NCHUNK; cc++) {
        if (cc + 1 < NCHUNK) {
            load_chunk((cc + 1) & 1, cc + 1);
            asm volatile("cp.async.wait_group 1;" ::: "memory");
        } else {
            asm volatile("cp.async.wait_group 0;" ::: "memory");
        }
        __syncthreads();
        const uint32_t Ab = sb + (cc & 1) * BUF;
        #pragma unroll
        for (int kk = 0; kk < 2; kk++) {
            const int ko = kk * 32;
            uint32_t ah[MI][4], al[MI][4];
            const uint32_t abase = Ab + ko + q * 4 + (wm * MWT + g) * 80;
            #pragma unroll
            for (int i = 0; i < MI; i++) {
                const uint32_t r = abase + i * (16 * 80);
                ah[i][0] = lds32(r);
                ah[i][1] = lds32(r + 8 * 80);
                ah[i][2] = lds32(r + 16);
                ah[i][3] = lds32(r + 8 * 80 + 16);
                const uint32_t rl = r + ASLAB;
                al[i][0] = lds32(rl);
                al[i][1] = lds32(rl + 8 * 80);
                al[i][2] = lds32(rl + 16);
                al[i][3] = lds32(rl + 8 * 80 + 16);
            }
            uint32_t bh[4][2], bl[4][2];
            const uint32_t bbase = Ab + BOFF + ko + q * 4 + (wn * 32 + g) * 80;
            #pragma unroll
            for (int j = 0; j < 4; j++) {
                const uint32_t r = bbase + j * (8 * 80);
                bh[j][0] = lds32(r);
                bh[j][1] = lds32(r + 16);
                bl[j][0] = lds32(r + BSLAB);
                bl[j][1] = lds32(r + BSLAB + 16);
            }
            #pragma unroll
            for (int i = 0; i < MI; i++)
                #pragma unroll
                for (int j = 0; j < 4; j++) {
                    mma16816(acc[i][j], ah[i], bh[j]);
                    mma16816(acc[i][j], al[i], bh[j]);
                    mma16816(acc[i][j], ah[i], bl[j]);
                }
        }
        __syncthreads();
    }

    // Epilogue
    #pragma unroll
    for (int j = 0; j < 4; j++) {
        const int col0 = o0 + wn * 32 + j * 8 + q * 2;
        const float b0 = HAS_BIAS ? bias[col0]     : 0.f;
        const float b1 = HAS_BIAS ? bias[col0 + 1] : 0.f;
        float sc0 = 1.f, sc1 = 1.f, sh0 = 0.f, sh1 = 0.f;
        if (HAS_MOD) {
            sc0 = zc[modoff + col0] + 1.f;       sc1 = zc[modoff + col0 + 1] + 1.f;
            sh0 = zc[modoff + HID + col0];       sh1 = zc[modoff + HID + col0 + 1];
        }
        #pragma unroll
        for (int i = 0; i < MI; i++) {
            #pragma unroll
            for (int h = 0; h < 2; h++) {
                const int row = rbase + wm * MWT + i * 16 + g + h * 8;
                float v0 = acc[i][j][h * 2 + 0] + b0;
                float v1 = acc[i][j][h * 2 + 1] + b1;
                if (HAS_RES) {
                    __nv_bfloat162 rh = *reinterpret_cast<const __nv_bfloat162*>(ResH + (size_t)row * OC + col0);
                    __nv_bfloat162 rl = *reinterpret_cast<const __nv_bfloat162*>(ResL + (size_t)row * OC + col0);
                    v0 += __bfloat162float(rh.x) + __bfloat162float(rl.x);
                    v1 += __bfloat162float(rh.y) + __bfloat162float(rl.y);
                }
                if (HAS_MOD) { v0 = v0 * sc0 + sh0; v1 = v1 * sc1 + sh1; }
                if (LRELU_)  { v0 = lrelu(v0); v1 = lrelu(v1); }
                if (SPLIT_OUT) {
                    __nv_bfloat162 hp = __floats2bfloat162_rn(v0, v1);
                    float r0 = v0 - __bfloat162float(hp.x);
                    float r1 = v1 - __bfloat162float(hp.y);
                    __nv_bfloat162 lp = __floats2bfloat162_rn(r0, r1);
                    *reinterpret_cast<__nv_bfloat162*>(Chi + (size_t)row * OC + col0) = hp;
                    *reinterpret_cast<__nv_bfloat162*>(Clo + (size_t)row * OC + col0) = lp;
                } else {
                    float2 v = {v0, v1};
                    *reinterpret_cast<float2*>(Cf + (size_t)row * OC + col0) = v;
                }
            }
        }
    }
}

// ---------------------------------------------------------------------------
// sigma[s] = wsig . (fhi+flo)[s] + bsig
// ---------------------------------------------------------------------------
__global__ void sigma_kernel(const __nv_bfloat16* __restrict__ fhi,
                             const __nv_bfloat16* __restrict__ flo,
                             const float* __restrict__ wsig,
                             const float* __restrict__ bsig, float* __restrict__ out) {
    int warp = (blockIdx.x * blockDim.x + threadIdx.x) >> 5;
    int lane = threadIdx.x & 31;
    if (warp >= S_TOT) return;
    const __nv_bfloat16* fh = fhi + (size_t)warp * HID;
    const __nv_bfloat16* fl = flo + (size_t)warp * HID;
    float acc = 0.f;
    #pragma unroll
    for (int t = 0; t < 8; t++) {
        int i = lane + 32 * t;
        acc += (__bfloat162float(fh[i]) + __bfloat162float(fl[i])) * wsig[i];
    }
    #pragma unroll
    for (int off = 16; off; off >>= 1) acc += __shfl_xor_sync(0xFFFFFFFFu, acc, off);
    if (lane == 0) out[warp] = acc + bsig[0];
}

// ---------------------------------------------------------------------------
// Volumetric compositing -> feat (pixel-major, bf16 hi/lo)
// ---------------------------------------------------------------------------
__global__ void composite_kernel(const float* __restrict__ sigma, const float* __restrict__ dists,
                                 const float* __restrict__ cbuf,
                                 __nv_bfloat16* __restrict__ feath,
                                 __nv_bfloat16* __restrict__ featl) {
    int pix = blockIdx.x;
    int t = threadIdx.x;
    __shared__ float wgt[MM];
    if (t == 0) {
        float T = 1.f;
        #pragma unroll
        for (int m = 0; m < MM; m++) {
            float sg = sigma[pix * MM + m];
            sg = sg > 0.f ? sg : 0.f;
            float a = 1.f - expf(-sg * dists[pix * MM + m]);
            wgt[m] = a * T;
            T *= (1.f - a + 1e-10f);
        }
    }
    __syncthreads();
    float acc = 0.f;
    #pragma unroll
    for (int m = 0; m < MM; m++)
        acc += wgt[m] * cbuf[(size_t)(pix * MM + m) * COL + t];
    split_store(acc, feath, featl, (size_t)pix * COL + t);
}

// ---------------------------------------------------------------------------
// Final 1x1 conv to 3 channels (warp per pixel)
// ---------------------------------------------------------------------------
__global__ void final_conv(const __nv_bfloat16* __restrict__ InH,
                           const __nv_bfloat16* __restrict__ InL,
                           const float* __restrict__ w,
                           const float* __restrict__ b, float* __restrict__ out) {
    int warp = (blockIdx.x * blockDim.x + threadIdx.x) >> 5;
    int lane = threadIdx.x & 31;
    if (warp >= HWPIX) return;
    const __nv_bfloat16* ph = InH + (size_t)warp * HID;
    const __nv_bfloat16* pl = InL + (size_t)warp * HID;
    float a0 = 0.f, a1 = 0.f, a2 = 0.f;
    #pragma unroll
    for (int t = 0; t < 8; t++) {
        int i = lane + 32 * t;
        float v = __bfloat162float(ph[i]) + __bfloat162float(pl[i]);
        a0 += v * w[i];
        a1 += v * w[HID + i];
        a2 += v * w[2 * HID + i];
    }
    #pragma unroll
    for (int off = 16; off; off >>= 1) {
        a0 += __shfl_xor_sync(0xFFFFFFFFu, a0, off);
        a1 += __shfl_xor_sync(0xFFFFFFFFu, a1, off);
        a2 += __shfl_xor_sync(0xFFFFFFFFu, a2, off);
    }
    if (lane == 0) {
        out[warp]             = a0 + b[0];
        out[HWPIX + warp]     = a1 + b[1];
        out[2 * HWPIX + warp] = a2 + b[2];
    }
}

// ---------------------------------------------------------------------------
// Launch
// ---------------------------------------------------------------------------
extern "C" void kernel_launch(void* const* d_in, const int* in_sizes, int n_in,
                              void* d_out, int out_size) {
    const float* x     = (const float*)d_in[0];
    const float* m     = (const float*)d_in[1];
    const float* z     = (const float*)d_in[2];
    const float* dists = (const float*)d_in[3];
    const float* w1    = (const float*)d_in[4];
    const float* b1    = (const float*)d_in[5];
    const float* wma   = (const float*)d_in[6];
    const float* ml_w  = (const float*)d_in[7];
    const float* ml_wa = (const float*)d_in[8];
    const float* ml_ba = (const float*)d_in[9];
    const float* ml_wb = (const float*)d_in[10];
    const float* ml_bb = (const float*)d_in[11];
    const float* wsig  = (const float*)d_in[12];
    const float* bsig  = (const float*)d_in[13];
    const float* wc    = (const float*)d_in[14];
    const float* bc    = (const float*)d_in[15];
    const float* wz    = (const float*)d_in[16];
    const float* bz    = (const float*)d_in[17];
    const float* c1_w  = (const float*)d_in[18];
    const float* c1_b  = (const float*)d_in[19];
    const float* c2a_w = (const float*)d_in[20];
    const float* c2a_b = (const float*)d_in[21];
    const float* c2b_w = (const float*)d_in[22];
    const float* c3a_w = (const float*)d_in[23];
    const float* c3a_b = (const float*)d_in[24];
    const float* c3b_w = (const float*)d_in[25];
    const float* c4a_w = (const float*)d_in[26];
    const float* c4a_b = (const float*)d_in[27];
    const float* c4b_w = (const float*)d_in[28];
    const float* c4b_b = (const float*)d_in[29];
    const float* c4_w  = (const float*)d_in[30];
    const float* c4_b  = (const float*)d_in[31];
    float* out = (float*)d_out;

    __nv_bfloat16 *xph, *xpl, *pah, *pal, *pbh, *pbl, *w1h, *w1l, *wmh, *wml, *wch, *wcl;
    __nv_bfloat16 *c3h, *c3l, *c1h, *c1l, *c4ah, *c4al, *c4bh, *c4bl;
    __nv_bfloat16 *yah, *yal, *ybh, *ybl, *ych, *ycl, *fth, *ftl;
    float *sig, *cb, *zcv, *be;
    cudaGetSymbolAddress((void**)&xph, d_xph);
    cudaGetSymbolAddress((void**)&xpl, d_xpl);
    cudaGetSymbolAddress((void**)&pah, d_pah);
    cudaGetSymbolAddress((void**)&pal, d_pal);
    cudaGetSymbolAddress((void**)&pbh, d_pbh);
    cudaGetSymbolAddress((void**)&pbl, d_pbl);
    cudaGetSymbolAddress((void**)&w1h, d_w1h);
    cudaGetSymbolAddress((void**)&w1l, d_w1l);
    cudaGetSymbolAddress((void**)&wmh, d_wmh);
    cudaGetSymbolAddress((void**)&wml, d_wml);
    cudaGetSymbolAddress((void**)&wch, d_wch);
    cudaGetSymbolAddress((void**)&wcl, d_wcl);
    cudaGetSymbolAddress((void**)&c3h, d_c3h);
    cudaGetSymbolAddress((void**)&c3l, d_c3l);
    cudaGetSymbolAddress((void**)&c1h, d_c1h);
    cudaGetSymbolAddress((void**)&c1l, d_c1l);
    cudaGetSymbolAddress((void**)&c4ah, d_c4ah);
    cudaGetSymbolAddress((void**)&c4al, d_c4al);
    cudaGetSymbolAddress((void**)&c4bh, d_c4bh);
    cudaGetSymbolAddress((void**)&c4bl, d_c4bl);
    cudaGetSymbolAddress((void**)&yah, d_yah);
    cudaGetSymbolAddress((void**)&yal, d_yal);
    cudaGetSymbolAddress((void**)&ybh, d_ybh);
    cudaGetSymbolAddress((void**)&ybl, d_ybl);
    cudaGetSymbolAddress((void**)&ych, d_ych);
    cudaGetSymbolAddress((void**)&ycl, d_ycl);
    cudaGetSymbolAddress((void**)&fth, d_feath);
    cudaGetSymbolAddress((void**)&ftl, d_featl);
    cudaGetSymbolAddress((void**)&sig, d_sig);
    cudaGetSymbolAddress((void**)&cb,  d_cbuf);
    cudaGetSymbolAddress((void**)&zcv, d_zc);
    cudaGetSymbolAddress((void**)&be,  d_beta);

    const int TW = 9 * HID * HID;
    const int SM128 = 2 * (2 * 128 * 80 + 2 * 128 * 80);   // 81920
    const int SM64  = 2 * (2 * 128 * 80 + 2 * 64 * 80);    // 61440

    // GEMM variants
    auto G1  = mma_gemm<1, KP1, 128, true,  true,  true,  false, false>;  // layer 1
    auto GH  = mma_gemm<1, HID, 128, true,  true,  true,  false, false>;  // fc2-6, c4a
    auto GW  = mma_gemm<1, HID, 64,  false, false, true,  false, false>;  // wc -> fp32
    auto GC1 = mma_gemm<1, COL, 128, true,  true,  true,  false, false>;  // c1
    auto CA  = mma_gemm<9, HID, 128, true,  true,  true,  false, false>;  // c2a/c3a
    auto CB  = mma_gemm<9, HID, 128, true,  true,  false, true,  true >;  // c2b/c3b
    auto C4B = mma_gemm<1, HID, 128, true,  true,  true,  true,  false>;  // c4b

    cudaFuncSetAttribute(G1,  cudaFuncAttributeMaxDynamicSharedMemorySize, SM128);
    cudaFuncSetAttribute(GH,  cudaFuncAttributeMaxDynamicSharedMemorySize, SM128);
    cudaFuncSetAttribute(GW,  cudaFuncAttributeMaxDynamicSharedMemorySize, SM64);
    cudaFuncSetAttribute(GC1, cudaFuncAttributeMaxDynamicSharedMemorySize, SM128);
    cudaFuncSetAttribute(CA,  cudaFuncAttributeMaxDynamicSharedMemorySize, SM128);
    cudaFuncSetAttribute(CB,  cudaFuncAttributeMaxDynamicSharedMemorySize, SM128);
    cudaFuncSetAttribute(C4B, cudaFuncAttributeMaxDynamicSharedMemorySize, SM128);

    // --- prep ---
    prep_vec<<<448, 256>>>(z, ml_wa, ml_ba, ml_wb, ml_bb, wz, bz);
    prep_fold_split<<<(5 * HID * HID + 255) / 256, 256>>>(ml_w);
    prep_w1p<<<(HID * KP1 + 255) / 256, 256>>>(w1, wma);
    prep_pair<<<(COL * HID + 255) / 256, 256>>>(wc, wch, wcl, COL * HID);
    prep_xm<<<(int)(((size_t)S_TOT * KP1 + 255) / 256), 256>>>(x, m);
    prep_tw_split<<<(TW + 255) / 256, 256>>>(c2a_w, c3h + 0 * TW, c3l + 0 * TW);
    prep_tw_split<<<(TW + 255) / 256, 256>>>(c2b_w, c3h + 1 * TW, c3l + 1 * TW);
    prep_tw_split<<<(TW + 255) / 256, 256>>>(c3a_w, c3h + 2 * TW, c3l + 2 * TW);
    prep_tw_split<<<(TW + 255) / 256, 256>>>(c3b_w, c3h + 3 * TW, c3l + 3 * TW);
    prep_pair<<<(HID * COL + 255) / 256, 256>>>(c1_w, c1h, c1l, HID * COL);
    prep_pair<<<(HID * HID + 255) / 256, 256>>>(c4a_w, c4ah, c4al, HID * HID);
    prep_pair<<<(HID * HID + 255) / 256, 256>>>(c4b_w, c4bh, c4bl, HID * HID);

    // --- MLP (bf16x3 mma) ---
    dim3 gM(S_TOT / 128, 2);
    G1<<<gM, 256, SM128>>>(xph, xpl, w1h, w1l, b1, nullptr, nullptr, nullptr, 0, pah, pal, nullptr, HID);
    GH<<<gM, 256, SM128>>>(pah, pal, wmh + 0 * 65536, wml + 0 * 65536, be + 0,    nullptr, nullptr, nullptr, 0, pbh, pbl, nullptr, HID);
    GH<<<gM, 256, SM128>>>(pbh, pbl, wmh + 1 * 65536, wml + 1 * 65536, be + 256,  nullptr, nullptr, nullptr, 0, pah, pal, nullptr, HID);
    GH<<<gM, 256, SM128>>>(pah, pal, wmh + 2 * 65536, wml + 2 * 65536, be + 512,  nullptr, nullptr, nullptr, 0, pbh, pbl, nullptr, HID);
    sigma_kernel<<<S_TOT / 8, 256>>>(pbh, pbl, wsig, bsig, sig);
    GH<<<gM, 256, SM128>>>(pbh, pbl, wmh + 3 * 65536, wml + 3 * 65536, be + 768,  nullptr, nullptr, nullptr, 0, pah, pal, nullptr, HID);
    GH<<<gM, 256, SM128>>>(pah, pal, wmh + 4 * 65536, wml + 4 * 65536, be + 1024, nullptr, nullptr, nullptr, 0, pbh, pbl, nullptr, HID);
    GW<<<dim3(S_TOT / 128, 1), 256, SM64>>>(pbh, pbl, wch, wcl, bc, nullptr, nullptr, nullptr, 0, nullptr, nullptr, cb, COL);

    // --- compositing ---
    composite_kernel<<<HWPIX, 64>>>(sig, dists, cb, fth, ftl);

    // --- CNN (bf16x3 implicit-GEMM mma) ---
    dim3 gC(HH, 2);
    GC1<<<gC, 256, SM128>>>(fth, ftl, c1h, c1l, c1_b, nullptr, nullptr, nullptr, 0, yah, yal, nullptr, HID);
    CA <<<gC, 256, SM128>>>(yah, yal, c3h + 0 * TW, c3l + 0 * TW, c2a_b, nullptr, nullptr, nullptr, 0, ybh, ybl, nullptr, HID);
    CB <<<gC, 256, SM128>>>(ybh, ybl, c3h + 1 * TW, c3l + 1 * TW, nullptr, yah, yal, zcv, 0,   ych, ycl, nullptr, HID);
    CA <<<gC, 256, SM128>>>(ych, ycl, c3h + 2 * TW, c3l + 2 * TW, c3a_b, nullptr, nullptr, nullptr, 0, ybh, ybl, nullptr, HID);
    CB <<<gC, 256, SM128>>>(ybh, ybl, c3h + 3 * TW, c3l + 3 * TW, nullptr, ych, ycl, zcv, 512, yah, yal, nullptr, HID);
    GH <<<gC, 256, SM128>>>(yah, yal, c4ah, c4al, c4a_b, nullptr, nullptr, nullptr, 0, ybh, ybl, nullptr, HID);
    C4B<<<gC, 256, SM128>>>(ybh, ybl, c4bh, c4bl, c4b_b, yah, yal, nullptr, 0, ych, ycl, nullptr, HID);
    final_conv<<<HWPIX / 8, 256>>>(ych, ycl, c4_w, c4_b, out);

    (void)in_sizes; (void)n_in; (void)out_size;
}

// round 5
// speedup vs baseline: 2.8148x; 1.0184x over previous
#include <cuda_runtime.h>
#include <cuda_bf16.h>
#include <cstdint>

// ---------------------------------------------------------------------------
// Problem constants
// ---------------------------------------------------------------------------
#define HH      128
#define WW      128
#define MM      16
#define CIN     128
#define NC      7
#define HID     256
#define STY     256
#define COL     64
#define HWPIX   (HH * WW)            // 16384
#define S_TOT   (HWPIX * MM)         // 262144
#define KP1     160                  // padded K for layer 1: 128 (x) + 7 (m) + 25 zeros

// ---------------------------------------------------------------------------
// Scratch (device globals; no runtime allocation allowed)
// ---------------------------------------------------------------------------
__device__ __nv_bfloat16 d_xph[(size_t)S_TOT * KP1];
__device__ __nv_bfloat16 d_xpl[(size_t)S_TOT * KP1];
__device__ __nv_bfloat16 d_pah[(size_t)S_TOT * HID];
__device__ __nv_bfloat16 d_pal[(size_t)S_TOT * HID];
__device__ __nv_bfloat16 d_pbh[(size_t)S_TOT * HID];
__device__ __nv_bfloat16 d_pbl[(size_t)S_TOT * HID];
__device__ __nv_bfloat16 d_w1h[HID * KP1];
__device__ __nv_bfloat16 d_w1l[HID * KP1];
__device__ __nv_bfloat16 d_wmh[5 * HID * HID];
__device__ __nv_bfloat16 d_wml[5 * HID * HID];
__device__ __nv_bfloat16 d_wch[COL * HID];
__device__ __nv_bfloat16 d_wcl[COL * HID];
// CNN weights (bf16 hi/lo)
__device__ __nv_bfloat16 d_c3h[4 * 9 * HID * HID];
__device__ __nv_bfloat16 d_c3l[4 * 9 * HID * HID];
__device__ __nv_bfloat16 d_c1h[HID * COL];
__device__ __nv_bfloat16 d_c1l[HID * COL];
__device__ __nv_bfloat16 d_c4ah[HID * HID];
__device__ __nv_bfloat16 d_c4al[HID * HID];
__device__ __nv_bfloat16 d_c4bh[HID * HID];
__device__ __nv_bfloat16 d_c4bl[HID * HID];
// CNN activations: pixel-major [pix][chan], bf16 hi/lo
__device__ __nv_bfloat16 d_yah[HWPIX * HID];
__device__ __nv_bfloat16 d_yal[HWPIX * HID];
__device__ __nv_bfloat16 d_ybh[HWPIX * HID];
__device__ __nv_bfloat16 d_ybl[HWPIX * HID];
__device__ __nv_bfloat16 d_ych[HWPIX * HID];
__device__ __nv_bfloat16 d_ycl[HWPIX * HID];
__device__ __nv_bfloat16 d_feath[HWPIX * COL];
__device__ __nv_bfloat16 d_featl[HWPIX * COL];
__device__ float d_sig[S_TOT];
__device__ float d_cbuf[(size_t)S_TOT * COL];
__device__ float d_alpha[5 * HID];
__device__ float d_beta[5 * HID];
__device__ float d_zc[4 * HID];

static __device__ __forceinline__ float lrelu(float v) {
    return v > 0.f ? v : 0.2f * v;
}

static __device__ __forceinline__ uint32_t smem_u32(const void* p) {
    uint32_t a;
    asm("{ .reg .u64 t; cvta.to.shared.u64 t, %1; cvt.u32.u64 %0, t; }" : "=r"(a) : "l"(p));
    return a;
}

static __device__ __forceinline__ void cpa16z(uint32_t dst, const void* src, uint32_t sz) {
    asm volatile("cp.async.cg.shared.global [%0], [%1], 16, %2;"
                 :: "r"(dst), "l"(src), "r"(sz));
}

static __device__ __forceinline__ uint32_t lds32(uint32_t a) {
    uint32_t v;
    asm volatile("ld.shared.b32 %0, [%1];" : "=r"(v) : "r"(a));
    return v;
}

static __device__ __forceinline__ void mma16816(float* d, const uint32_t* a, const uint32_t* b) {
    asm volatile(
        "mma.sync.aligned.m16n8k16.row.col.f32.bf16.bf16.f32 "
        "{%0,%1,%2,%3}, {%4,%5,%6,%7}, {%8,%9}, {%0,%1,%2,%3};"
        : "+f"(d[0]), "+f"(d[1]), "+f"(d[2]), "+f"(d[3])
        : "r"(a[0]), "r"(a[1]), "r"(a[2]), "r"(a[3]), "r"(b[0]), "r"(b[1]));
}

// ---------------------------------------------------------------------------
// Prep kernels
// ---------------------------------------------------------------------------
__global__ void prep_vec(const float* __restrict__ z,
                         const float* __restrict__ wa, const float* __restrict__ ba,
                         const float* __restrict__ wb, const float* __restrict__ bb,
                         const float* __restrict__ wz, const float* __restrict__ bz) {
    int warp = (blockIdx.x * blockDim.x + threadIdx.x) >> 5;
    int lane = threadIdx.x & 31;
    if (warp >= 3584) return;
    const float* row; float bias; float* out;
    if (warp < 1280)      { row = wa + (size_t)warp * STY; bias = ba[warp]; out = d_alpha + warp; }
    else if (warp < 2560) { int i = warp - 1280; row = wb + (size_t)i * STY; bias = bb[i]; out = d_beta + i; }
    else                  { int i = warp - 2560; row = wz + (size_t)i * STY; bias = bz[i]; out = d_zc + i; }
    float acc = 0.f;
    #pragma unroll
    for (int t = 0; t < 8; t++) acc += z[lane + 32 * t] * row[lane + 32 * t];
    #pragma unroll
    for (int off = 16; off; off >>= 1) acc += __shfl_xor_sync(0xFFFFFFFFu, acc, off);
    if (lane == 0) *out = acc + bias;
}

static __device__ __forceinline__ void split_store(float v, __nv_bfloat16* hi,
                                                   __nv_bfloat16* lo, size_t idx) {
    __nv_bfloat16 h = __float2bfloat16(v);
    hi[idx] = h;
    lo[idx] = __float2bfloat16(v - __bfloat162float(h));
}

__global__ void prep_fold_split(const float* __restrict__ mlw) {
    int idx = blockIdx.x * blockDim.x + threadIdx.x;
    if (idx >= 5 * HID * HID) return;
    int k = idx & (HID - 1);
    int i = idx >> 16;
    float w = mlw[idx] * d_alpha[i * HID + k];
    split_store(w, d_wmh, d_wml, idx);
}

__global__ void prep_w1p(const float* __restrict__ w1, const float* __restrict__ wma) {
    int idx = blockIdx.x * blockDim.x + threadIdx.x;
    if (idx >= HID * KP1) return;
    int o = idx / KP1, c = idx - o * KP1;
    float v = 0.f;
    if (c < CIN)           v = w1[(size_t)o * CIN + c];
    else if (c < CIN + NC) v = wma[(size_t)o * NC + (c - CIN)];
    split_store(v, d_w1h, d_w1l, idx);
}

__global__ void prep_pair(const float* __restrict__ w, __nv_bfloat16* __restrict__ hi,
                          __nv_bfloat16* __restrict__ lo, int n) {
    int idx = blockIdx.x * blockDim.x + threadIdx.x;
    if (idx >= n) return;
    split_store(w[idx], hi, lo, idx);
}

__global__ void prep_xm(const float* __restrict__ x, const float* __restrict__ m) {
    size_t idx = (size_t)blockIdx.x * blockDim.x + threadIdx.x;
    if (idx >= (size_t)S_TOT * KP1) return;
    int c = (int)(idx % KP1);
    size_t s = idx / KP1;
    float v = 0.f;
    if (c < CIN)           v = x[s * CIN + c];
    else if (c < CIN + NC) v = m[s * NC + (c - CIN)];
    split_store(v, d_xph, d_xpl, idx);
}

// [O][K][9] -> [tap][O][K], bf16 hi/lo
__global__ void prep_tw_split(const float* __restrict__ w, __nv_bfloat16* __restrict__ hi,
                              __nv_bfloat16* __restrict__ lo) {
    int idx = blockIdx.x * blockDim.x + threadIdx.x;
    if (idx >= 9 * HID * HID) return;
    int tap = idx / (HID * HID);
    int ok  = idx - tap * (HID * HID);
    split_store(w[(size_t)ok * 9 + tap], hi, lo, idx);
}

// ---------------------------------------------------------------------------
// Fused 2-layer bf16x3 GEMM: 512 threads, M=128 x N=256 per CTA.
// GEMM1 streams A (gmem) + B1; epilogue (bias+lrelu+split) -> smem intermediate
// (row stride 528B, conflict-free). GEMM2 reads A-frags from smem, streams B2.
// Optional fused sigma (wsig dot) on the second layer's post-lrelu output via
// deterministic smem tree reduction.
// ---------------------------------------------------------------------------
template<int K1, bool DO_SIG>
__global__ void __launch_bounds__(512)
fused2(const __nv_bfloat16* __restrict__ A1h, const __nv_bfloat16* __restrict__ A1l,
       const __nv_bfloat16* __restrict__ B1h, const __nv_bfloat16* __restrict__ B1l,
       const float* __restrict__ bias1,
       const __nv_bfloat16* __restrict__ B2h, const __nv_bfloat16* __restrict__ B2l,
       const float* __restrict__ bias2,
       __nv_bfloat16* __restrict__ Ch, __nv_bfloat16* __restrict__ Cl,
       const float* __restrict__ wsig, const float* __restrict__ bsig,
       float* __restrict__ sigout) {
    extern __shared__ char smem[];
    constexpr int ASLAB = 128 * 80;           // 10240
    constexpr int BSLAB = 256 * 80;           // 20480
    constexpr int BUF1  = 2 * ASLAB + 2 * BSLAB;  // 61440 (stage1, double-buffered)
    constexpr int ISTR  = 528;                // intermediate row stride (conflict-free)
    constexpr int IHI   = 0;
    constexpr int ILO   = 128 * ISTR;         // 67584
    constexpr int B2OFF = 2 * 128 * ISTR;     // 135168
    constexpr int B2BUF = 2 * BSLAB;          // 40960
    constexpr int NCH1  = K1 / 32;
    constexpr int NCH2  = HID / 32;           // 8

    const uint32_t sb = smem_u32(smem);
    const int tid = threadIdx.x;
    const int lane = tid & 31, wid = tid >> 5;
    const int wn = wid & 7, wm = wid >> 3;    // 8 warps along N, 2 along M
    const int g = lane >> 2, q = lane & 3;
    const int rbase = blockIdx.x * 128;

    auto load1 = [&](int buf, int c) {
        const uint32_t base = sb + buf * BUF1;
        const int k0 = c * 32;
        {   // A chunk: 128 rows x 4 16B pieces per plane; 1 piece/thread
            const int row = tid >> 2, cc = tid & 3;
            const size_t go = (size_t)(rbase + row) * K1 + k0 + cc * 8;
            const uint32_t d = base + row * 80 + cc * 16;
            cpa16z(d,         A1h + go, 16);
            cpa16z(d + ASLAB, A1l + go, 16);
        }
        const uint32_t bb = base + 2 * ASLAB;
        #pragma unroll
        for (int t = 0; t < 2; t++) {
            const int idx = tid + t * 512;
            const int row = idx >> 2, cc = idx & 3;
            const size_t go = (size_t)row * K1 + k0 + cc * 8;
            const uint32_t d = bb + row * 80 + cc * 16;
            cpa16z(d,         B1h + go, 16);
            cpa16z(d + BSLAB, B1l + go, 16);
        }
        asm volatile("cp.async.commit_group;" ::: "memory");
    };
    auto load2 = [&](int buf, int c) {
        const uint32_t bb = sb + B2OFF + buf * B2BUF;
        const int k0 = c * 32;
        #pragma unroll
        for (int t = 0; t < 2; t++) {
            const int idx = tid + t * 512;
            const int row = idx >> 2, cc = idx & 3;
            const size_t go = (size_t)row * HID + k0 + cc * 8;
            const uint32_t d = bb + row * 80 + cc * 16;
            cpa16z(d,         B2h + go, 16);
            cpa16z(d + BSLAB, B2l + go, 16);
        }
        asm volatile("cp.async.commit_group;" ::: "memory");
    };

    float acc[4][4][4];
    #pragma unroll
    for (int i = 0; i < 4; i++)
        #pragma unroll
        for (int j = 0; j < 4; j++)
            #pragma unroll
            for (int r = 0; r < 4; r++) acc[i][j][r] = 0.f;

    // ---------------- GEMM1: A (gmem) x B1 ----------------
    load1(0, 0);
    for (int c = 0; c < NCH1; c++) {
        if (c + 1 < NCH1) {
            load1((c + 1) & 1, c + 1);
            asm volatile("cp.async.wait_group 1;" ::: "memory");
        } else {
            asm volatile("cp.async.wait_group 0;" ::: "memory");
        }
        __syncthreads();
        const uint32_t Ab = sb + (c & 1) * BUF1;
        #pragma unroll
        for (int kk = 0; kk < 2; kk++) {
            const int ko = kk * 32;
            uint32_t ah[4][4], al[4][4];
            const uint32_t abase = Ab + ko + q * 4 + (wm * 64 + g) * 80;
            #pragma unroll
            for (int i = 0; i < 4; i++) {
                const uint32_t r = abase + i * (16 * 80);
                ah[i][0] = lds32(r);            ah[i][1] = lds32(r + 8 * 80);
                ah[i][2] = lds32(r + 16);       ah[i][3] = lds32(r + 8 * 80 + 16);
                const uint32_t rl = r + ASLAB;
                al[i][0] = lds32(rl);           al[i][1] = lds32(rl + 8 * 80);
                al[i][2] = lds32(rl + 16);      al[i][3] = lds32(rl + 8 * 80 + 16);
            }
            uint32_t bh[4][2], bl[4][2];
            const uint32_t bbase = Ab + 2 * ASLAB + ko + q * 4 + (wn * 32 + g) * 80;
            #pragma unroll
            for (int j = 0; j < 4; j++) {
                const uint32_t r = bbase + j * (8 * 80);
                bh[j][0] = lds32(r);            bh[j][1] = lds32(r + 16);
                bl[j][0] = lds32(r + BSLAB);    bl[j][1] = lds32(r + BSLAB + 16);
            }
            #pragma unroll
            for (int i = 0; i < 4; i++)
                #pragma unroll
                for (int j = 0; j < 4; j++) {
                    mma16816(acc[i][j], ah[i], bh[j]);
                    mma16816(acc[i][j], al[i], bh[j]);
                    mma16816(acc[i][j], ah[i], bl[j]);
                }
        }
        __syncthreads();
    }

    // prefetch GEMM2's first B chunk (disjoint smem region) before epilogue
    load2(0, 0);

    // ---------------- epilogue 1 -> smem intermediate ----------------
    #pragma unroll
    for (int j = 0; j < 4; j++) {
        const int col0 = wn * 32 + j * 8 + q * 2;
        const float b0 = bias1[col0], b1 = bias1[col0 + 1];
        #pragma unroll
        for (int i = 0; i < 4; i++) {
            #pragma unroll
            for (int h = 0; h < 2; h++) {
                const int row = wm * 64 + i * 16 + g + h * 8;
                float v0 = lrelu(acc[i][j][h * 2 + 0] + b0);
                float v1 = lrelu(acc[i][j][h * 2 + 1] + b1);
                __nv_bfloat162 hp = __floats2bfloat162_rn(v0, v1);
                float r0 = v0 - __bfloat162float(hp.x);
                float r1 = v1 - __bfloat162float(hp.y);
                __nv_bfloat162 lp = __floats2bfloat162_rn(r0, r1);
                *reinterpret_cast<__nv_bfloat162*>(smem + IHI + row * ISTR + col0 * 2) = hp;
                *reinterpret_cast<__nv_bfloat162*>(smem + ILO + row * ISTR + col0 * 2) = lp;
            }
        }
    }
    __syncthreads();

    // ---------------- GEMM2: A (smem intermediate) x B2 ----------------
    #pragma unroll
    for (int i = 0; i < 4; i++)
        #pragma unroll
        for (int j = 0; j < 4; j++)
            #pragma unroll
            for (int r = 0; r < 4; r++) acc[i][j][r] = 0.f;

    for (int c = 0; c < NCH2; c++) {
        if (c + 1 < NCH2) {
            load2((c + 1) & 1, c + 1);
            asm volatile("cp.async.wait_group 1;" ::: "memory");
        } else {
            asm volatile("cp.async.wait_group 0;" ::: "memory");
        }
        __syncthreads();
        const uint32_t Bb = sb + B2OFF + (c & 1) * B2BUF;
        #pragma unroll
        for (int kk = 0; kk < 2; kk++) {
            uint32_t ah[4][4], al[4][4];
            const uint32_t abase = sb + IHI + (wm * 64 + g) * ISTR + c * 64 + kk * 32 + q * 4;
            #pragma unroll
            for (int i = 0; i < 4; i++) {
                const uint32_t r = abase + i * (16 * ISTR);
                ah[i][0] = lds32(r);            ah[i][1] = lds32(r + 8 * ISTR);
                ah[i][2] = lds32(r + 16);       ah[i][3] = lds32(r + 8 * ISTR + 16);
                const uint32_t rl = r + (ILO - IHI);
                al[i][0] = lds32(rl);           al[i][1] = lds32(rl + 8 * ISTR);
                al[i][2] = lds32(rl + 16);      al[i][3] = lds32(rl + 8 * ISTR + 16);
            }
            uint32_t bh[4][2], bl[4][2];
            const uint32_t bbase = Bb + kk * 32 + q * 4 + (wn * 32 + g) * 80;
            #pragma unroll
            for (int j = 0; j < 4; j++) {
                const uint32_t r = bbase + j * (8 * 80);
                bh[j][0] = lds32(r);            bh[j][1] = lds32(r + 16);
                bl[j][0] = lds32(r + BSLAB);    bl[j][1] = lds32(r + BSLAB + 16);
            }
            #pragma unroll
            for (int i = 0; i < 4; i++)
                #pragma unroll
                for (int j = 0; j < 4; j++) {
                    mma16816(acc[i][j], ah[i], bh[j]);
                    mma16816(acc[i][j], al[i], bh[j]);
                    mma16816(acc[i][j], ah[i], bl[j]);
                }
        }
        __syncthreads();
    }

    // ---------------- epilogue 2 -> gmem (+ fused sigma) ----------------
    float rp[4][2];
    if (DO_SIG) {
        #pragma unroll
        for (int i = 0; i < 4; i++) { rp[i][0] = 0.f; rp[i][1] = 0.f; }
    }
    #pragma unroll
    for (int j = 0; j < 4; j++) {
        const int col0 = wn * 32 + j * 8 + q * 2;
        const float b0 = bias2[col0], b1 = bias2[col0 + 1];
        float ws0 = 0.f, ws1 = 0.f;
        if (DO_SIG) { ws0 = wsig[col0]; ws1 = wsig[col0 + 1]; }
        #pragma unroll
        for (int i = 0; i < 4; i++) {
            #pragma unroll
            for (int h = 0; h < 2; h++) {
                const int lrow = wm * 64 + i * 16 + g + h * 8;
                const int row = rbase + lrow;
                float v0 = lrelu(acc[i][j][h * 2 + 0] + b0);
                float v1 = lrelu(acc[i][j][h * 2 + 1] + b1);
                if (DO_SIG) rp[i][h] += v0 * ws0 + v1 * ws1;
                __nv_bfloat162 hp = __floats2bfloat162_rn(v0, v1);
                float r0 = v0 - __bfloat162float(hp.x);
                float r1 = v1 - __bfloat162float(hp.y);
                __nv_bfloat162 lp = __floats2bfloat162_rn(r0, r1);
                *reinterpret_cast<__nv_bfloat162*>(Ch + (size_t)row * HID + col0) = hp;
                *reinterpret_cast<__nv_bfloat162*>(Cl + (size_t)row * HID + col0) = lp;
            }
        }
    }
    if (DO_SIG) {
        // deterministic reduction: sigbuf[row][wn*4+q], each slot single-writer
        float* sf = reinterpret_cast<float*>(smem + B2OFF);
        const int slot = wn * 4 + q;
        #pragma unroll
        for (int i = 0; i < 4; i++)
            #pragma unroll
            for (int h = 0; h < 2; h++) {
                const int lrow = wm * 64 + i * 16 + g + h * 8;
                sf[lrow * 32 + slot] = rp[i][h];
            }
        __syncthreads();
        if (tid < 128) {
            float s = 0.f;
            #pragma unroll
            for (int k = 0; k < 32; k++) s += sf[tid * 32 + k];
            sigout[rbase + tid] = s + bsig[0];
        }
    }
}

// ---------------------------------------------------------------------------
// Unified bf16x3 GEMM / implicit-GEMM conv (256 threads) — CNN + wc head.
// ---------------------------------------------------------------------------
template<int TAPS, int K, int NT, bool LRELU_, bool SPLIT_OUT, bool HAS_BIAS,
         bool HAS_RES, bool HAS_MOD>
__global__ void __launch_bounds__(256)
mma_gemm(const __nv_bfloat16* __restrict__ Ahi, const __nv_bfloat16* __restrict__ Alo,
         const __nv_bfloat16* __restrict__ Bhi, const __nv_bfloat16* __restrict__ Blo,
         const float* __restrict__ bias,
         const __nv_bfloat16* __restrict__ ResH, const __nv_bfloat16* __restrict__ ResL,
         const float* __restrict__ zc, int modoff,
         __nv_bfloat16* __restrict__ Chi, __nv_bfloat16* __restrict__ Clo,
         float* __restrict__ Cf, int OC) {
    extern __shared__ char smem[];
    constexpr int KCH    = K / 32;
    constexpr int NCHUNK = TAPS * KCH;
    constexpr int ASLAB  = 128 * 80;
    constexpr int BSLAB  = NT * 80;
    constexpr int BOFF   = 2 * ASLAB;
    constexpr int BUF    = 2 * ASLAB + 2 * BSLAB;
    constexpr int WN     = NT / 32;
    constexpr int MI     = WN;
    constexpr int MWT    = 16 * MI;
    constexpr size_t BTAP = (TAPS == 9) ? (size_t)HID * K : 0;

    const uint32_t sb = smem_u32(smem);
    const int tid = threadIdx.x;
    const int lane = tid & 31, wid = tid >> 5;
    const int wn = wid % WN, wm = wid / WN;
    const int g = lane >> 2, q = lane & 3;
    const int o0 = blockIdx.y * NT;
    const int rbase = blockIdx.x * 128;

    auto load_chunk = [&](int buf, int chunk) {
        const int tap = (TAPS == 9) ? (chunk / KCH) : 0;
        const int k0  = ((TAPS == 9) ? (chunk - tap * KCH) : chunk) * 32;
        const uint32_t base = sb + buf * BUF;
        #pragma unroll
        for (int t = 0; t < 2; t++) {
            const int idx = tid + t * 256;
            const int row = idx >> 2, c = idx & 3;
            uint32_t sz = 16;
            size_t grow;
            if (TAPS == 9) {
                const int dy = tap / 3 - 1, dx = tap % 3 - 1;
                const int py = (int)blockIdx.x + dy, px = row + dx;
                const bool ok = (py >= 0) && (py < HH) && (px >= 0) && (px < WW);
                sz = ok ? 16u : 0u;
                grow = ok ? (size_t)(py * WW + px) : 0;
            } else {
                grow = (size_t)(rbase + row);
            }
            const size_t go = grow * K + k0 + c * 8;
            const uint32_t d = base + row * 80 + c * 16;
            cpa16z(d,         Ahi + go, sz);
            cpa16z(d + ASLAB, Alo + go, sz);
        }
        const __nv_bfloat16* bh = Bhi + (size_t)tap * BTAP;
        const __nv_bfloat16* bl = Blo + (size_t)tap * BTAP;
        for (int idx = tid; idx < NT * 4; idx += 256) {
            const int row = idx >> 2, c = idx & 3;
            const size_t go = (size_t)(o0 + row) * K + k0 + c * 8;
            const uint32_t d = base + BOFF + row * 80 + c * 16;
            cpa16z(d,         bh + go, 16);
            cpa16z(d + BSLAB, bl + go, 16);
        }
        asm volatile("cp.async.commit_group;" ::: "memory");
    };

    float acc[MI][4][4];
    #pragma unroll
    for (int i = 0; i < MI; i++)
        #pragma unroll
        for (int j = 0; j < 4; j++)
            #pragma unroll
            for (int r = 0; r < 4; r++) acc[i][j][r] = 0.f;

    load_chunk(0, 0);
    for (int cc = 0; cc < NCHUNK; cc++) {
        if (cc + 1 < NCHUNK) {
            load_chunk((cc + 1) & 1, cc + 1);
            asm volatile("cp.async.wait_group 1;" ::: "memory");
        } else {
            asm volatile("cp.async.wait_group 0;" ::: "memory");
        }
        __syncthreads();
        const uint32_t Ab = sb + (cc & 1) * BUF;
        #pragma unroll
        for (int kk = 0; kk < 2; kk++) {
            const int ko = kk * 32;
            uint32_t ah[MI][4], al[MI][4];
            const uint32_t abase = Ab + ko + q * 4 + (wm * MWT + g) * 80;
            #pragma unroll
            for (int i = 0; i < MI; i++) {
                const uint32_t r = abase + i * (16 * 80);
                ah[i][0] = lds32(r);
                ah[i][1] = lds32(r + 8 * 80);
                ah[i][2] = lds32(r + 16);
                ah[i][3] = lds32(r + 8 * 80 + 16);
                const uint32_t rl = r + ASLAB;
                al[i][0] = lds32(rl);
                al[i][1] = lds32(rl + 8 * 80);
                al[i][2] = lds32(rl + 16);
                al[i][3] = lds32(rl + 8 * 80 + 16);
            }
            uint32_t bh[4][2], bl[4][2];
            const uint32_t bbase = Ab + BOFF + ko + q * 4 + (wn * 32 + g) * 80;
            #pragma unroll
            for (int j = 0; j < 4; j++) {
                const uint32_t r = bbase + j * (8 * 80);
                bh[j][0] = lds32(r);
                bh[j][1] = lds32(r + 16);
                bl[j][0] = lds32(r + BSLAB);
                bl[j][1] = lds32(r + BSLAB + 16);
            }
            #pragma unroll
            for (int i = 0; i < MI; i++)
                #pragma unroll
                for (int j = 0; j < 4; j++) {
                    mma16816(acc[i][j], ah[i], bh[j]);
                    mma16816(acc[i][j], al[i], bh[j]);
                    mma16816(acc[i][j], ah[i], bl[j]);
                }
        }
        __syncthreads();
    }

    #pragma unroll
    for (int j = 0; j < 4; j++) {
        const int col0 = o0 + wn * 32 + j * 8 + q * 2;
        const float b0 = HAS_BIAS ? bias[col0]     : 0.f;
        const float b1 = HAS_BIAS ? bias[col0 + 1] : 0.f;
        float sc0 = 1.f, sc1 = 1.f, sh0 = 0.f, sh1 = 0.f;
        if (HAS_MOD) {
            sc0 = zc[modoff + col0] + 1.f;       sc1 = zc[modoff + col0 + 1] + 1.f;
            sh0 = zc[modoff + HID + col0];       sh1 = zc[modoff + HID + col0 + 1];
        }
        #pragma unroll
        for (int i = 0; i < MI; i++) {
            #pragma unroll
            for (int h = 0; h < 2; h++) {
                const int row = rbase + wm * MWT + i * 16 + g + h * 8;
                float v0 = acc[i][j][h * 2 + 0] + b0;
                float v1 = acc[i][j][h * 2 + 1] + b1;
                if (HAS_RES) {
                    __nv_bfloat162 rh = *reinterpret_cast<const __nv_bfloat162*>(ResH + (size_t)row * OC + col0);
                    __nv_bfloat162 rl = *reinterpret_cast<const __nv_bfloat162*>(ResL + (size_t)row * OC + col0);
                    v0 += __bfloat162float(rh.x) + __bfloat162float(rl.x);
                    v1 += __bfloat162float(rh.y) + __bfloat162float(rl.y);
                }
                if (HAS_MOD) { v0 = v0 * sc0 + sh0; v1 = v1 * sc1 + sh1; }
                if (LRELU_)  { v0 = lrelu(v0); v1 = lrelu(v1); }
                if (SPLIT_OUT) {
                    __nv_bfloat162 hp = __floats2bfloat162_rn(v0, v1);
                    float r0 = v0 - __bfloat162float(hp.x);
                    float r1 = v1 - __bfloat162float(hp.y);
                    __nv_bfloat162 lp = __floats2bfloat162_rn(r0, r1);
                    *reinterpret_cast<__nv_bfloat162*>(Chi + (size_t)row * OC + col0) = hp;
                    *reinterpret_cast<__nv_bfloat162*>(Clo + (size_t)row * OC + col0) = lp;
                } else {
                    float2 v = {v0, v1};
                    *reinterpret_cast<float2*>(Cf + (size_t)row * OC + col0) = v;
                }
            }
        }
    }
}

// ---------------------------------------------------------------------------
// Volumetric compositing -> feat (pixel-major, bf16 hi/lo)
// ---------------------------------------------------------------------------
__global__ void composite_kernel(const float* __restrict__ sigma, const float* __restrict__ dists,
                                 const float* __restrict__ cbuf,
                                 __nv_bfloat16* __restrict__ feath,
                                 __nv_bfloat16* __restrict__ featl) {
    int pix = blockIdx.x;
    int t = threadIdx.x;
    __shared__ float wgt[MM];
    if (t == 0) {
        float T = 1.f;
        #pragma unroll
        for (int m = 0; m < MM; m++) {
            float sg = sigma[pix * MM + m];
            sg = sg > 0.f ? sg : 0.f;
            float a = 1.f - expf(-sg * dists[pix * MM + m]);
            wgt[m] = a * T;
            T *= (1.f - a + 1e-10f);
        }
    }
    __syncthreads();
    float acc = 0.f;
    #pragma unroll
    for (int m = 0; m < MM; m++)
        acc += wgt[m] * cbuf[(size_t)(pix * MM + m) * COL + t];
    split_store(acc, feath, featl, (size_t)pix * COL + t);
}

// ---------------------------------------------------------------------------
// Final 1x1 conv to 3 channels (warp per pixel)
// ---------------------------------------------------------------------------
__global__ void final_conv(const __nv_bfloat16* __restrict__ InH,
                           const __nv_bfloat16* __restrict__ InL,
                           const float* __restrict__ w,
                           const float* __restrict__ b, float* __restrict__ out) {
    int warp = (blockIdx.x * blockDim.x + threadIdx.x) >> 5;
    int lane = threadIdx.x & 31;
    if (warp >= HWPIX) return;
    const __nv_bfloat16* ph = InH + (size_t)warp * HID;
    const __nv_bfloat16* pl = InL + (size_t)warp * HID;
    float a0 = 0.f, a1 = 0.f, a2 = 0.f;
    #pragma unroll
    for (int t = 0; t < 8; t++) {
        int i = lane + 32 * t;
        float v = __bfloat162float(ph[i]) + __bfloat162float(pl[i]);
        a0 += v * w[i];
        a1 += v * w[HID + i];
        a2 += v * w[2 * HID + i];
    }
    #pragma unroll
    for (int off = 16; off; off >>= 1) {
        a0 += __shfl_xor_sync(0xFFFFFFFFu, a0, off);
        a1 += __shfl_xor_sync(0xFFFFFFFFu, a1, off);
        a2 += __shfl_xor_sync(0xFFFFFFFFu, a2, off);
    }
    if (lane == 0) {
        out[warp]             = a0 + b[0];
        out[HWPIX + warp]     = a1 + b[1];
        out[2 * HWPIX + warp] = a2 + b[2];
    }
}

// ---------------------------------------------------------------------------
// Launch
// ---------------------------------------------------------------------------
extern "C" void kernel_launch(void* const* d_in, const int* in_sizes, int n_in,
                              void* d_out, int out_size) {
    const float* x     = (const float*)d_in[0];
    const float* m     = (const float*)d_in[1];
    const float* z     = (const float*)d_in[2];
    const float* dists = (const float*)d_in[3];
    const float* w1    = (const float*)d_in[4];
    const float* b1    = (const float*)d_in[5];
    const float* wma   = (const float*)d_in[6];
    const float* ml_w  = (const float*)d_in[7];
    const float* ml_wa = (const float*)d_in[8];
    const float* ml_ba = (const float*)d_in[9];
    const float* ml_wb = (const float*)d_in[10];
    const float* ml_bb = (const float*)d_in[11];
    const float* wsig  = (const float*)d_in[12];
    const float* bsig  = (const float*)d_in[13];
    const float* wc    = (const float*)d_in[14];
    const float* bc    = (const float*)d_in[15];
    const float* wz    = (const float*)d_in[16];
    const float* bz    = (const float*)d_in[17];
    const float* c1_w  = (const float*)d_in[18];
    const float* c1_b  = (const float*)d_in[19];
    const float* c2a_w = (const float*)d_in[20];
    const float* c2a_b = (const float*)d_in[21];
    const float* c2b_w = (const float*)d_in[22];
    const float* c3a_w = (const float*)d_in[23];
    const float* c3a_b = (const float*)d_in[24];
    const float* c3b_w = (const float*)d_in[25];
    const float* c4a_w = (const float*)d_in[26];
    const float* c4a_b = (const float*)d_in[27];
    const float* c4b_w = (const float*)d_in[28];
    const float* c4b_b = (const float*)d_in[29];
    const float* c4_w  = (const float*)d_in[30];
    const float* c4_b  = (const float*)d_in[31];
    float* out = (float*)d_out;

    __nv_bfloat16 *xph, *xpl, *pah, *pal, *pbh, *pbl, *w1h, *w1l, *wmh, *wml, *wch, *wcl;
    __nv_bfloat16 *c3h, *c3l, *c1h, *c1l, *c4ah, *c4al, *c4bh, *c4bl;
    __nv_bfloat16 *yah, *yal, *ybh, *ybl, *ych, *ycl, *fth, *ftl;
    float *sig, *cb, *zcv, *be;
    cudaGetSymbolAddress((void**)&xph, d_xph);
    cudaGetSymbolAddress((void**)&xpl, d_xpl);
    cudaGetSymbolAddress((void**)&pah, d_pah);
    cudaGetSymbolAddress((void**)&pal, d_pal);
    cudaGetSymbolAddress((void**)&pbh, d_pbh);
    cudaGetSymbolAddress((void**)&pbl, d_pbl);
    cudaGetSymbolAddress((void**)&w1h, d_w1h);
    cudaGetSymbolAddress((void**)&w1l, d_w1l);
    cudaGetSymbolAddress((void**)&wmh, d_wmh);
    cudaGetSymbolAddress((void**)&wml, d_wml);
    cudaGetSymbolAddress((void**)&wch, d_wch);
    cudaGetSymbolAddress((void**)&wcl, d_wcl);
    cudaGetSymbolAddress((void**)&c3h, d_c3h);
    cudaGetSymbolAddress((void**)&c3l, d_c3l);
    cudaGetSymbolAddress((void**)&c1h, d_c1h);
    cudaGetSymbolAddress((void**)&c1l, d_c1l);
    cudaGetSymbolAddress((void**)&c4ah, d_c4ah);
    cudaGetSymbolAddress((void**)&c4al, d_c4al);
    cudaGetSymbolAddress((void**)&c4bh, d_c4bh);
    cudaGetSymbolAddress((void**)&c4bl, d_c4bl);
    cudaGetSymbolAddress((void**)&yah, d_yah);
    cudaGetSymbolAddress((void**)&yal, d_yal);
    cudaGetSymbolAddress((void**)&ybh, d_ybh);
    cudaGetSymbolAddress((void**)&ybl, d_ybl);
    cudaGetSymbolAddress((void**)&ych, d_ych);
    cudaGetSymbolAddress((void**)&ycl, d_ycl);
    cudaGetSymbolAddress((void**)&fth, d_feath);
    cudaGetSymbolAddress((void**)&ftl, d_featl);
    cudaGetSymbolAddress((void**)&sig, d_sig);
    cudaGetSymbolAddress((void**)&cb,  d_cbuf);
    cudaGetSymbolAddress((void**)&zcv, d_zc);
    cudaGetSymbolAddress((void**)&be,  d_beta);

    const int TW = 9 * HID * HID;
    const int SMF   = 2 * 128 * 528 + 2 * (2 * 256 * 80);  // 217088 (fused kernel)
    const int SM128 = 2 * (2 * 128 * 80 + 2 * 128 * 80);   // 81920
    const int SM64  = 2 * (2 * 128 * 80 + 2 * 64 * 80);    // 61440

    auto F1  = fused2<KP1, false>;
    auto F2  = fused2<HID, true >;
    auto F3  = fused2<HID, false>;
    auto GH  = mma_gemm<1, HID, 128, true,  true,  true,  false, false>;  // c4a
    auto GW  = mma_gemm<1, HID, 64,  false, false, true,  false, false>;  // wc -> fp32
    auto GC1 = mma_gemm<1, COL, 128, true,  true,  true,  false, false>;  // c1
    auto CA  = mma_gemm<9, HID, 128, true,  true,  true,  false, false>;  // c2a/c3a
    auto CB  = mma_gemm<9, HID, 128, true,  true,  false, true,  true >;  // c2b/c3b
    auto C4B = mma_gemm<1, HID, 128, true,  true,  true,  true,  false>;  // c4b

    cudaFuncSetAttribute(F1,  cudaFuncAttributeMaxDynamicSharedMemorySize, SMF);
    cudaFuncSetAttribute(F2,  cudaFuncAttributeMaxDynamicSharedMemorySize, SMF);
    cudaFuncSetAttribute(F3,  cudaFuncAttributeMaxDynamicSharedMemorySize, SMF);
    cudaFuncSetAttribute(GH,  cudaFuncAttributeMaxDynamicSharedMemorySize, SM128);
    cudaFuncSetAttribute(GW,  cudaFuncAttributeMaxDynamicSharedMemorySize, SM64);
    cudaFuncSetAttribute(GC1, cudaFuncAttributeMaxDynamicSharedMemorySize, SM128);
    cudaFuncSetAttribute(CA,  cudaFuncAttributeMaxDynamicSharedMemorySize, SM128);
    cudaFuncSetAttribute(CB,  cudaFuncAttributeMaxDynamicSharedMemorySize, SM128);
    cudaFuncSetAttribute(C4B, cudaFuncAttributeMaxDynamicSharedMemorySize, SM128);

    // --- prep ---
    prep_vec<<<448, 256>>>(z, ml_wa, ml_ba, ml_wb, ml_bb, wz, bz);
    prep_fold_split<<<(5 * HID * HID + 255) / 256, 256>>>(ml_w);
    prep_w1p<<<(HID * KP1 + 255) / 256, 256>>>(w1, wma);
    prep_pair<<<(COL * HID + 255) / 256, 256>>>(wc, wch, wcl, COL * HID);
    prep_xm<<<(int)(((size_t)S_TOT * KP1 + 255) / 256), 256>>>(x, m);
    prep_tw_split<<<(TW + 255) / 256, 256>>>(c2a_w, c3h + 0 * TW, c3l + 0 * TW);
    prep_tw_split<<<(TW + 255) / 256, 256>>>(c2b_w, c3h + 1 * TW, c3l + 1 * TW);
    prep_tw_split<<<(TW + 255) / 256, 256>>>(c3a_w, c3h + 2 * TW, c3l + 2 * TW);
    prep_tw_split<<<(TW + 255) / 256, 256>>>(c3b_w, c3h + 3 * TW, c3l + 3 * TW);
    prep_pair<<<(HID * COL + 255) / 256, 256>>>(c1_w, c1h, c1l, HID * COL);
    prep_pair<<<(HID * HID + 255) / 256, 256>>>(c4a_w, c4ah, c4al, HID * HID);
    prep_pair<<<(HID * HID + 255) / 256, 256>>>(c4b_w, c4bh, c4bl, HID * HID);

    // --- MLP: 3 fused layer-pair kernels + wc head ---
    F1<<<S_TOT / 128, 512, SMF>>>(xph, xpl, w1h, w1l, b1,
                                  wmh + 0 * 65536, wml + 0 * 65536, be + 0,
                                  pah, pal, nullptr, nullptr, nullptr);
    F2<<<S_TOT / 128, 512, SMF>>>(pah, pal, wmh + 1 * 65536, wml + 1 * 65536, be + 256,
                                  wmh + 2 * 65536, wml + 2 * 65536, be + 512,
                                  pbh, pbl, wsig, bsig, sig);
    F3<<<S_TOT / 128, 512, SMF>>>(pbh, pbl, wmh + 3 * 65536, wml + 3 * 65536, be + 768,
                                  wmh + 4 * 65536, wml + 4 * 65536, be + 1024,
                                  pah, pal, nullptr, nullptr, nullptr);
    GW<<<dim3(S_TOT / 128, 1), 256, SM64>>>(pah, pal, wch, wcl, bc, nullptr, nullptr,
                                            nullptr, 0, nullptr, nullptr, cb, COL);

    // --- compositing ---
    composite_kernel<<<HWPIX, 64>>>(sig, dists, cb, fth, ftl);

    // --- CNN (bf16x3 implicit-GEMM mma) ---
    dim3 gC(HH, 2);
    GC1<<<gC, 256, SM128>>>(fth, ftl, c1h, c1l, c1_b, nullptr, nullptr, nullptr, 0, yah, yal, nullptr, HID);
    CA <<<gC, 256, SM128>>>(yah, yal, c3h + 0 * TW, c3l + 0 * TW, c2a_b, nullptr, nullptr, nullptr, 0, ybh, ybl, nullptr, HID);
    CB <<<gC, 256, SM128>>>(ybh, ybl, c3h + 1 * TW, c3l + 1 * TW, nullptr, yah, yal, zcv, 0,   ych, ycl, nullptr, HID);
    CA <<<gC, 256, SM128>>>(ych, ycl, c3h + 2 * TW, c3l + 2 * TW, c3a_b, nullptr, nullptr, nullptr, 0, ybh, ybl, nullptr, HID);
    CB <<<gC, 256, SM128>>>(ybh, ybl, c3h + 3 * TW, c3l + 3 * TW, nullptr, ych, ycl, zcv, 512, yah, yal, nullptr, HID);
    GH <<<gC, 256, SM128>>>(yah, yal, c4ah, c4al, c4a_b, nullptr, nullptr, nullptr, 0, ybh, ybl, nullptr, HID);
    C4B<<<gC, 256, SM128>>>(ybh, ybl, c4bh, c4bl, c4b_b, yah, yal, nullptr, 0, ych, ycl, nullptr, HID);
    final_conv<<<HWPIX / 8, 256>>>(ych, ycl, c4_w, c4_b, out);

    (void)in_sizes; (void)n_in; (void)out_size;
}

// round 6
// speedup vs baseline: 2.9919x; 1.0629x over previous
#include <cuda_runtime.h>
#include <cuda_bf16.h>
#include <cstdint>

// ---------------------------------------------------------------------------
// Problem constants
// ---------------------------------------------------------------------------
#define HH      128
#define WW      128
#define MM      16
#define CIN     128
#define NC      7
#define HID     256
#define STY     256
#define COL     64
#define HWPIX   (HH * WW)            // 16384
#define S_TOT   (HWPIX * MM)         // 262144
#define KQ1     192                  // padded K for layer 1: 128 (x) + 7 (m) + 57 zeros

// Fixed-point constants: value = scale * (Q1*128 + Q2) / 16256,  Q1,Q2 int8
#define QMAX    16256.0f             // 127 * 128
#define QDEN    (16256.0f * 16256.0f)

// ---------------------------------------------------------------------------
// Scratch (device globals; no runtime allocation allowed)
// ---------------------------------------------------------------------------
// MLP int8 activations + per-row scales
__device__ int8_t d_xq1[(size_t)S_TOT * KQ1];
__device__ int8_t d_xq2[(size_t)S_TOT * KQ1];
__device__ float  d_xs[S_TOT];
__device__ int8_t d_aq1[(size_t)S_TOT * HID];
__device__ int8_t d_aq2[(size_t)S_TOT * HID];
__device__ float  d_as[S_TOT];
__device__ int8_t d_bq1[(size_t)S_TOT * HID];
__device__ int8_t d_bq2[(size_t)S_TOT * HID];
__device__ float  d_bsc[S_TOT];
// MLP int8 weights + per-outchannel scales
__device__ int8_t d_w1q1[HID * KQ1];
__device__ int8_t d_w1q2[HID * KQ1];
__device__ float  d_w1s[HID];
__device__ int8_t d_wmq1[5 * HID * HID];
__device__ int8_t d_wmq2[5 * HID * HID];
__device__ float  d_wms[5 * HID];
__device__ int8_t d_wcq1[COL * HID];
__device__ int8_t d_wcq2[COL * HID];
__device__ float  d_wcs[COL];
// CNN weights (bf16 hi/lo)
__device__ __nv_bfloat16 d_c3h[4 * 9 * HID * HID];
__device__ __nv_bfloat16 d_c3l[4 * 9 * HID * HID];
__device__ __nv_bfloat16 d_c1h[HID * COL];
__device__ __nv_bfloat16 d_c1l[HID * COL];
__device__ __nv_bfloat16 d_c4ah[HID * HID];
__device__ __nv_bfloat16 d_c4al[HID * HID];
__device__ __nv_bfloat16 d_c4bh[HID * HID];
__device__ __nv_bfloat16 d_c4bl[HID * HID];
// CNN activations: pixel-major [pix][chan], bf16 hi/lo
__device__ __nv_bfloat16 d_yah[HWPIX * HID];
__device__ __nv_bfloat16 d_yal[HWPIX * HID];
__device__ __nv_bfloat16 d_ybh[HWPIX * HID];
__device__ __nv_bfloat16 d_ybl[HWPIX * HID];
__device__ __nv_bfloat16 d_ych[HWPIX * HID];
__device__ __nv_bfloat16 d_ycl[HWPIX * HID];
__device__ __nv_bfloat16 d_feath[HWPIX * COL];
__device__ __nv_bfloat16 d_featl[HWPIX * COL];
__device__ float d_sig[S_TOT];
__device__ float d_cbuf[(size_t)S_TOT * COL];
__device__ float d_alpha[5 * HID];
__device__ float d_beta[5 * HID];
__device__ float d_zc[4 * HID];

static __device__ __forceinline__ float lrelu(float v) {
    return v > 0.f ? v : 0.2f * v;
}

static __device__ __forceinline__ uint32_t smem_u32(const void* p) {
    uint32_t a;
    asm("{ .reg .u64 t; cvta.to.shared.u64 t, %1; cvt.u32.u64 %0, t; }" : "=r"(a) : "l"(p));
    return a;
}

static __device__ __forceinline__ void cpa16z(uint32_t dst, const void* src, uint32_t sz) {
    asm volatile("cp.async.cg.shared.global [%0], [%1], 16, %2;"
                 :: "r"(dst), "l"(src), "r"(sz));
}

static __device__ __forceinline__ uint32_t lds32(uint32_t a) {
    uint32_t v;
    asm volatile("ld.shared.b32 %0, [%1];" : "=r"(v) : "r"(a));
    return v;
}

static __device__ __forceinline__ void mma16816(float* d, const uint32_t* a, const uint32_t* b) {
    asm volatile(
        "mma.sync.aligned.m16n8k16.row.col.f32.bf16.bf16.f32 "
        "{%0,%1,%2,%3}, {%4,%5,%6,%7}, {%8,%9}, {%0,%1,%2,%3};"
        : "+f"(d[0]), "+f"(d[1]), "+f"(d[2]), "+f"(d[3])
        : "r"(a[0]), "r"(a[1]), "r"(a[2]), "r"(a[3]), "r"(b[0]), "r"(b[1]));
}

static __device__ __forceinline__ void imma16832(int* d, const uint32_t* a, const uint32_t* b) {
    asm volatile(
        "mma.sync.aligned.m16n8k32.row.col.s32.s8.s8.s32 "
        "{%0,%1,%2,%3}, {%4,%5,%6,%7}, {%8,%9}, {%0,%1,%2,%3};"
        : "+r"(d[0]), "+r"(d[1]), "+r"(d[2]), "+r"(d[3])
        : "r"(a[0]), "r"(a[1]), "r"(a[2]), "r"(a[3]), "r"(b[0]), "r"(b[1]));
}

// Quantize v (|v|<=mx) to q1*128+q2 with q1 in [-127,127], q2 in [-64,64]
static __device__ __forceinline__ void quant2(float v, float inv, int& q1, int& q2) {
    float qf = rintf(v * inv);
    int   q  = (int)qf;
    q1 = (int)rintf(qf * (1.f / 128.f));
    q2 = q - (q1 << 7);
}

// ---------------------------------------------------------------------------
// Prep kernels
// ---------------------------------------------------------------------------
__global__ void prep_vec(const float* __restrict__ z,
                         const float* __restrict__ wa, const float* __restrict__ ba,
                         const float* __restrict__ wb, const float* __restrict__ bb,
                         const float* __restrict__ wz, const float* __restrict__ bz) {
    int warp = (blockIdx.x * blockDim.x + threadIdx.x) >> 5;
    int lane = threadIdx.x & 31;
    if (warp >= 3584) return;
    const float* row; float bias; float* out;
    if (warp < 1280)      { row = wa + (size_t)warp * STY; bias = ba[warp]; out = d_alpha + warp; }
    else if (warp < 2560) { int i = warp - 1280; row = wb + (size_t)i * STY; bias = bb[i]; out = d_beta + i; }
    else                  { int i = warp - 2560; row = wz + (size_t)i * STY; bias = bz[i]; out = d_zc + i; }
    float acc = 0.f;
    #pragma unroll
    for (int t = 0; t < 8; t++) acc += z[lane + 32 * t] * row[lane + 32 * t];
    #pragma unroll
    for (int off = 16; off; off >>= 1) acc += __shfl_xor_sync(0xFFFFFFFFu, acc, off);
    if (lane == 0) *out = acc + bias;
}

static __device__ __forceinline__ float warp_amax(float a) {
    #pragma unroll
    for (int off = 16; off; off >>= 1) a = fmaxf(a, __shfl_xor_sync(0xFFFFFFFFu, a, off));
    return a;
}

// Quantize [x||m] rows -> xq planes (K padded to 192)
__global__ void prep_xq(const float* __restrict__ x, const float* __restrict__ m) {
    int s = blockIdx.x * 8 + (threadIdx.x >> 5);
    int lane = threadIdx.x & 31;
    if (s >= S_TOT) return;
    float v[6];
    #pragma unroll
    for (int t = 0; t < 6; t++) {
        int c = lane + 32 * t;
        float val = 0.f;
        if (c < CIN)           val = x[(size_t)s * CIN + c];
        else if (c < CIN + NC) val = m[(size_t)s * NC + (c - CIN)];
        v[t] = val;
    }
    float am = 0.f;
    #pragma unroll
    for (int t = 0; t < 6; t++) am = fmaxf(am, fabsf(v[t]));
    am = warp_amax(am);
    if (lane == 0) d_xs[s] = am;
    float inv = QMAX / fmaxf(am, 1e-20f);
    #pragma unroll
    for (int t = 0; t < 6; t++) {
        int c = lane + 32 * t;
        int q1, q2; quant2(v[t], inv, q1, q2);
        d_xq1[(size_t)s * KQ1 + c] = (int8_t)q1;
        d_xq2[(size_t)s * KQ1 + c] = (int8_t)q2;
    }
}

// Quantize [w1||wma] rows -> w1q (K padded to 192)
__global__ void prep_w1q(const float* __restrict__ w1, const float* __restrict__ wma) {
    int o = blockIdx.x * 8 + (threadIdx.x >> 5);
    int lane = threadIdx.x & 31;
    if (o >= HID) return;
    float v[6];
    #pragma unroll
    for (int t = 0; t < 6; t++) {
        int c = lane + 32 * t;
        float val = 0.f;
        if (c < CIN)           val = w1[(size_t)o * CIN + c];
        else if (c < CIN + NC) val = wma[(size_t)o * NC + (c - CIN)];
        v[t] = val;
    }
    float am = 0.f;
    #pragma unroll
    for (int t = 0; t < 6; t++) am = fmaxf(am, fabsf(v[t]));
    am = warp_amax(am);
    if (lane == 0) d_w1s[o] = am;
    float inv = QMAX / fmaxf(am, 1e-20f);
    #pragma unroll
    for (int t = 0; t < 6; t++) {
        int c = lane + 32 * t;
        int q1, q2; quant2(v[t], inv, q1, q2);
        d_w1q1[(size_t)o * KQ1 + c] = (int8_t)q1;
        d_w1q2[(size_t)o * KQ1 + c] = (int8_t)q2;
    }
}

// Fold alpha into ModLinear weights and quantize per-outchannel
__global__ void prep_wmq(const float* __restrict__ mlw) {
    int r = blockIdx.x * 8 + (threadIdx.x >> 5);   // 5*HID rows
    int lane = threadIdx.x & 31;
    if (r >= 5 * HID) return;
    int layer = r >> 8;
    float v[8];
    #pragma unroll
    for (int t = 0; t < 8; t++) {
        int k = lane + 32 * t;
        v[t] = mlw[(size_t)r * HID + k] * d_alpha[layer * HID + k];
    }
    float am = 0.f;
    #pragma unroll
    for (int t = 0; t < 8; t++) am = fmaxf(am, fabsf(v[t]));
    am = warp_amax(am);
    if (lane == 0) d_wms[r] = am;
    float inv = QMAX / fmaxf(am, 1e-20f);
    #pragma unroll
    for (int t = 0; t < 8; t++) {
        int k = lane + 32 * t;
        int q1, q2; quant2(v[t], inv, q1, q2);
        d_wmq1[(size_t)r * HID + k] = (int8_t)q1;
        d_wmq2[(size_t)r * HID + k] = (int8_t)q2;
    }
}

__global__ void prep_wcq(const float* __restrict__ wc) {
    int o = blockIdx.x * 8 + (threadIdx.x >> 5);
    int lane = threadIdx.x & 31;
    if (o >= COL) return;
    float v[8];
    #pragma unroll
    for (int t = 0; t < 8; t++) v[t] = wc[(size_t)o * HID + lane + 32 * t];
    float am = 0.f;
    #pragma unroll
    for (int t = 0; t < 8; t++) am = fmaxf(am, fabsf(v[t]));
    am = warp_amax(am);
    if (lane == 0) d_wcs[o] = am;
    float inv = QMAX / fmaxf(am, 1e-20f);
    #pragma unroll
    for (int t = 0; t < 8; t++) {
        int q1, q2; quant2(v[t], inv, q1, q2);
        d_wcq1[(size_t)o * HID + lane + 32 * t] = (int8_t)q1;
        d_wcq2[(size_t)o * HID + lane + 32 * t] = (int8_t)q2;
    }
}

static __device__ __forceinline__ void split_store(float v, __nv_bfloat16* hi,
                                                   __nv_bfloat16* lo, size_t idx) {
    __nv_bfloat16 h = __float2bfloat16(v);
    hi[idx] = h;
    lo[idx] = __float2bfloat16(v - __bfloat162float(h));
}

__global__ void prep_pair(const float* __restrict__ w, __nv_bfloat16* __restrict__ hi,
                          __nv_bfloat16* __restrict__ lo, int n) {
    int idx = blockIdx.x * blockDim.x + threadIdx.x;
    if (idx >= n) return;
    split_store(w[idx], hi, lo, idx);
}

// [O][K][9] -> [tap][O][K], bf16 hi/lo
__global__ void prep_tw_split(const float* __restrict__ w, __nv_bfloat16* __restrict__ hi,
                              __nv_bfloat16* __restrict__ lo) {
    int idx = blockIdx.x * blockDim.x + threadIdx.x;
    if (idx >= 9 * HID * HID) return;
    int tap = idx / (HID * HID);
    int ok  = idx - tap * (HID * HID);
    split_store(w[(size_t)ok * 9 + tap], hi, lo, idx);
}

// ---------------------------------------------------------------------------
// int8 two-digit GEMM via mma.sync.m16n8k32.s8 (exact s32 accumulation).
// C[r][o] = epi( sa[r]*sb[o]*(16384*acc1 + 128*acc2)/16256^2 + bias[o] )
// acc1 = A1*B1, acc2 = A1*B2 + A2*B1  (A2*B2 dropped, ~2^-16 rel).
// CTA 256 threads, tile MT x NT; 80B-padded int8 rows (conflict-free).
// QOUT: epilogue re-quantizes output rows (per-row amax via smem atomicMax).
// ---------------------------------------------------------------------------
template<int MT, int NT, int K, bool LRELU_, bool QOUT>
__global__ void __launch_bounds__(256)
imma_gemm(const int8_t* __restrict__ Aq1, const int8_t* __restrict__ Aq2,
          const float* __restrict__ As,
          const int8_t* __restrict__ Bq1, const int8_t* __restrict__ Bq2,
          const float* __restrict__ Bs,
          const float* __restrict__ bias,
          int8_t* __restrict__ Oq1, int8_t* __restrict__ Oq2, float* __restrict__ Os,
          float* __restrict__ Of, int OC) {
    extern __shared__ char smem[];
    constexpr int NCH   = K / 64;
    constexpr int ASLAB = MT * 80;
    constexpr int BSLAB = NT * 80;
    constexpr int BOFF  = 2 * ASLAB;
    constexpr int BUF   = 2 * ASLAB + 2 * BSLAB;
    constexpr int WN    = NT / 32;        // warps along N
    constexpr int WM    = 8 / WN;         // warps along M
    constexpr int MI    = MT / (16 * WM); // m16-atoms per warp

    const uint32_t sb = smem_u32(smem);
    const int tid = threadIdx.x;
    const int lane = tid & 31, wid = tid >> 5;
    const int wn = wid % WN, wm = wid / WN;
    const int g = lane >> 2, q = lane & 3;
    const int rbase = blockIdx.x * MT;
    const int o0 = blockIdx.y * NT;

    auto load_chunk = [&](int buf, int c) {
        const uint32_t base = sb + buf * BUF;
        const int k0 = c * 64;
        #pragma unroll
        for (int idx = tid; idx < MT * 4; idx += 256) {
            const int row = idx >> 2, cc = idx & 3;
            const size_t go = (size_t)(rbase + row) * K + k0 + cc * 16;
            const uint32_t d = base + row * 80 + cc * 16;
            cpa16z(d,         Aq1 + go, 16);
            cpa16z(d + ASLAB, Aq2 + go, 16);
        }
        #pragma unroll
        for (int idx = tid; idx < NT * 4; idx += 256) {
            const int row = idx >> 2, cc = idx & 3;
            const size_t go = (size_t)(o0 + row) * K + k0 + cc * 16;
            const uint32_t d = base + BOFF + row * 80 + cc * 16;
            cpa16z(d,         Bq1 + go, 16);
            cpa16z(d + BSLAB, Bq2 + go, 16);
        }
        asm volatile("cp.async.commit_group;" ::: "memory");
    };

    int acc1[MI][4][4], acc2[MI][4][4];
    #pragma unroll
    for (int i = 0; i < MI; i++)
        #pragma unroll
        for (int j = 0; j < 4; j++)
            #pragma unroll
            for (int r = 0; r < 4; r++) { acc1[i][j][r] = 0; acc2[i][j][r] = 0; }

    load_chunk(0, 0);
    for (int c = 0; c < NCH; c++) {
        if (c + 1 < NCH) {
            load_chunk((c + 1) & 1, c + 1);
            asm volatile("cp.async.wait_group 1;" ::: "memory");
        } else {
            asm volatile("cp.async.wait_group 0;" ::: "memory");
        }
        __syncthreads();
        const uint32_t Ab = sb + (c & 1) * BUF;
        #pragma unroll
        for (int kk = 0; kk < 2; kk++) {
            const int koff = kk * 32;
            uint32_t a1[MI][4], a2[MI][4];
            const uint32_t abase = Ab + koff + q * 4 + (wm * MI * 16 + g) * 80;
            #pragma unroll
            for (int i = 0; i < MI; i++) {
                const uint32_t r = abase + i * (16 * 80);
                a1[i][0] = lds32(r);            a1[i][1] = lds32(r + 8 * 80);
                a1[i][2] = lds32(r + 16);       a1[i][3] = lds32(r + 8 * 80 + 16);
                const uint32_t rl = r + ASLAB;
                a2[i][0] = lds32(rl);           a2[i][1] = lds32(rl + 8 * 80);
                a2[i][2] = lds32(rl + 16);      a2[i][3] = lds32(rl + 8 * 80 + 16);
            }
            uint32_t b1[4][2], b2[4][2];
            const uint32_t bbase = Ab + BOFF + koff + q * 4 + (wn * 32 + g) * 80;
            #pragma unroll
            for (int j = 0; j < 4; j++) {
                const uint32_t r = bbase + j * (8 * 80);
                b1[j][0] = lds32(r);            b1[j][1] = lds32(r + 16);
                b2[j][0] = lds32(r + BSLAB);    b2[j][1] = lds32(r + BSLAB + 16);
            }
            #pragma unroll
            for (int i = 0; i < MI; i++)
                #pragma unroll
                for (int j = 0; j < 4; j++) {
                    imma16832(acc1[i][j], a1[i], b1[j]);
                    imma16832(acc2[i][j], a1[i], b2[j]);
                    imma16832(acc2[i][j], a2[i], b1[j]);
                }
        }
        __syncthreads();
    }

    // --------------- epilogue ---------------
    float* sf = reinterpret_cast<float*>(smem);     // reused smem: per-row amax
    if (QOUT) {
        if (tid < MT) sf[tid] = 0.f;
        __syncthreads();
    }
    // per-column constants
    float sbv[4][2], bv[4][2];
    #pragma unroll
    for (int j = 0; j < 4; j++) {
        const int col0 = o0 + wn * 32 + j * 8 + q * 2;
        sbv[j][0] = Bs[col0];     sbv[j][1] = Bs[col0 + 1];
        bv[j][0]  = bias[col0];   bv[j][1]  = bias[col0 + 1];
    }
    // pass 1: compute fp32 values (stored back into acc1 as float bits), row amax
    #pragma unroll
    for (int i = 0; i < MI; i++) {
        #pragma unroll
        for (int h = 0; h < 2; h++) {
            const int lrow = wm * MI * 16 + i * 16 + g + h * 8;
            const float sa = As[rbase + lrow] * (1.f / QDEN);
            float rmax = 0.f;
            #pragma unroll
            for (int j = 0; j < 4; j++) {
                float t0 = 16384.f * (float)acc1[i][j][h * 2 + 0] + 128.f * (float)acc2[i][j][h * 2 + 0];
                float t1 = 16384.f * (float)acc1[i][j][h * 2 + 1] + 128.f * (float)acc2[i][j][h * 2 + 1];
                float v0 = sa * sbv[j][0] * t0 + bv[j][0];
                float v1 = sa * sbv[j][1] * t1 + bv[j][1];
                if (LRELU_) { v0 = lrelu(v0); v1 = lrelu(v1); }
                acc1[i][j][h * 2 + 0] = __float_as_int(v0);
                acc1[i][j][h * 2 + 1] = __float_as_int(v1);
                rmax = fmaxf(rmax, fmaxf(fabsf(v0), fabsf(v1)));
            }
            if (QOUT) atomicMax(reinterpret_cast<int*>(&sf[lrow]), __float_as_int(rmax));
        }
    }
    if (QOUT) {
        __syncthreads();
        #pragma unroll
        for (int i = 0; i < MI; i++) {
            #pragma unroll
            for (int h = 0; h < 2; h++) {
                const int lrow = wm * MI * 16 + i * 16 + g + h * 8;
                const int grow = rbase + lrow;
                const float mx = sf[lrow];
                const float inv = QMAX / fmaxf(mx, 1e-20f);
                if (wn == 0 && q == 0) Os[grow] = mx;
                #pragma unroll
                for (int j = 0; j < 4; j++) {
                    const int col0 = o0 + wn * 32 + j * 8 + q * 2;
                    float v0 = __int_as_float(acc1[i][j][h * 2 + 0]);
                    float v1 = __int_as_float(acc1[i][j][h * 2 + 1]);
                    int p1, p2, r1, r2;
                    quant2(v0, inv, p1, p2);
                    quant2(v1, inv, r1, r2);
                    char2 o1; o1.x = (char)p1; o1.y = (char)r1;
                    char2 o2; o2.x = (char)p2; o2.y = (char)r2;
                    *reinterpret_cast<char2*>(Oq1 + (size_t)grow * OC + col0) = o1;
                    *reinterpret_cast<char2*>(Oq2 + (size_t)grow * OC + col0) = o2;
                }
            }
        }
    } else {
        #pragma unroll
        for (int i = 0; i < MI; i++) {
            #pragma unroll
            for (int h = 0; h < 2; h++) {
                const int lrow = wm * MI * 16 + i * 16 + g + h * 8;
                const int grow = rbase + lrow;
                #pragma unroll
                for (int j = 0; j < 4; j++) {
                    const int col0 = o0 + wn * 32 + j * 8 + q * 2;
                    float2 v;
                    v.x = __int_as_float(acc1[i][j][h * 2 + 0]);
                    v.y = __int_as_float(acc1[i][j][h * 2 + 1]);
                    *reinterpret_cast<float2*>(Of + (size_t)grow * OC + col0) = v;
                }
            }
        }
    }
}

// ---------------------------------------------------------------------------
// sigma[s] = wsig . dequant(f[s]) + bsig  (warp per sample)
// ---------------------------------------------------------------------------
__global__ void sigma_q(const int8_t* __restrict__ A1, const int8_t* __restrict__ A2,
                        const float* __restrict__ As, const float* __restrict__ wsig,
                        const float* __restrict__ bsig, float* __restrict__ out) {
    int s = (blockIdx.x * blockDim.x + threadIdx.x) >> 5;
    int lane = threadIdx.x & 31;
    if (s >= S_TOT) return;
    const char4* p1 = reinterpret_cast<const char4*>(A1 + (size_t)s * HID);
    const char4* p2 = reinterpret_cast<const char4*>(A2 + (size_t)s * HID);
    float acc = 0.f;
    #pragma unroll
    for (int t = 0; t < 2; t++) {
        int idx = lane + 32 * t;
        char4 c1 = p1[idx];
        char4 c2 = p2[idx];
        int k = idx * 4;
        acc += (float)(c1.x * 128 + c2.x) * wsig[k + 0];
        acc += (float)(c1.y * 128 + c2.y) * wsig[k + 1];
        acc += (float)(c1.z * 128 + c2.z) * wsig[k + 2];
        acc += (float)(c1.w * 128 + c2.w) * wsig[k + 3];
    }
    #pragma unroll
    for (int off = 16; off; off >>= 1) acc += __shfl_xor_sync(0xFFFFFFFFu, acc, off);
    if (lane == 0) out[s] = acc * (As[s] * (1.f / QMAX)) + bsig[0];
}

// ---------------------------------------------------------------------------
// Unified bf16x3 GEMM / implicit-GEMM conv (256 threads) — CNN.
// ---------------------------------------------------------------------------
template<int TAPS, int K, int NT, bool LRELU_, bool SPLIT_OUT, bool HAS_BIAS,
         bool HAS_RES, bool HAS_MOD>
__global__ void __launch_bounds__(256)
mma_gemm(const __nv_bfloat16* __restrict__ Ahi, const __nv_bfloat16* __restrict__ Alo,
         const __nv_bfloat16* __restrict__ Bhi, const __nv_bfloat16* __restrict__ Blo,
         const float* __restrict__ bias,
         const __nv_bfloat16* __restrict__ ResH, const __nv_bfloat16* __restrict__ ResL,
         const float* __restrict__ zc, int modoff,
         __nv_bfloat16* __restrict__ Chi, __nv_bfloat16* __restrict__ Clo,
         float* __restrict__ Cf, int OC) {
    extern __shared__ char smem[];
    constexpr int KCH    = K / 32;
    constexpr int NCHUNK = TAPS * KCH;
    constexpr int ASLAB  = 128 * 80;
    constexpr int BSLAB  = NT * 80;
    constexpr int BOFF   = 2 * ASLAB;
    constexpr int BUF    = 2 * ASLAB + 2 * BSLAB;
    constexpr int WN     = NT / 32;
    constexpr int MI     = WN;
    constexpr int MWT    = 16 * MI;
    constexpr size_t BTAP = (TAPS == 9) ? (size_t)HID * K : 0;

    const uint32_t sb = smem_u32(smem);
    const int tid = threadIdx.x;
    const int lane = tid & 31, wid = tid >> 5;
    const int wn = wid % WN, wm = wid / WN;
    const int g = lane >> 2, q = lane & 3;
    const int o0 = blockIdx.y * NT;
    const int rbase = blockIdx.x * 128;

    auto load_chunk = [&](int buf, int chunk) {
        const int tap = (TAPS == 9) ? (chunk / KCH) : 0;
        const int k0  = ((TAPS == 9) ? (chunk - tap * KCH) : chunk) * 32;
        const uint32_t base = sb + buf * BUF;
        #pragma unroll
        for (int t = 0; t < 2; t++) {
            const int idx = tid + t * 256;
            const int row = idx >> 2, c = idx & 3;
            uint32_t sz = 16;
            size_t grow;
            if (TAPS == 9) {
                const int dy = tap / 3 - 1, dx = tap % 3 - 1;
                const int py = (int)blockIdx.x + dy, px = row + dx;
                const bool ok = (py >= 0) && (py < HH) && (px >= 0) && (px < WW);
                sz = ok ? 16u : 0u;
                grow = ok ? (size_t)(py * WW + px) : 0;
            } else {
                grow = (size_t)(rbase + row);
            }
            const size_t go = grow * K + k0 + c * 8;
            const uint32_t d = base + row * 80 + c * 16;
            cpa16z(d,         Ahi + go, sz);
            cpa16z(d + ASLAB, Alo + go, sz);
        }
        const __nv_bfloat16* bh = Bhi + (size_t)tap * BTAP;
        const __nv_bfloat16* bl = Blo + (size_t)tap * BTAP;
        for (int idx = tid; idx < NT * 4; idx += 256) {
            const int row = idx >> 2, c = idx & 3;
            const size_t go = (size_t)(o0 + row) * K + k0 + c * 8;
            const uint32_t d = base + BOFF + row * 80 + c * 16;
            cpa16z(d,         bh + go, 16);
            cpa16z(d + BSLAB, bl + go, 16);
        }
        asm volatile("cp.async.commit_group;" ::: "memory");
    };

    float acc[MI][4][4];
    #pragma unroll
    for (int i = 0; i < MI; i++)
        #pragma unroll
        for (int j = 0; j < 4; j++)
            #pragma unroll
            for (int r = 0; r < 4; r++) acc[i][j][r] = 0.f;

    load_chunk(0, 0);
    for (int cc = 0; cc < NCHUNK; cc++) {
        if (cc + 1 < NCHUNK) {
            load_chunk((cc + 1) & 1, cc + 1);
            asm volatile("cp.async.wait_group 1;" ::: "memory");
        } else {
            asm volatile("cp.async.wait_group 0;" ::: "memory");
        }
        __syncthreads();
        const uint32_t Ab = sb + (cc & 1) * BUF;
        #pragma unroll
        for (int kk = 0; kk < 2; kk++) {
            const int ko = kk * 32;
            uint32_t ah[MI][4], al[MI][4];
            const uint32_t abase = Ab + ko + q * 4 + (wm * MWT + g) * 80;
            #pragma unroll
            for (int i = 0; i < MI; i++) {
                const uint32_t r = abase + i * (16 * 80);
                ah[i][0] = lds32(r);
                ah[i][1] = lds32(r + 8 * 80);
                ah[i][2] = lds32(r + 16);
                ah[i][3] = lds32(r + 8 * 80 + 16);
                const uint32_t rl = r + ASLAB;
                al[i][0] = lds32(rl);
                al[i][1] = lds32(rl + 8 * 80);
                al[i][2] = lds32(rl + 16);
                al[i][3] = lds32(rl + 8 * 80 + 16);
            }
            uint32_t bh[4][2], bl[4][2];
            const uint32_t bbase = Ab + BOFF + ko + q * 4 + (wn * 32 + g) * 80;
            #pragma unroll
            for (int j = 0; j < 4; j++) {
                const uint32_t r = bbase + j * (8 * 80);
                bh[j][0] = lds32(r);
                bh[j][1] = lds32(r + 16);
                bl[j][0] = lds32(r + BSLAB);
                bl[j][1] = lds32(r + BSLAB + 16);
            }
            #pragma unroll
            for (int i = 0; i < MI; i++)
                #pragma unroll
                for (int j = 0; j < 4; j++) {
                    mma16816(acc[i][j], ah[i], bh[j]);
                    mma16816(acc[i][j], al[i], bh[j]);
                    mma16816(acc[i][j], ah[i], bl[j]);
                }
        }
        __syncthreads();
    }

    #pragma unroll
    for (int j = 0; j < 4; j++) {
        const int col0 = o0 + wn * 32 + j * 8 + q * 2;
        const float b0 = HAS_BIAS ? bias[col0]     : 0.f;
        const float b1 = HAS_BIAS ? bias[col0 + 1] : 0.f;
        float sc0 = 1.f, sc1 = 1.f, sh0 = 0.f, sh1 = 0.f;
        if (HAS_MOD) {
            sc0 = zc[modoff + col0] + 1.f;       sc1 = zc[modoff + col0 + 1] + 1.f;
            sh0 = zc[modoff + HID + col0];       sh1 = zc[modoff + HID + col0 + 1];
        }
        #pragma unroll
        for (int i = 0; i < MI; i++) {
            #pragma unroll
            for (int h = 0; h < 2; h++) {
                const int row = rbase + wm * MWT + i * 16 + g + h * 8;
                float v0 = acc[i][j][h * 2 + 0] + b0;
                float v1 = acc[i][j][h * 2 + 1] + b1;
                if (HAS_RES) {
                    __nv_bfloat162 rh = *reinterpret_cast<const __nv_bfloat162*>(ResH + (size_t)row * OC + col0);
                    __nv_bfloat162 rl = *reinterpret_cast<const __nv_bfloat162*>(ResL + (size_t)row * OC + col0);
                    v0 += __bfloat162float(rh.x) + __bfloat162float(rl.x);
                    v1 += __bfloat162float(rh.y) + __bfloat162float(rl.y);
                }
                if (HAS_MOD) { v0 = v0 * sc0 + sh0; v1 = v1 * sc1 + sh1; }
                if (LRELU_)  { v0 = lrelu(v0); v1 = lrelu(v1); }
                if (SPLIT_OUT) {
                    __nv_bfloat162 hp = __floats2bfloat162_rn(v0, v1);
                    float r0 = v0 - __bfloat162float(hp.x);
                    float r1 = v1 - __bfloat162float(hp.y);
                    __nv_bfloat162 lp = __floats2bfloat162_rn(r0, r1);
                    *reinterpret_cast<__nv_bfloat162*>(Chi + (size_t)row * OC + col0) = hp;
                    *reinterpret_cast<__nv_bfloat162*>(Clo + (size_t)row * OC + col0) = lp;
                } else {
                    float2 v = {v0, v1};
                    *reinterpret_cast<float2*>(Cf + (size_t)row * OC + col0) = v;
                }
            }
        }
    }
}

// ---------------------------------------------------------------------------
// Volumetric compositing -> feat (pixel-major, bf16 hi/lo)
// ---------------------------------------------------------------------------
__global__ void composite_kernel(const float* __restrict__ sigma, const float* __restrict__ dists,
                                 const float* __restrict__ cbuf,
                                 __nv_bfloat16* __restrict__ feath,
                                 __nv_bfloat16* __restrict__ featl) {
    int pix = blockIdx.x;
    int t = threadIdx.x;
    __shared__ float wgt[MM];
    if (t == 0) {
        float T = 1.f;
        #pragma unroll
        for (int m = 0; m < MM; m++) {
            float sg = sigma[pix * MM + m];
            sg = sg > 0.f ? sg : 0.f;
            float a = 1.f - expf(-sg * dists[pix * MM + m]);
            wgt[m] = a * T;
            T *= (1.f - a + 1e-10f);
        }
    }
    __syncthreads();
    float acc = 0.f;
    #pragma unroll
    for (int m = 0; m < MM; m++)
        acc += wgt[m] * cbuf[(size_t)(pix * MM + m) * COL + t];
    split_store(acc, feath, featl, (size_t)pix * COL + t);
}

// ---------------------------------------------------------------------------
// Final 1x1 conv to 3 channels (warp per pixel)
// ---------------------------------------------------------------------------
__global__ void final_conv(const __nv_bfloat16* __restrict__ InH,
                           const __nv_bfloat16* __restrict__ InL,
                           const float* __restrict__ w,
                           const float* __restrict__ b, float* __restrict__ out) {
    int warp = (blockIdx.x * blockDim.x + threadIdx.x) >> 5;
    int lane = threadIdx.x & 31;
    if (warp >= HWPIX) return;
    const __nv_bfloat16* ph = InH + (size_t)warp * HID;
    const __nv_bfloat16* pl = InL + (size_t)warp * HID;
    float a0 = 0.f, a1 = 0.f, a2 = 0.f;
    #pragma unroll
    for (int t = 0; t < 8; t++) {
        int i = lane + 32 * t;
        float v = __bfloat162float(ph[i]) + __bfloat162float(pl[i]);
        a0 += v * w[i];
        a1 += v * w[HID + i];
        a2 += v * w[2 * HID + i];
    }
    #pragma unroll
    for (int off = 16; off; off >>= 1) {
        a0 += __shfl_xor_sync(0xFFFFFFFFu, a0, off);
        a1 += __shfl_xor_sync(0xFFFFFFFFu, a1, off);
        a2 += __shfl_xor_sync(0xFFFFFFFFu, a2, off);
    }
    if (lane == 0) {
        out[warp]             = a0 + b[0];
        out[HWPIX + warp]     = a1 + b[1];
        out[2 * HWPIX + warp] = a2 + b[2];
    }
}

// ---------------------------------------------------------------------------
// Launch
// ---------------------------------------------------------------------------
extern "C" void kernel_launch(void* const* d_in, const int* in_sizes, int n_in,
                              void* d_out, int out_size) {
    const float* x     = (const float*)d_in[0];
    const float* m     = (const float*)d_in[1];
    const float* z     = (const float*)d_in[2];
    const float* dists = (const float*)d_in[3];
    const float* w1    = (const float*)d_in[4];
    const float* b1    = (const float*)d_in[5];
    const float* wma   = (const float*)d_in[6];
    const float* ml_w  = (const float*)d_in[7];
    const float* ml_wa = (const float*)d_in[8];
    const float* ml_ba = (const float*)d_in[9];
    const float* ml_wb = (const float*)d_in[10];
    const float* ml_bb = (const float*)d_in[11];
    const float* wsig  = (const float*)d_in[12];
    const float* bsig  = (const float*)d_in[13];
    const float* wc    = (const float*)d_in[14];
    const float* bc    = (const float*)d_in[15];
    const float* wz    = (const float*)d_in[16];
    const float* bz    = (const float*)d_in[17];
    const float* c1_w  = (const float*)d_in[18];
    const float* c1_b  = (const float*)d_in[19];
    const float* c2a_w = (const float*)d_in[20];
    const float* c2a_b = (const float*)d_in[21];
    const float* c2b_w = (const float*)d_in[22];
    const float* c3a_w = (const float*)d_in[23];
    const float* c3a_b = (const float*)d_in[24];
    const float* c3b_w = (const float*)d_in[25];
    const float* c4a_w = (const float*)d_in[26];
    const float* c4a_b = (const float*)d_in[27];
    const float* c4b_w = (const float*)d_in[28];
    const float* c4b_b = (const float*)d_in[29];
    const float* c4_w  = (const float*)d_in[30];
    const float* c4_b  = (const float*)d_in[31];
    float* out = (float*)d_out;

    int8_t *xq1, *xq2, *aq1, *aq2, *bq1, *bq2;
    int8_t *w1q1, *w1q2, *wmq1, *wmq2, *wcq1, *wcq2;
    float *xs, *as, *bsc, *w1s, *wms, *wcs;
    __nv_bfloat16 *c3h, *c3l, *c1h, *c1l, *c4ah, *c4al, *c4bh, *c4bl;
    __nv_bfloat16 *yah, *yal, *ybh, *ybl, *ych, *ycl, *fth, *ftl;
    float *sig, *cb, *zcv, *be;
    cudaGetSymbolAddress((void**)&xq1, d_xq1);
    cudaGetSymbolAddress((void**)&xq2, d_xq2);
    cudaGetSymbolAddress((void**)&xs,  d_xs);
    cudaGetSymbolAddress((void**)&aq1, d_aq1);
    cudaGetSymbolAddress((void**)&aq2, d_aq2);
    cudaGetSymbolAddress((void**)&as,  d_as);
    cudaGetSymbolAddress((void**)&bq1, d_bq1);
    cudaGetSymbolAddress((void**)&bq2, d_bq2);
    cudaGetSymbolAddress((void**)&bsc, d_bsc);
    cudaGetSymbolAddress((void**)&w1q1, d_w1q1);
    cudaGetSymbolAddress((void**)&w1q2, d_w1q2);
    cudaGetSymbolAddress((void**)&w1s,  d_w1s);
    cudaGetSymbolAddress((void**)&wmq1, d_wmq1);
    cudaGetSymbolAddress((void**)&wmq2, d_wmq2);
    cudaGetSymbolAddress((void**)&wms,  d_wms);
    cudaGetSymbolAddress((void**)&wcq1, d_wcq1);
    cudaGetSymbolAddress((void**)&wcq2, d_wcq2);
    cudaGetSymbolAddress((void**)&wcs,  d_wcs);
    cudaGetSymbolAddress((void**)&c3h, d_c3h);
    cudaGetSymbolAddress((void**)&c3l, d_c3l);
    cudaGetSymbolAddress((void**)&c1h, d_c1h);
    cudaGetSymbolAddress((void**)&c1l, d_c1l);
    cudaGetSymbolAddress((void**)&c4ah, d_c4ah);
    cudaGetSymbolAddress((void**)&c4al, d_c4al);
    cudaGetSymbolAddress((void**)&c4bh, d_c4bh);
    cudaGetSymbolAddress((void**)&c4bl, d_c4bl);
    cudaGetSymbolAddress((void**)&yah, d_yah);
    cudaGetSymbolAddress((void**)&yal, d_yal);
    cudaGetSymbolAddress((void**)&ybh, d_ybh);
    cudaGetSymbolAddress((void**)&ybl, d_ybl);
    cudaGetSymbolAddress((void**)&ych, d_ych);
    cudaGetSymbolAddress((void**)&ycl, d_ycl);
    cudaGetSymbolAddress((void**)&fth, d_feath);
    cudaGetSymbolAddress((void**)&ftl, d_featl);
    cudaGetSymbolAddress((void**)&sig, d_sig);
    cudaGetSymbolAddress((void**)&cb,  d_cbuf);
    cudaGetSymbolAddress((void**)&zcv, d_zc);
    cudaGetSymbolAddress((void**)&be,  d_beta);

    const int TW = 9 * HID * HID;
    // smem sizes
    const int SMI_L  = 2 * (2 * 64 * 80 + 2 * 256 * 80);   // 102400 (MT=64, NT=256)
    const int SMI_W  = 2 * (2 * 128 * 80 + 2 * 64 * 80);   // 61440  (MT=128, NT=64)
    const int SM128  = 2 * (2 * 128 * 80 + 2 * 128 * 80);  // 81920 (CNN bf16)

    auto L1 = imma_gemm<64, 256, KQ1, true,  true >;
    auto LH = imma_gemm<64, 256, HID, true,  true >;
    auto LW = imma_gemm<128, 64, HID, false, false>;
    auto GH  = mma_gemm<1, HID, 128, true,  true,  true,  false, false>;  // c4a
    auto GC1 = mma_gemm<1, COL, 128, true,  true,  true,  false, false>;  // c1
    auto CA  = mma_gemm<9, HID, 128, true,  true,  true,  false, false>;  // c2a/c3a
    auto CB  = mma_gemm<9, HID, 128, true,  true,  false, true,  true >;  // c2b/c3b
    auto C4B = mma_gemm<1, HID, 128, true,  true,  true,  true,  false>;  // c4b

    cudaFuncSetAttribute(L1,  cudaFuncAttributeMaxDynamicSharedMemorySize, SMI_L);
    cudaFuncSetAttribute(LH,  cudaFuncAttributeMaxDynamicSharedMemorySize, SMI_L);
    cudaFuncSetAttribute(LW,  cudaFuncAttributeMaxDynamicSharedMemorySize, SMI_W);
    cudaFuncSetAttribute(GH,  cudaFuncAttributeMaxDynamicSharedMemorySize, SM128);
    cudaFuncSetAttribute(GC1, cudaFuncAttributeMaxDynamicSharedMemorySize, SM128);
    cudaFuncSetAttribute(CA,  cudaFuncAttributeMaxDynamicSharedMemorySize, SM128);
    cudaFuncSetAttribute(CB,  cudaFuncAttributeMaxDynamicSharedMemorySize, SM128);
    cudaFuncSetAttribute(C4B, cudaFuncAttributeMaxDynamicSharedMemorySize, SM128);

    // --- prep ---
    prep_vec<<<448, 256>>>(z, ml_wa, ml_ba, ml_wb, ml_bb, wz, bz);
    prep_xq<<<S_TOT / 8, 256>>>(x, m);
    prep_w1q<<<HID / 8, 256>>>(w1, wma);
    prep_wmq<<<5 * HID / 8, 256>>>(ml_w);
    prep_wcq<<<COL / 8, 256>>>(wc);
    prep_tw_split<<<(TW + 255) / 256, 256>>>(c2a_w, c3h + 0 * TW, c3l + 0 * TW);
    prep_tw_split<<<(TW + 255) / 256, 256>>>(c2b_w, c3h + 1 * TW, c3l + 1 * TW);
    prep_tw_split<<<(TW + 255) / 256, 256>>>(c3a_w, c3h + 2 * TW, c3l + 2 * TW);
    prep_tw_split<<<(TW + 255) / 256, 256>>>(c3b_w, c3h + 3 * TW, c3l + 3 * TW);
    prep_pair<<<(HID * COL + 255) / 256, 256>>>(c1_w, c1h, c1l, HID * COL);
    prep_pair<<<(HID * HID + 255) / 256, 256>>>(c4a_w, c4ah, c4al, HID * HID);
    prep_pair<<<(HID * HID + 255) / 256, 256>>>(c4b_w, c4bh, c4bl, HID * HID);

    // --- MLP (int8 two-digit IMMA) ---
    const int GR = S_TOT / 64;  // 4096
    L1<<<GR, 256, SMI_L>>>(xq1, xq2, xs, w1q1, w1q2, w1s, b1,
                           aq1, aq2, as, nullptr, HID);
    LH<<<GR, 256, SMI_L>>>(aq1, aq2, as, wmq1 + 0 * 65536, wmq2 + 0 * 65536, wms + 0,
                           be + 0,    bq1, bq2, bsc, nullptr, HID);
    LH<<<GR, 256, SMI_L>>>(bq1, bq2, bsc, wmq1 + 1 * 65536, wmq2 + 1 * 65536, wms + 256,
                           be + 256,  aq1, aq2, as, nullptr, HID);
    LH<<<GR, 256, SMI_L>>>(aq1, aq2, as, wmq1 + 2 * 65536, wmq2 + 2 * 65536, wms + 512,
                           be + 512,  bq1, bq2, bsc, nullptr, HID);
    sigma_q<<<S_TOT / 8, 256>>>(bq1, bq2, bsc, wsig, bsig, sig);
    LH<<<GR, 256, SMI_L>>>(bq1, bq2, bsc, wmq1 + 3 * 65536, wmq2 + 3 * 65536, wms + 768,
                           be + 768,  aq1, aq2, as, nullptr, HID);
    LH<<<GR, 256, SMI_L>>>(aq1, aq2, as, wmq1 + 4 * 65536, wmq2 + 4 * 65536, wms + 1024,
                           be + 1024, bq1, bq2, bsc, nullptr, HID);
    LW<<<S_TOT / 128, 256, SMI_W>>>(bq1, bq2, bsc, wcq1, wcq2, wcs, bc,
                                    nullptr, nullptr, nullptr, cb, COL);

    // --- compositing ---
    composite_kernel<<<HWPIX, 64>>>(sig, dists, cb, fth, ftl);

    // --- CNN (bf16x3 implicit-GEMM mma) ---
    dim3 gC(HH, 2);
    GC1<<<gC, 256, SM128>>>(fth, ftl, c1h, c1l, c1_b, nullptr, nullptr, nullptr, 0, yah, yal, nullptr, HID);
    CA <<<gC, 256, SM128>>>(yah, yal, c3h + 0 * TW, c3l + 0 * TW, c2a_b, nullptr, nullptr, nullptr, 0, ybh, ybl, nullptr, HID);
    CB <<<gC, 256, SM128>>>(ybh, ybl, c3h + 1 * TW, c3l + 1 * TW, nullptr, yah, yal, zcv, 0,   ych, ycl, nullptr, HID);
    CA <<<gC, 256, SM128>>>(ych, ycl, c3h + 2 * TW, c3l + 2 * TW, c3a_b, nullptr, nullptr, nullptr, 0, ybh, ybl, nullptr, HID);
    CB <<<gC, 256, SM128>>>(ybh, ybl, c3h + 3 * TW, c3l + 3 * TW, nullptr, ych, ycl, zcv, 512, yah, yal, nullptr, HID);
    GH <<<gC, 256, SM128>>>(yah, yal, c4ah, c4al, c4a_b, nullptr, nullptr, nullptr, 0, ybh, ybl, nullptr, HID);
    C4B<<<gC, 256, SM128>>>(ybh, ybl, c4bh, c4bl, c4b_b, yah, yal, nullptr, 0, ych, ycl, nullptr, HID);
    final_conv<<<HWPIX / 8, 256>>>(ych, ycl, c4_w, c4_b, out);

    (void)in_sizes; (void)n_in; (void)out_size;
}

// round 7
// speedup vs baseline: 3.0618x; 1.0234x over previous
#include <cuda_runtime.h>
#include <cuda_bf16.h>
#include <cstdint>

// ---------------------------------------------------------------------------
// Problem constants
// ---------------------------------------------------------------------------
#define HH      128
#define WW      128
#define MM      16
#define CIN     128
#define NC      7
#define HID     256
#define STY     256
#define COL     64
#define HWPIX   (HH * WW)            // 16384
#define S_TOT   (HWPIX * MM)         // 262144
#define KQ1     192                  // padded K for layer 1: 128 (x) + 7 (m) + 57 zeros

// Fixed-point constants: value = scale * (Q1*128 + Q2) / 16256,  Q1,Q2 int8
#define QMAX    16256.0f             // 127 * 128
#define QDEN    (16256.0f * 16256.0f)

// ---------------------------------------------------------------------------
// Scratch (device globals; no runtime allocation allowed)
// ---------------------------------------------------------------------------
__device__ int8_t d_xq1[(size_t)S_TOT * KQ1];
__device__ int8_t d_xq2[(size_t)S_TOT * KQ1];
__device__ float  d_xs[S_TOT];
__device__ int8_t d_aq1[(size_t)S_TOT * HID];
__device__ int8_t d_aq2[(size_t)S_TOT * HID];
__device__ float  d_as[S_TOT];
__device__ int8_t d_bq1[(size_t)S_TOT * HID];
__device__ int8_t d_bq2[(size_t)S_TOT * HID];
__device__ float  d_bsc[S_TOT];
__device__ int8_t d_w1q1[HID * KQ1];
__device__ int8_t d_w1q2[HID * KQ1];
__device__ float  d_w1s[HID];
__device__ int8_t d_wmq1[5 * HID * HID];
__device__ int8_t d_wmq2[5 * HID * HID];
__device__ float  d_wms[5 * HID];
__device__ int8_t d_wcq1[COL * HID];
__device__ int8_t d_wcq2[COL * HID];
__device__ float  d_wcs[COL];
// CNN weights (bf16 hi/lo)
__device__ __nv_bfloat16 d_c3h[4 * 9 * HID * HID];
__device__ __nv_bfloat16 d_c3l[4 * 9 * HID * HID];
__device__ __nv_bfloat16 d_c1h[HID * COL];
__device__ __nv_bfloat16 d_c1l[HID * COL];
__device__ __nv_bfloat16 d_c4ah[HID * HID];
__device__ __nv_bfloat16 d_c4al[HID * HID];
__device__ __nv_bfloat16 d_c4bh[HID * HID];
__device__ __nv_bfloat16 d_c4bl[HID * HID];
// CNN activations: pixel-major [pix][chan], bf16 hi/lo
__device__ __nv_bfloat16 d_yah[HWPIX * HID];
__device__ __nv_bfloat16 d_yal[HWPIX * HID];
__device__ __nv_bfloat16 d_ybh[HWPIX * HID];
__device__ __nv_bfloat16 d_ybl[HWPIX * HID];
__device__ __nv_bfloat16 d_ych[HWPIX * HID];
__device__ __nv_bfloat16 d_ycl[HWPIX * HID];
__device__ __nv_bfloat16 d_feath[HWPIX * COL];
__device__ __nv_bfloat16 d_featl[HWPIX * COL];
__device__ float d_sig[S_TOT];
__device__ float d_cbuf[(size_t)S_TOT * COL];
__device__ float d_alpha[5 * HID];
__device__ float d_beta[5 * HID];
__device__ float d_zc[4 * HID];

static __device__ __forceinline__ float lrelu(float v) {
    return v > 0.f ? v : 0.2f * v;
}

static __device__ __forceinline__ uint32_t smem_u32(const void* p) {
    uint32_t a;
    asm("{ .reg .u64 t; cvta.to.shared.u64 t, %1; cvt.u32.u64 %0, t; }" : "=r"(a) : "l"(p));
    return a;
}

static __device__ __forceinline__ void cpa16z(uint32_t dst, const void* src, uint32_t sz) {
    asm volatile("cp.async.cg.shared.global [%0], [%1], 16, %2;"
                 :: "r"(dst), "l"(src), "r"(sz));
}

static __device__ __forceinline__ void ldm_x4(uint32_t* r, uint32_t addr) {
    asm volatile("ldmatrix.sync.aligned.m8n8.x4.shared.b16 {%0,%1,%2,%3}, [%4];"
                 : "=r"(r[0]), "=r"(r[1]), "=r"(r[2]), "=r"(r[3]) : "r"(addr));
}

static __device__ __forceinline__ void mma16816(float* d, const uint32_t* a, const uint32_t* b) {
    asm volatile(
        "mma.sync.aligned.m16n8k16.row.col.f32.bf16.bf16.f32 "
        "{%0,%1,%2,%3}, {%4,%5,%6,%7}, {%8,%9}, {%0,%1,%2,%3};"
        : "+f"(d[0]), "+f"(d[1]), "+f"(d[2]), "+f"(d[3])
        : "r"(a[0]), "r"(a[1]), "r"(a[2]), "r"(a[3]), "r"(b[0]), "r"(b[1]));
}

static __device__ __forceinline__ void imma16832(int* d, const uint32_t* a, const uint32_t* b) {
    asm volatile(
        "mma.sync.aligned.m16n8k32.row.col.s32.s8.s8.s32 "
        "{%0,%1,%2,%3}, {%4,%5,%6,%7}, {%8,%9}, {%0,%1,%2,%3};"
        : "+r"(d[0]), "+r"(d[1]), "+r"(d[2]), "+r"(d[3])
        : "r"(a[0]), "r"(a[1]), "r"(a[2]), "r"(a[3]), "r"(b[0]), "r"(b[1]));
}

// A-fragment ldmatrix address: block row0, 32B k-chunk at koff, 80B row stride.
// matrix0=rows0-7/k0, m1=rows8-15/k0, m2=rows0-7/k16, m3=rows8-15/k16.
static __device__ __forceinline__ uint32_t ldm_a_addr(uint32_t base, int lane) {
    return base + (uint32_t)(lane & 15) * 80 + (uint32_t)((lane >> 4) << 4);
}
// B-pair ldmatrix address (two n8 blocks): m0=n0-7/k0, m1=n0-7/k16, m2=n8-15/k0, m3=n8-15/k16.
static __device__ __forceinline__ uint32_t ldm_b_addr(uint32_t base, int lane) {
    const int n = (lane & 7) + ((lane >= 16) ? 8 : 0);
    const int k16 = ((lane >> 3) & 1) << 4;
    return base + (uint32_t)n * 80 + (uint32_t)k16;
}

// Quantize v to q1*128+q2 with q1,q2 int8
static __device__ __forceinline__ void quant2(float v, float inv, int& q1, int& q2) {
    float qf = rintf(v * inv);
    int   q  = (int)qf;
    q1 = (int)rintf(qf * (1.f / 128.f));
    q2 = q - (q1 << 7);
}

// ---------------------------------------------------------------------------
// Prep kernels
// ---------------------------------------------------------------------------
__global__ void prep_vec(const float* __restrict__ z,
                         const float* __restrict__ wa, const float* __restrict__ ba,
                         const float* __restrict__ wb, const float* __restrict__ bb,
                         const float* __restrict__ wz, const float* __restrict__ bz) {
    int warp = (blockIdx.x * blockDim.x + threadIdx.x) >> 5;
    int lane = threadIdx.x & 31;
    if (warp >= 3584) return;
    const float* row; float bias; float* out;
    if (warp < 1280)      { row = wa + (size_t)warp * STY; bias = ba[warp]; out = d_alpha + warp; }
    else if (warp < 2560) { int i = warp - 1280; row = wb + (size_t)i * STY; bias = bb[i]; out = d_beta + i; }
    else                  { int i = warp - 2560; row = wz + (size_t)i * STY; bias = bz[i]; out = d_zc + i; }
    float acc = 0.f;
    #pragma unroll
    for (int t = 0; t < 8; t++) acc += z[lane + 32 * t] * row[lane + 32 * t];
    #pragma unroll
    for (int off = 16; off; off >>= 1) acc += __shfl_xor_sync(0xFFFFFFFFu, acc, off);
    if (lane == 0) *out = acc + bias;
}

static __device__ __forceinline__ float warp_amax(float a) {
    #pragma unroll
    for (int off = 16; off; off >>= 1) a = fmaxf(a, __shfl_xor_sync(0xFFFFFFFFu, a, off));
    return a;
}

__global__ void prep_xq(const float* __restrict__ x, const float* __restrict__ m) {
    int s = blockIdx.x * 8 + (threadIdx.x >> 5);
    int lane = threadIdx.x & 31;
    if (s >= S_TOT) return;
    float v[6];
    #pragma unroll
    for (int t = 0; t < 6; t++) {
        int c = lane + 32 * t;
        float val = 0.f;
        if (c < CIN)           val = x[(size_t)s * CIN + c];
        else if (c < CIN + NC) val = m[(size_t)s * NC + (c - CIN)];
        v[t] = val;
    }
    float am = 0.f;
    #pragma unroll
    for (int t = 0; t < 6; t++) am = fmaxf(am, fabsf(v[t]));
    am = warp_amax(am);
    if (lane == 0) d_xs[s] = am;
    float inv = QMAX / fmaxf(am, 1e-20f);
    #pragma unroll
    for (int t = 0; t < 6; t++) {
        int c = lane + 32 * t;
        int q1, q2; quant2(v[t], inv, q1, q2);
        d_xq1[(size_t)s * KQ1 + c] = (int8_t)q1;
        d_xq2[(size_t)s * KQ1 + c] = (int8_t)q2;
    }
}

__global__ void prep_w1q(const float* __restrict__ w1, const float* __restrict__ wma) {
    int o = blockIdx.x * 8 + (threadIdx.x >> 5);
    int lane = threadIdx.x & 31;
    if (o >= HID) return;
    float v[6];
    #pragma unroll
    for (int t = 0; t < 6; t++) {
        int c = lane + 32 * t;
        float val = 0.f;
        if (c < CIN)           val = w1[(size_t)o * CIN + c];
        else if (c < CIN + NC) val = wma[(size_t)o * NC + (c - CIN)];
        v[t] = val;
    }
    float am = 0.f;
    #pragma unroll
    for (int t = 0; t < 6; t++) am = fmaxf(am, fabsf(v[t]));
    am = warp_amax(am);
    if (lane == 0) d_w1s[o] = am;
    float inv = QMAX / fmaxf(am, 1e-20f);
    #pragma unroll
    for (int t = 0; t < 6; t++) {
        int c = lane + 32 * t;
        int q1, q2; quant2(v[t], inv, q1, q2);
        d_w1q1[(size_t)o * KQ1 + c] = (int8_t)q1;
        d_w1q2[(size_t)o * KQ1 + c] = (int8_t)q2;
    }
}

__global__ void prep_wmq(const float* __restrict__ mlw) {
    int r = blockIdx.x * 8 + (threadIdx.x >> 5);
    int lane = threadIdx.x & 31;
    if (r >= 5 * HID) return;
    int layer = r >> 8;
    float v[8];
    #pragma unroll
    for (int t = 0; t < 8; t++) {
        int k = lane + 32 * t;
        v[t] = mlw[(size_t)r * HID + k] * d_alpha[layer * HID + k];
    }
    float am = 0.f;
    #pragma unroll
    for (int t = 0; t < 8; t++) am = fmaxf(am, fabsf(v[t]));
    am = warp_amax(am);
    if (lane == 0) d_wms[r] = am;
    float inv = QMAX / fmaxf(am, 1e-20f);
    #pragma unroll
    for (int t = 0; t < 8; t++) {
        int k = lane + 32 * t;
        int q1, q2; quant2(v[t], inv, q1, q2);
        d_wmq1[(size_t)r * HID + k] = (int8_t)q1;
        d_wmq2[(size_t)r * HID + k] = (int8_t)q2;
    }
}

__global__ void prep_wcq(const float* __restrict__ wc) {
    int o = blockIdx.x * 8 + (threadIdx.x >> 5);
    int lane = threadIdx.x & 31;
    if (o >= COL) return;
    float v[8];
    #pragma unroll
    for (int t = 0; t < 8; t++) v[t] = wc[(size_t)o * HID + lane + 32 * t];
    float am = 0.f;
    #pragma unroll
    for (int t = 0; t < 8; t++) am = fmaxf(am, fabsf(v[t]));
    am = warp_amax(am);
    if (lane == 0) d_wcs[o] = am;
    float inv = QMAX / fmaxf(am, 1e-20f);
    #pragma unroll
    for (int t = 0; t < 8; t++) {
        int q1, q2; quant2(v[t], inv, q1, q2);
        d_wcq1[(size_t)o * HID + lane + 32 * t] = (int8_t)q1;
        d_wcq2[(size_t)o * HID + lane + 32 * t] = (int8_t)q2;
    }
}

static __device__ __forceinline__ void split_store(float v, __nv_bfloat16* hi,
                                                   __nv_bfloat16* lo, size_t idx) {
    __nv_bfloat16 h = __float2bfloat16(v);
    hi[idx] = h;
    lo[idx] = __float2bfloat16(v - __bfloat162float(h));
}

__global__ void prep_pair(const float* __restrict__ w, __nv_bfloat16* __restrict__ hi,
                          __nv_bfloat16* __restrict__ lo, int n) {
    int idx = blockIdx.x * blockDim.x + threadIdx.x;
    if (idx >= n) return;
    split_store(w[idx], hi, lo, idx);
}

__global__ void prep_tw_split(const float* __restrict__ w, __nv_bfloat16* __restrict__ hi,
                              __nv_bfloat16* __restrict__ lo) {
    int idx = blockIdx.x * blockDim.x + threadIdx.x;
    if (idx >= 9 * HID * HID) return;
    int tap = idx / (HID * HID);
    int ok  = idx - tap * (HID * HID);
    split_store(w[(size_t)ok * 9 + tap], hi, lo, idx);
}

// ---------------------------------------------------------------------------
// int8 two-digit GEMM via mma.sync.m16n8k32.s8 + ldmatrix fragment loads.
// ---------------------------------------------------------------------------
template<int NTHR, int MT, int NT, int K, bool LRELU_, bool QOUT>
__global__ void __launch_bounds__(NTHR)
imma_gemm(const int8_t* __restrict__ Aq1, const int8_t* __restrict__ Aq2,
          const float* __restrict__ As,
          const int8_t* __restrict__ Bq1, const int8_t* __restrict__ Bq2,
          const float* __restrict__ Bs,
          const float* __restrict__ bias,
          int8_t* __restrict__ Oq1, int8_t* __restrict__ Oq2, float* __restrict__ Os,
          float* __restrict__ Of, int OC) {
    extern __shared__ char smem[];
    constexpr int NCH   = K / 64;
    constexpr int ASLAB = MT * 80;
    constexpr int BSLAB = NT * 80;
    constexpr int BOFF  = 2 * ASLAB;
    constexpr int BUF   = 2 * ASLAB + 2 * BSLAB;
    constexpr int NW    = NTHR / 32;
    constexpr int WN    = NT / 32;
    constexpr int WM    = NW / WN;
    constexpr int MI    = MT / (16 * WM);

    const uint32_t sb = smem_u32(smem);
    const int tid = threadIdx.x;
    const int lane = tid & 31, wid = tid >> 5;
    const int wn = wid % WN, wm = wid / WN;
    const int g = lane >> 2, q = lane & 3;
    const int rbase = blockIdx.x * MT;
    const int o0 = blockIdx.y * NT;

    auto load_chunk = [&](int buf, int c) {
        const uint32_t base = sb + buf * BUF;
        const int k0 = c * 64;
        for (int idx = tid; idx < MT * 4; idx += NTHR) {
            const int row = idx >> 2, cc = idx & 3;
            const size_t go = (size_t)(rbase + row) * K + k0 + cc * 16;
            const uint32_t d = base + row * 80 + cc * 16;
            cpa16z(d,         Aq1 + go, 16);
            cpa16z(d + ASLAB, Aq2 + go, 16);
        }
        for (int idx = tid; idx < NT * 4; idx += NTHR) {
            const int row = idx >> 2, cc = idx & 3;
            const size_t go = (size_t)(o0 + row) * K + k0 + cc * 16;
            const uint32_t d = base + BOFF + row * 80 + cc * 16;
            cpa16z(d,         Bq1 + go, 16);
            cpa16z(d + BSLAB, Bq2 + go, 16);
        }
        asm volatile("cp.async.commit_group;" ::: "memory");
    };

    int acc1[MI][4][4], acc2[MI][4][4];
    #pragma unroll
    for (int i = 0; i < MI; i++)
        #pragma unroll
        for (int j = 0; j < 4; j++)
            #pragma unroll
            for (int r = 0; r < 4; r++) { acc1[i][j][r] = 0; acc2[i][j][r] = 0; }

    load_chunk(0, 0);
    for (int c = 0; c < NCH; c++) {
        if (c + 1 < NCH) {
            load_chunk((c + 1) & 1, c + 1);
            asm volatile("cp.async.wait_group 1;" ::: "memory");
        } else {
            asm volatile("cp.async.wait_group 0;" ::: "memory");
        }
        __syncthreads();
        const uint32_t Ab = sb + (c & 1) * BUF;
        const uint32_t Bb = Ab + BOFF;
        #pragma unroll
        for (int kk = 0; kk < 2; kk++) {
            const int koff = kk * 32;
            uint32_t a1[MI][4], a2[MI][4];
            #pragma unroll
            for (int i = 0; i < MI; i++) {
                const uint32_t r0 = ldm_a_addr(Ab + (uint32_t)(wm * MI * 16 + i * 16) * 80 + koff, lane);
                ldm_x4(a1[i], r0);
                ldm_x4(a2[i], r0 + ASLAB);
            }
            uint32_t b1[4][2], b2[4][2];
            #pragma unroll
            for (int jp = 0; jp < 2; jp++) {
                const uint32_t r0 = ldm_b_addr(Bb + (uint32_t)(wn * 32 + jp * 16) * 80 + koff, lane);
                uint32_t t[4];
                ldm_x4(t, r0);
                b1[2 * jp][0] = t[0]; b1[2 * jp][1] = t[1];
                b1[2 * jp + 1][0] = t[2]; b1[2 * jp + 1][1] = t[3];
                ldm_x4(t, r0 + BSLAB);
                b2[2 * jp][0] = t[0]; b2[2 * jp][1] = t[1];
                b2[2 * jp + 1][0] = t[2]; b2[2 * jp + 1][1] = t[3];
            }
            #pragma unroll
            for (int i = 0; i < MI; i++)
                #pragma unroll
                for (int j = 0; j < 4; j++) {
                    imma16832(acc1[i][j], a1[i], b1[j]);
                    imma16832(acc2[i][j], a1[i], b2[j]);
                    imma16832(acc2[i][j], a2[i], b1[j]);
                }
        }
        __syncthreads();
    }

    // --------------- epilogue ---------------
    float* sf = reinterpret_cast<float*>(smem);
    if (QOUT) {
        for (int i2 = tid; i2 < MT; i2 += NTHR) sf[i2] = 0.f;
        __syncthreads();
    }
    float sbv[4][2], bv[4][2];
    #pragma unroll
    for (int j = 0; j < 4; j++) {
        const int col0 = o0 + wn * 32 + j * 8 + q * 2;
        sbv[j][0] = Bs[col0];     sbv[j][1] = Bs[col0 + 1];
        bv[j][0]  = bias[col0];   bv[j][1]  = bias[col0 + 1];
    }
    #pragma unroll
    for (int i = 0; i < MI; i++) {
        #pragma unroll
        for (int h = 0; h < 2; h++) {
            const int lrow = wm * MI * 16 + i * 16 + g + h * 8;
            const float sa = As[rbase + lrow] * (1.f / QDEN);
            float rmax = 0.f;
            #pragma unroll
            for (int j = 0; j < 4; j++) {
                float t0 = 16384.f * (float)acc1[i][j][h * 2 + 0] + 128.f * (float)acc2[i][j][h * 2 + 0];
                float t1 = 16384.f * (float)acc1[i][j][h * 2 + 1] + 128.f * (float)acc2[i][j][h * 2 + 1];
                float v0 = sa * sbv[j][0] * t0 + bv[j][0];
                float v1 = sa * sbv[j][1] * t1 + bv[j][1];
                if (LRELU_) { v0 = lrelu(v0); v1 = lrelu(v1); }
                acc1[i][j][h * 2 + 0] = __float_as_int(v0);
                acc1[i][j][h * 2 + 1] = __float_as_int(v1);
                rmax = fmaxf(rmax, fmaxf(fabsf(v0), fabsf(v1)));
            }
            if (QOUT) atomicMax(reinterpret_cast<int*>(&sf[lrow]), __float_as_int(rmax));
        }
    }
    if (QOUT) {
        __syncthreads();
        #pragma unroll
        for (int i = 0; i < MI; i++) {
            #pragma unroll
            for (int h = 0; h < 2; h++) {
                const int lrow = wm * MI * 16 + i * 16 + g + h * 8;
                const int grow = rbase + lrow;
                const float mx = sf[lrow];
                const float inv = QMAX / fmaxf(mx, 1e-20f);
                if (wn == 0 && q == 0) Os[grow] = mx;
                #pragma unroll
                for (int j = 0; j < 4; j++) {
                    const int col0 = o0 + wn * 32 + j * 8 + q * 2;
                    float v0 = __int_as_float(acc1[i][j][h * 2 + 0]);
                    float v1 = __int_as_float(acc1[i][j][h * 2 + 1]);
                    int p1, p2, r1, r2;
                    quant2(v0, inv, p1, p2);
                    quant2(v1, inv, r1, r2);
                    char2 o1; o1.x = (char)p1; o1.y = (char)r1;
                    char2 o2; o2.x = (char)p2; o2.y = (char)r2;
                    *reinterpret_cast<char2*>(Oq1 + (size_t)grow * OC + col0) = o1;
                    *reinterpret_cast<char2*>(Oq2 + (size_t)grow * OC + col0) = o2;
                }
            }
        }
    } else {
        #pragma unroll
        for (int i = 0; i < MI; i++) {
            #pragma unroll
            for (int h = 0; h < 2; h++) {
                const int lrow = wm * MI * 16 + i * 16 + g + h * 8;
                const int grow = rbase + lrow;
                #pragma unroll
                for (int j = 0; j < 4; j++) {
                    const int col0 = o0 + wn * 32 + j * 8 + q * 2;
                    float2 v;
                    v.x = __int_as_float(acc1[i][j][h * 2 + 0]);
                    v.y = __int_as_float(acc1[i][j][h * 2 + 1]);
                    *reinterpret_cast<float2*>(Of + (size_t)grow * OC + col0) = v;
                }
            }
        }
    }
}

// ---------------------------------------------------------------------------
// sigma[s] = wsig . dequant(f[s]) + bsig  (warp per sample)
// ---------------------------------------------------------------------------
__global__ void sigma_q(const int8_t* __restrict__ A1, const int8_t* __restrict__ A2,
                        const float* __restrict__ As, const float* __restrict__ wsig,
                        const float* __restrict__ bsig, float* __restrict__ out) {
    int s = (blockIdx.x * blockDim.x + threadIdx.x) >> 5;
    int lane = threadIdx.x & 31;
    if (s >= S_TOT) return;
    const char4* p1 = reinterpret_cast<const char4*>(A1 + (size_t)s * HID);
    const char4* p2 = reinterpret_cast<const char4*>(A2 + (size_t)s * HID);
    float acc = 0.f;
    #pragma unroll
    for (int t = 0; t < 2; t++) {
        int idx = lane + 32 * t;
        char4 c1 = p1[idx];
        char4 c2 = p2[idx];
        int k = idx * 4;
        acc += (float)(c1.x * 128 + c2.x) * wsig[k + 0];
        acc += (float)(c1.y * 128 + c2.y) * wsig[k + 1];
        acc += (float)(c1.z * 128 + c2.z) * wsig[k + 2];
        acc += (float)(c1.w * 128 + c2.w) * wsig[k + 3];
    }
    #pragma unroll
    for (int off = 16; off; off >>= 1) acc += __shfl_xor_sync(0xFFFFFFFFu, acc, off);
    if (lane == 0) out[s] = acc * (As[s] * (1.f / QMAX)) + bsig[0];
}

// ---------------------------------------------------------------------------
// bf16x3 GEMM / implicit-GEMM conv (256 threads, ldmatrix frags) — CNN.
// ---------------------------------------------------------------------------
template<int TAPS, int K, int NT, bool LRELU_, bool SPLIT_OUT, bool HAS_BIAS,
         bool HAS_RES, bool HAS_MOD>
__global__ void __launch_bounds__(256)
mma_gemm(const __nv_bfloat16* __restrict__ Ahi, const __nv_bfloat16* __restrict__ Alo,
         const __nv_bfloat16* __restrict__ Bhi, const __nv_bfloat16* __restrict__ Blo,
         const float* __restrict__ bias,
         const __nv_bfloat16* __restrict__ ResH, const __nv_bfloat16* __restrict__ ResL,
         const float* __restrict__ zc, int modoff,
         __nv_bfloat16* __restrict__ Chi, __nv_bfloat16* __restrict__ Clo,
         float* __restrict__ Cf, int OC) {
    extern __shared__ char smem[];
    constexpr int KCH    = K / 32;
    constexpr int NCHUNK = TAPS * KCH;
    constexpr int ASLAB  = 128 * 80;
    constexpr int BSLAB  = NT * 80;
    constexpr int BOFF   = 2 * ASLAB;
    constexpr int BUF    = 2 * ASLAB + 2 * BSLAB;
    constexpr int WN     = NT / 32;
    constexpr int MI     = WN;
    constexpr int MWT    = 16 * MI;
    constexpr size_t BTAP = (TAPS == 9) ? (size_t)HID * K : 0;

    const uint32_t sb = smem_u32(smem);
    const int tid = threadIdx.x;
    const int lane = tid & 31, wid = tid >> 5;
    const int wn = wid % WN, wm = wid / WN;
    const int g = lane >> 2, q = lane & 3;
    const int o0 = blockIdx.y * NT;
    const int rbase = blockIdx.x * 128;

    auto load_chunk = [&](int buf, int chunk) {
        const int tap = (TAPS == 9) ? (chunk / KCH) : 0;
        const int k0  = ((TAPS == 9) ? (chunk - tap * KCH) : chunk) * 32;
        const uint32_t base = sb + buf * BUF;
        #pragma unroll
        for (int t = 0; t < 2; t++) {
            const int idx = tid + t * 256;
            const int row = idx >> 2, c = idx & 3;
            uint32_t sz = 16;
            size_t grow;
            if (TAPS == 9) {
                const int dy = tap / 3 - 1, dx = tap % 3 - 1;
                const int py = (int)blockIdx.x + dy, px = row + dx;
                const bool ok = (py >= 0) && (py < HH) && (px >= 0) && (px < WW);
                sz = ok ? 16u : 0u;
                grow = ok ? (size_t)(py * WW + px) : 0;
            } else {
                grow = (size_t)(rbase + row);
            }
            const size_t go = grow * K + k0 + c * 8;
            const uint32_t d = base + row * 80 + c * 16;
            cpa16z(d,         Ahi + go, sz);
            cpa16z(d + ASLAB, Alo + go, sz);
        }
        const __nv_bfloat16* bh = Bhi + (size_t)tap * BTAP;
        const __nv_bfloat16* bl = Blo + (size_t)tap * BTAP;
        for (int idx = tid; idx < NT * 4; idx += 256) {
            const int row = idx >> 2, c = idx & 3;
            const size_t go = (size_t)(o0 + row) * K + k0 + c * 8;
            const uint32_t d = base + BOFF + row * 80 + c * 16;
            cpa16z(d,         bh + go, 16);
            cpa16z(d + BSLAB, bl + go, 16);
        }
        asm volatile("cp.async.commit_group;" ::: "memory");
    };

    float acc[MI][4][4];
    #pragma unroll
    for (int i = 0; i < MI; i++)
        #pragma unroll
        for (int j = 0; j < 4; j++)
            #pragma unroll
            for (int r = 0; r < 4; r++) acc[i][j][r] = 0.f;

    load_chunk(0, 0);
    for (int cc = 0; cc < NCHUNK; cc++) {
        if (cc + 1 < NCHUNK) {
            load_chunk((cc + 1) & 1, cc + 1);
            asm volatile("cp.async.wait_group 1;" ::: "memory");
        } else {
            asm volatile("cp.async.wait_group 0;" ::: "memory");
        }
        __syncthreads();
        const uint32_t Ab = sb + (cc & 1) * BUF;
        const uint32_t Bb = Ab + BOFF;
        #pragma unroll
        for (int kk = 0; kk < 2; kk++) {
            const int koff = kk * 32;
            uint32_t ah[MI][4], al[MI][4];
            #pragma unroll
            for (int i = 0; i < MI; i++) {
                const uint32_t r0 = ldm_a_addr(Ab + (uint32_t)(wm * MWT + i * 16) * 80 + koff, lane);
                ldm_x4(ah[i], r0);
                ldm_x4(al[i], r0 + ASLAB);
            }
            uint32_t bh[4][2], bl[4][2];
            #pragma unroll
            for (int jp = 0; jp < 2; jp++) {
                const uint32_t r0 = ldm_b_addr(Bb + (uint32_t)(wn * 32 + jp * 16) * 80 + koff, lane);
                uint32_t t[4];
                ldm_x4(t, r0);
                bh[2 * jp][0] = t[0]; bh[2 * jp][1] = t[1];
                bh[2 * jp + 1][0] = t[2]; bh[2 * jp + 1][1] = t[3];
                ldm_x4(t, r0 + BSLAB);
                bl[2 * jp][0] = t[0]; bl[2 * jp][1] = t[1];
                bl[2 * jp + 1][0] = t[2]; bl[2 * jp + 1][1] = t[3];
            }
            #pragma unroll
            for (int i = 0; i < MI; i++)
                #pragma unroll
                for (int j = 0; j < 4; j++) {
                    mma16816(acc[i][j], ah[i], bh[j]);
                    mma16816(acc[i][j], al[i], bh[j]);
                    mma16816(acc[i][j], ah[i], bl[j]);
                }
        }
        __syncthreads();
    }

    #pragma unroll
    for (int j = 0; j < 4; j++) {
        const int col0 = o0 + wn * 32 + j * 8 + q * 2;
        const float b0 = HAS_BIAS ? bias[col0]     : 0.f;
        const float b1 = HAS_BIAS ? bias[col0 + 1] : 0.f;
        float sc0 = 1.f, sc1 = 1.f, sh0 = 0.f, sh1 = 0.f;
        if (HAS_MOD) {
            sc0 = zc[modoff + col0] + 1.f;       sc1 = zc[modoff + col0 + 1] + 1.f;
            sh0 = zc[modoff + HID + col0];       sh1 = zc[modoff + HID + col0 + 1];
        }
        #pragma unroll
        for (int i = 0; i < MI; i++) {
            #pragma unroll
            for (int h = 0; h < 2; h++) {
                const int row = rbase + wm * MWT + i * 16 + g + h * 8;
                float v0 = acc[i][j][h * 2 + 0] + b0;
                float v1 = acc[i][j][h * 2 + 1] + b1;
                if (HAS_RES) {
                    __nv_bfloat162 rh = *reinterpret_cast<const __nv_bfloat162*>(ResH + (size_t)row * OC + col0);
                    __nv_bfloat162 rl = *reinterpret_cast<const __nv_bfloat162*>(ResL + (size_t)row * OC + col0);
                    v0 += __bfloat162float(rh.x) + __bfloat162float(rl.x);
                    v1 += __bfloat162float(rh.y) + __bfloat162float(rl.y);
                }
                if (HAS_MOD) { v0 = v0 * sc0 + sh0; v1 = v1 * sc1 + sh1; }
                if (LRELU_)  { v0 = lrelu(v0); v1 = lrelu(v1); }
                if (SPLIT_OUT) {
                    __nv_bfloat162 hp = __floats2bfloat162_rn(v0, v1);
                    float r0 = v0 - __bfloat162float(hp.x);
                    float r1 = v1 - __bfloat162float(hp.y);
                    __nv_bfloat162 lp = __floats2bfloat162_rn(r0, r1);
                    *reinterpret_cast<__nv_bfloat162*>(Chi + (size_t)row * OC + col0) = hp;
                    *reinterpret_cast<__nv_bfloat162*>(Clo + (size_t)row * OC + col0) = lp;
                } else {
                    float2 v = {v0, v1};
                    *reinterpret_cast<float2*>(Cf + (size_t)row * OC + col0) = v;
                }
            }
        }
    }
}

// ---------------------------------------------------------------------------
// Volumetric compositing -> feat (pixel-major, bf16 hi/lo)
// ---------------------------------------------------------------------------
__global__ void composite_kernel(const float* __restrict__ sigma, const float* __restrict__ dists,
                                 const float* __restrict__ cbuf,
                                 __nv_bfloat16* __restrict__ feath,
                                 __nv_bfloat16* __restrict__ featl) {
    int pix = blockIdx.x;
    int t = threadIdx.x;
    __shared__ float wgt[MM];
    if (t == 0) {
        float T = 1.f;
        #pragma unroll
        for (int m = 0; m < MM; m++) {
            float sg = sigma[pix * MM + m];
            sg = sg > 0.f ? sg : 0.f;
            float a = 1.f - expf(-sg * dists[pix * MM + m]);
            wgt[m] = a * T;
            T *= (1.f - a + 1e-10f);
        }
    }
    __syncthreads();
    float acc = 0.f;
    #pragma unroll
    for (int m = 0; m < MM; m++)
        acc += wgt[m] * cbuf[(size_t)(pix * MM + m) * COL + t];
    split_store(acc, feath, featl, (size_t)pix * COL + t);
}

// ---------------------------------------------------------------------------
// Final 1x1 conv to 3 channels (warp per pixel)
// ---------------------------------------------------------------------------
__global__ void final_conv(const __nv_bfloat16* __restrict__ InH,
                           const __nv_bfloat16* __restrict__ InL,
                           const float* __restrict__ w,
                           const float* __restrict__ b, float* __restrict__ out) {
    int warp = (blockIdx.x * blockDim.x + threadIdx.x) >> 5;
    int lane = threadIdx.x & 31;
    if (warp >= HWPIX) return;
    const __nv_bfloat16* ph = InH + (size_t)warp * HID;
    const __nv_bfloat16* pl = InL + (size_t)warp * HID;
    float a0 = 0.f, a1 = 0.f, a2 = 0.f;
    #pragma unroll
    for (int t = 0; t < 8; t++) {
        int i = lane + 32 * t;
        float v = __bfloat162float(ph[i]) + __bfloat162float(pl[i]);
        a0 += v * w[i];
        a1 += v * w[HID + i];
        a2 += v * w[2 * HID + i];
    }
    #pragma unroll
    for (int off = 16; off; off >>= 1) {
        a0 += __shfl_xor_sync(0xFFFFFFFFu, a0, off);
        a1 += __shfl_xor_sync(0xFFFFFFFFu, a1, off);
        a2 += __shfl_xor_sync(0xFFFFFFFFu, a2, off);
    }
    if (lane == 0) {
        out[warp]             = a0 + b[0];
        out[HWPIX + warp]     = a1 + b[1];
        out[2 * HWPIX + warp] = a2 + b[2];
    }
}

// ---------------------------------------------------------------------------
// Launch
// ---------------------------------------------------------------------------
extern "C" void kernel_launch(void* const* d_in, const int* in_sizes, int n_in,
                              void* d_out, int out_size) {
    const float* x     = (const float*)d_in[0];
    const float* m     = (const float*)d_in[1];
    const float* z     = (const float*)d_in[2];
    const float* dists = (const float*)d_in[3];
    const float* w1    = (const float*)d_in[4];
    const float* b1    = (const float*)d_in[5];
    const float* wma   = (const float*)d_in[6];
    const float* ml_w  = (const float*)d_in[7];
    const float* ml_wa = (const float*)d_in[8];
    const float* ml_ba = (const float*)d_in[9];
    const float* ml_wb = (const float*)d_in[10];
    const float* ml_bb = (const float*)d_in[11];
    const float* wsig  = (const float*)d_in[12];
    const float* bsig  = (const float*)d_in[13];
    const float* wc    = (const float*)d_in[14];
    const float* bc    = (const float*)d_in[15];
    const float* wz    = (const float*)d_in[16];
    const float* bz    = (const float*)d_in[17];
    const float* c1_w  = (const float*)d_in[18];
    const float* c1_b  = (const float*)d_in[19];
    const float* c2a_w = (const float*)d_in[20];
    const float* c2a_b = (const float*)d_in[21];
    const float* c2b_w = (const float*)d_in[22];
    const float* c3a_w = (const float*)d_in[23];
    const float* c3a_b = (const float*)d_in[24];
    const float* c3b_w = (const float*)d_in[25];
    const float* c4a_w = (const float*)d_in[26];
    const float* c4a_b = (const float*)d_in[27];
    const float* c4b_w = (const float*)d_in[28];
    const float* c4b_b = (const float*)d_in[29];
    const float* c4_w  = (const float*)d_in[30];
    const float* c4_b  = (const float*)d_in[31];
    float* out = (float*)d_out;

    int8_t *xq1, *xq2, *aq1, *aq2, *bq1, *bq2;
    int8_t *w1q1, *w1q2, *wmq1, *wmq2, *wcq1, *wcq2;
    float *xs, *as, *bsc, *w1s, *wms, *wcs;
    __nv_bfloat16 *c3h, *c3l, *c1h, *c1l, *c4ah, *c4al, *c4bh, *c4bl;
    __nv_bfloat16 *yah, *yal, *ybh, *ybl, *ych, *ycl, *fth, *ftl;
    float *sig, *cb, *zcv, *be;
    cudaGetSymbolAddress((void**)&xq1, d_xq1);
    cudaGetSymbolAddress((void**)&xq2, d_xq2);
    cudaGetSymbolAddress((void**)&xs,  d_xs);
    cudaGetSymbolAddress((void**)&aq1, d_aq1);
    cudaGetSymbolAddress((void**)&aq2, d_aq2);
    cudaGetSymbolAddress((void**)&as,  d_as);
    cudaGetSymbolAddress((void**)&bq1, d_bq1);
    cudaGetSymbolAddress((void**)&bq2, d_bq2);
    cudaGetSymbolAddress((void**)&bsc, d_bsc);
    cudaGetSymbolAddress((void**)&w1q1, d_w1q1);
    cudaGetSymbolAddress((void**)&w1q2, d_w1q2);
    cudaGetSymbolAddress((void**)&w1s,  d_w1s);
    cudaGetSymbolAddress((void**)&wmq1, d_wmq1);
    cudaGetSymbolAddress((void**)&wmq2, d_wmq2);
    cudaGetSymbolAddress((void**)&wms,  d_wms);
    cudaGetSymbolAddress((void**)&wcq1, d_wcq1);
    cudaGetSymbolAddress((void**)&wcq2, d_wcq2);
    cudaGetSymbolAddress((void**)&wcs,  d_wcs);
    cudaGetSymbolAddress((void**)&c3h, d_c3h);
    cudaGetSymbolAddress((void**)&c3l, d_c3l);
    cudaGetSymbolAddress((void**)&c1h, d_c1h);
    cudaGetSymbolAddress((void**)&c1l, d_c1l);
    cudaGetSymbolAddress((void**)&c4ah, d_c4ah);
    cudaGetSymbolAddress((void**)&c4al, d_c4al);
    cudaGetSymbolAddress((void**)&c4bh, d_c4bh);
    cudaGetSymbolAddress((void**)&c4bl, d_c4bl);
    cudaGetSymbolAddress((void**)&yah, d_yah);
    cudaGetSymbolAddress((void**)&yal, d_yal);
    cudaGetSymbolAddress((void**)&ybh, d_ybh);
    cudaGetSymbolAddress((void**)&ybl, d_ybl);
    cudaGetSymbolAddress((void**)&ych, d_ych);
    cudaGetSymbolAddress((void**)&ycl, d_ycl);
    cudaGetSymbolAddress((void**)&fth, d_feath);
    cudaGetSymbolAddress((void**)&ftl, d_featl);
    cudaGetSymbolAddress((void**)&sig, d_sig);
    cudaGetSymbolAddress((void**)&cb,  d_cbuf);
    cudaGetSymbolAddress((void**)&zcv, d_zc);
    cudaGetSymbolAddress((void**)&be,  d_beta);

    const int TW = 9 * HID * HID;
    const int SMI_L = 2 * (2 * 64 * 80 + 2 * 256 * 80);   // 102400 (MT=64, NT=256)
    const int SMI_W = 2 * (2 * 128 * 80 + 2 * 64 * 80);   // 61440  (MT=128, NT=64)
    const int SM128 = 2 * (2 * 128 * 80 + 2 * 128 * 80);  // 81920  (CNN bf16)

    auto L1 = imma_gemm<512, 64, 256, KQ1, true,  true >;
    auto LH = imma_gemm<512, 64, 256, HID, true,  true >;
    auto LW = imma_gemm<256, 128, 64, HID, false, false>;
    auto GH  = mma_gemm<1, HID, 128, true,  true,  true,  false, false>;  // c4a
    auto GC1 = mma_gemm<1, COL, 128, true,  true,  true,  false, false>;  // c1
    auto CA  = mma_gemm<9, HID, 128, true,  true,  true,  false, false>;  // c2a/c3a
    auto CB  = mma_gemm<9, HID, 128, true,  true,  false, true,  true >;  // c2b/c3b
    auto C4B = mma_gemm<1, HID, 128, true,  true,  true,  true,  false>;  // c4b

    cudaFuncSetAttribute(L1,  cudaFuncAttributeMaxDynamicSharedMemorySize, SMI_L);
    cudaFuncSetAttribute(LH,  cudaFuncAttributeMaxDynamicSharedMemorySize, SMI_L);
    cudaFuncSetAttribute(LW,  cudaFuncAttributeMaxDynamicSharedMemorySize, SMI_W);
    cudaFuncSetAttribute(GH,  cudaFuncAttributeMaxDynamicSharedMemorySize, SM128);
    cudaFuncSetAttribute(GC1, cudaFuncAttributeMaxDynamicSharedMemorySize, SM128);
    cudaFuncSetAttribute(CA,  cudaFuncAttributeMaxDynamicSharedMemorySize, SM128);
    cudaFuncSetAttribute(CB,  cudaFuncAttributeMaxDynamicSharedMemorySize, SM128);
    cudaFuncSetAttribute(C4B, cudaFuncAttributeMaxDynamicSharedMemorySize, SM128);

    // --- minimal preps first; launch #6 (0-indexed 5) = L1 imma, so ncu
    // (-s 5 -c 1) captures a real GEMM this round ---
    prep_vec<<<448, 256>>>(z, ml_wa, ml_ba, ml_wb, ml_bb, wz, bz);        // 1
    prep_xq<<<S_TOT / 8, 256>>>(x, m);                                    // 2
    prep_w1q<<<HID / 8, 256>>>(w1, wma);                                  // 3
    prep_wmq<<<5 * HID / 8, 256>>>(ml_w);                                 // 4
    prep_wcq<<<COL / 8, 256>>>(wc);                                       // 5

    // --- MLP (int8 two-digit IMMA, ldmatrix frags, 512-thread CTAs) ---
    const int GR = S_TOT / 64;  // 4096
    L1<<<GR, 512, SMI_L>>>(xq1, xq2, xs, w1q1, w1q2, w1s, b1,
                           aq1, aq2, as, nullptr, HID);                   // 6 <-- ncu
    LH<<<GR, 512, SMI_L>>>(aq1, aq2, as, wmq1 + 0 * 65536, wmq2 + 0 * 65536, wms + 0,
                           be + 0,    bq1, bq2, bsc, nullptr, HID);
    LH<<<GR, 512, SMI_L>>>(bq1, bq2, bsc, wmq1 + 1 * 65536, wmq2 + 1 * 65536, wms + 256,
                           be + 256,  aq1, aq2, as, nullptr, HID);
    LH<<<GR, 512, SMI_L>>>(aq1, aq2, as, wmq1 + 2 * 65536, wmq2 + 2 * 65536, wms + 512,
                           be + 512,  bq1, bq2, bsc, nullptr, HID);
    sigma_q<<<S_TOT / 8, 256>>>(bq1, bq2, bsc, wsig, bsig, sig);
    LH<<<GR, 512, SMI_L>>>(bq1, bq2, bsc, wmq1 + 3 * 65536, wmq2 + 3 * 65536, wms + 768,
                           be + 768,  aq1, aq2, as, nullptr, HID);
    LH<<<GR, 512, SMI_L>>>(aq1, aq2, as, wmq1 + 4 * 65536, wmq2 + 4 * 65536, wms + 1024,
                           be + 1024, bq1, bq2, bsc, nullptr, HID);
    LW<<<S_TOT / 128, 256, SMI_W>>>(bq1, bq2, bsc, wcq1, wcq2, wcs, bc,
                                    nullptr, nullptr, nullptr, cb, COL);

    // --- CNN weight preps (moved after MLP; only needed before CNN) ---
    prep_tw_split<<<(TW + 255) / 256, 256>>>(c2a_w, c3h + 0 * TW, c3l + 0 * TW);
    prep_tw_split<<<(TW + 255) / 256, 256>>>(c2b_w, c3h + 1 * TW, c3l + 1 * TW);
    prep_tw_split<<<(TW + 255) / 256, 256>>>(c3a_w, c3h + 2 * TW, c3l + 2 * TW);
    prep_tw_split<<<(TW + 255) / 256, 256>>>(c3b_w, c3h + 3 * TW, c3l + 3 * TW);
    prep_pair<<<(HID * COL + 255) / 256, 256>>>(c1_w, c1h, c1l, HID * COL);
    prep_pair<<<(HID * HID + 255) / 256, 256>>>(c4a_w, c4ah, c4al, HID * HID);
    prep_pair<<<(HID * HID + 255) / 256, 256>>>(c4b_w, c4bh, c4bl, HID * HID);

    // --- compositing ---
    composite_kernel<<<HWPIX, 64>>>(sig, dists, cb, fth, ftl);

    // --- CNN (bf16x3 implicit-GEMM mma) ---
    dim3 gC(HH, 2);
    GC1<<<gC, 256, SM128>>>(fth, ftl, c1h, c1l, c1_b, nullptr, nullptr, nullptr, 0, yah, yal, nullptr, HID);
    CA <<<gC, 256, SM128>>>(yah, yal, c3h + 0 * TW, c3l + 0 * TW, c2a_b, nullptr, nullptr, nullptr, 0, ybh, ybl, nullptr, HID);
    CB <<<gC, 256, SM128>>>(ybh, ybl, c3h + 1 * TW, c3l + 1 * TW, nullptr, yah, yal, zcv, 0,   ych, ycl, nullptr, HID);
    CA <<<gC, 256, SM128>>>(ych, ycl, c3h + 2 * TW, c3l + 2 * TW, c3a_b, nullptr, nullptr, nullptr, 0, ybh, ybl, nullptr, HID);
    CB <<<gC, 256, SM128>>>(ybh, ybl, c3h + 3 * TW, c3l + 3 * TW, nullptr, ych, ycl, zcv, 512, yah, yal, nullptr, HID);
    GH <<<gC, 256, SM128>>>(yah, yal, c4ah, c4al, c4a_b, nullptr, nullptr, nullptr, 0, ybh, ybl, nullptr, HID);
    C4B<<<gC, 256, SM128>>>(ybh, ybl, c4bh, c4bl, c4b_b, yah, yal, nullptr, 0, ych, ycl, nullptr, HID);
    final_conv<<<HWPIX / 8, 256>>>(ych, ycl, c4_w, c4_b, out);

    (void)in_sizes; (void)n_in; (void)out_size;
}

// round 8
// speedup vs baseline: 3.2952x; 1.0762x over previous
#include <cuda_runtime.h>
#include <cuda_bf16.h>
#include <cstdint>

// ---------------------------------------------------------------------------
// Problem constants
// ---------------------------------------------------------------------------
#define HH      128
#define WW      128
#define MM      16
#define CIN     128
#define NC      7
#define HID     256
#define STY     256
#define COL     64
#define HWPIX   (HH * WW)            // 16384
#define S_TOT   (HWPIX * MM)         // 262144
#define KQ1     192                  // padded K for layer 1

#define QMAX    16256.0f             // 127 * 128
#define QDEN    (16256.0f * 16256.0f)

// ---------------------------------------------------------------------------
// Scratch (device globals)
// ---------------------------------------------------------------------------
__device__ int8_t d_xq1[(size_t)S_TOT * KQ1];
__device__ int8_t d_xq2[(size_t)S_TOT * KQ1];
__device__ float  d_xs[S_TOT];
__device__ int8_t d_aq1[(size_t)S_TOT * HID];
__device__ int8_t d_aq2[(size_t)S_TOT * HID];
__device__ float  d_as[S_TOT];
__device__ int8_t d_bq1[(size_t)S_TOT * HID];
__device__ int8_t d_bq2[(size_t)S_TOT * HID];
__device__ float  d_bsc[S_TOT];
__device__ int8_t d_w1q1[HID * KQ1];
__device__ int8_t d_w1q2[HID * KQ1];
__device__ float  d_w1s[HID];
__device__ int8_t d_wmq1[5 * HID * HID];
__device__ int8_t d_wmq2[5 * HID * HID];
__device__ float  d_wms[5 * HID];
__device__ int8_t d_wcq1[COL * HID];
__device__ int8_t d_wcq2[COL * HID];
__device__ float  d_wcs[COL];
// CNN: fp transposed 3x3 weights, runtime-requantized int8 weights, scales
__device__ float  d_wt3f[4 * 9 * HID * HID];     // [conv][tap][O][K] fp32
__device__ int8_t d_cwq1[9 * HID * HID];
__device__ int8_t d_cwq2[9 * HID * HID];
__device__ float  d_cts[HID];
__device__ float  d_camax[7 * HID];
// CNN activations: bf16 hi/lo pairs + int8 quantized planes
__device__ __nv_bfloat16 d_yah[HWPIX * HID];
__device__ __nv_bfloat16 d_yal[HWPIX * HID];
__device__ __nv_bfloat16 d_ybh[HWPIX * HID];
__device__ __nv_bfloat16 d_ybl[HWPIX * HID];
__device__ __nv_bfloat16 d_ych[HWPIX * HID];
__device__ __nv_bfloat16 d_ycl[HWPIX * HID];
__device__ __nv_bfloat16 d_feath[HWPIX * COL];
__device__ __nv_bfloat16 d_featl[HWPIX * COL];
__device__ int8_t d_cq1[HWPIX * HID];
__device__ int8_t d_cq2[HWPIX * HID];
__device__ float d_sig[S_TOT];
__device__ float d_cbuf[(size_t)S_TOT * COL];
__device__ float d_alpha[5 * HID];
__device__ float d_beta[5 * HID];
__device__ float d_zc[4 * HID];

static __device__ __forceinline__ float lrelu(float v) {
    return v > 0.f ? v : 0.2f * v;
}

static __device__ __forceinline__ uint32_t smem_u32(const void* p) {
    uint32_t a;
    asm("{ .reg .u64 t; cvta.to.shared.u64 t, %1; cvt.u32.u64 %0, t; }" : "=r"(a) : "l"(p));
    return a;
}

static __device__ __forceinline__ void cpa16z(uint32_t dst, const void* src, uint32_t sz) {
    asm volatile("cp.async.cg.shared.global [%0], [%1], 16, %2;"
                 :: "r"(dst), "l"(src), "r"(sz));
}

static __device__ __forceinline__ void ldm_x4(uint32_t* r, uint32_t addr) {
    asm volatile("ldmatrix.sync.aligned.m8n8.x4.shared.b16 {%0,%1,%2,%3}, [%4];"
                 : "=r"(r[0]), "=r"(r[1]), "=r"(r[2]), "=r"(r[3]) : "r"(addr));
}

static __device__ __forceinline__ void imma16832(int* d, const uint32_t* a, const uint32_t* b) {
    asm volatile(
        "mma.sync.aligned.m16n8k32.row.col.s32.s8.s8.s32 "
        "{%0,%1,%2,%3}, {%4,%5,%6,%7}, {%8,%9}, {%0,%1,%2,%3};"
        : "+r"(d[0]), "+r"(d[1]), "+r"(d[2]), "+r"(d[3])
        : "r"(a[0]), "r"(a[1]), "r"(a[2]), "r"(a[3]), "r"(b[0]), "r"(b[1]));
}

static __device__ __forceinline__ uint32_t ldm_a_addr(uint32_t base, int lane) {
    return base + (uint32_t)(lane & 15) * 80 + (uint32_t)((lane >> 4) << 4);
}
static __device__ __forceinline__ uint32_t ldm_b_addr(uint32_t base, int lane) {
    const int n = (lane & 7) + ((lane >= 16) ? 8 : 0);
    const int k16 = ((lane >> 3) & 1) << 4;
    return base + (uint32_t)n * 80 + (uint32_t)k16;
}

static __device__ __forceinline__ void quant2(float v, float inv, int& q1, int& q2) {
    float qf = rintf(v * inv);
    int   q  = (int)qf;
    q1 = (int)rintf(qf * (1.f / 128.f));
    q2 = q - (q1 << 7);
}

static __device__ __forceinline__ void amax_atomic(float* addr, float v) {
    atomicMax(reinterpret_cast<int*>(addr), __float_as_int(v));
}

// ---------------------------------------------------------------------------
// Prep kernels
// ---------------------------------------------------------------------------
__global__ void prep_vec(const float* __restrict__ z,
                         const float* __restrict__ wa, const float* __restrict__ ba,
                         const float* __restrict__ wb, const float* __restrict__ bb,
                         const float* __restrict__ wz, const float* __restrict__ bz) {
    int warp = (blockIdx.x * blockDim.x + threadIdx.x) >> 5;
    int lane = threadIdx.x & 31;
    if (warp >= 3584) return;
    const float* row; float bias; float* out;
    if (warp < 1280)      { row = wa + (size_t)warp * STY; bias = ba[warp]; out = d_alpha + warp; }
    else if (warp < 2560) { int i = warp - 1280; row = wb + (size_t)i * STY; bias = bb[i]; out = d_beta + i; }
    else                  { int i = warp - 2560; row = wz + (size_t)i * STY; bias = bz[i]; out = d_zc + i; }
    float acc = 0.f;
    #pragma unroll
    for (int t = 0; t < 8; t++) acc += z[lane + 32 * t] * row[lane + 32 * t];
    #pragma unroll
    for (int off = 16; off; off >>= 1) acc += __shfl_xor_sync(0xFFFFFFFFu, acc, off);
    if (lane == 0) *out = acc + bias;
}

static __device__ __forceinline__ float warp_amax(float a) {
    #pragma unroll
    for (int off = 16; off; off >>= 1) a = fmaxf(a, __shfl_xor_sync(0xFFFFFFFFu, a, off));
    return a;
}

__global__ void prep_xq(const float* __restrict__ x, const float* __restrict__ m) {
    int s = blockIdx.x * 8 + (threadIdx.x >> 5);
    int lane = threadIdx.x & 31;
    if (s >= S_TOT) return;
    float v[6];
    #pragma unroll
    for (int t = 0; t < 6; t++) {
        int c = lane + 32 * t;
        float val = 0.f;
        if (c < CIN)           val = x[(size_t)s * CIN + c];
        else if (c < CIN + NC) val = m[(size_t)s * NC + (c - CIN)];
        v[t] = val;
    }
    float am = 0.f;
    #pragma unroll
    for (int t = 0; t < 6; t++) am = fmaxf(am, fabsf(v[t]));
    am = warp_amax(am);
    if (lane == 0) d_xs[s] = am;
    float inv = QMAX / fmaxf(am, 1e-20f);
    #pragma unroll
    for (int t = 0; t < 6; t++) {
        int c = lane + 32 * t;
        int q1, q2; quant2(v[t], inv, q1, q2);
        d_xq1[(size_t)s * KQ1 + c] = (int8_t)q1;
        d_xq2[(size_t)s * KQ1 + c] = (int8_t)q2;
    }
}

__global__ void prep_w1q(const float* __restrict__ w1, const float* __restrict__ wma) {
    int o = blockIdx.x * 8 + (threadIdx.x >> 5);
    int lane = threadIdx.x & 31;
    if (o >= HID) return;
    float v[6];
    #pragma unroll
    for (int t = 0; t < 6; t++) {
        int c = lane + 32 * t;
        float val = 0.f;
        if (c < CIN)           val = w1[(size_t)o * CIN + c];
        else if (c < CIN + NC) val = wma[(size_t)o * NC + (c - CIN)];
        v[t] = val;
    }
    float am = 0.f;
    #pragma unroll
    for (int t = 0; t < 6; t++) am = fmaxf(am, fabsf(v[t]));
    am = warp_amax(am);
    if (lane == 0) d_w1s[o] = am;
    float inv = QMAX / fmaxf(am, 1e-20f);
    #pragma unroll
    for (int t = 0; t < 6; t++) {
        int c = lane + 32 * t;
        int q1, q2; quant2(v[t], inv, q1, q2);
        d_w1q1[(size_t)o * KQ1 + c] = (int8_t)q1;
        d_w1q2[(size_t)o * KQ1 + c] = (int8_t)q2;
    }
}

__global__ void prep_wmq(const float* __restrict__ mlw) {
    int r = blockIdx.x * 8 + (threadIdx.x >> 5);
    int lane = threadIdx.x & 31;
    if (r >= 5 * HID) return;
    int layer = r >> 8;
    float v[8];
    #pragma unroll
    for (int t = 0; t < 8; t++) {
        int k = lane + 32 * t;
        v[t] = mlw[(size_t)r * HID + k] * d_alpha[layer * HID + k];
    }
    float am = 0.f;
    #pragma unroll
    for (int t = 0; t < 8; t++) am = fmaxf(am, fabsf(v[t]));
    am = warp_amax(am);
    if (lane == 0) d_wms[r] = am;
    float inv = QMAX / fmaxf(am, 1e-20f);
    #pragma unroll
    for (int t = 0; t < 8; t++) {
        int k = lane + 32 * t;
        int q1, q2; quant2(v[t], inv, q1, q2);
        d_wmq1[(size_t)r * HID + k] = (int8_t)q1;
        d_wmq2[(size_t)r * HID + k] = (int8_t)q2;
    }
}

__global__ void prep_wcq(const float* __restrict__ wc) {
    int o = blockIdx.x * 8 + (threadIdx.x >> 5);
    int lane = threadIdx.x & 31;
    if (o >= COL) return;
    float v[8];
    #pragma unroll
    for (int t = 0; t < 8; t++) v[t] = wc[(size_t)o * HID + lane + 32 * t];
    float am = 0.f;
    #pragma unroll
    for (int t = 0; t < 8; t++) am = fmaxf(am, fabsf(v[t]));
    am = warp_amax(am);
    if (lane == 0) d_wcs[o] = am;
    float inv = QMAX / fmaxf(am, 1e-20f);
    #pragma unroll
    for (int t = 0; t < 8; t++) {
        int q1, q2; quant2(v[t], inv, q1, q2);
        d_wcq1[(size_t)o * HID + lane + 32 * t] = (int8_t)q1;
        d_wcq2[(size_t)o * HID + lane + 32 * t] = (int8_t)q2;
    }
}

// [O][K][9] -> [tap][O][K] fp32
__global__ void prep_twf(const float* __restrict__ w, float* __restrict__ out) {
    int idx = blockIdx.x * blockDim.x + threadIdx.x;
    if (idx >= 9 * HID * HID) return;
    int tap = idx / (HID * HID);
    int ok  = idx - tap * (HID * HID);
    out[idx] = w[(size_t)ok * 9 + tap];
}

__global__ void reset_amax() {
    int idx = blockIdx.x * blockDim.x + threadIdx.x;
    if (idx < 7 * HID) d_camax[idx] = 0.f;
}

// ---------------------------------------------------------------------------
// Runtime CNN weight requant: fold per-channel act amax into weights.
// warp per out-channel o: u[tap][k] = w[tap][o][k]*camax_in[k];
// Ts[o] = amax(u)/QDEN; wq = 2-digit quant of u.
// ---------------------------------------------------------------------------
template<int TAPS, int K>
__global__ void wreq(const float* __restrict__ wsrc, const float* __restrict__ camax_in,
                     int8_t* __restrict__ wq1, int8_t* __restrict__ wq2,
                     float* __restrict__ Ts) {
    int o = blockIdx.x * 8 + (threadIdx.x >> 5);
    int lane = threadIdx.x & 31;
    if (o >= HID) return;
    const int E = TAPS * K;
    float am = 0.f;
    for (int e = lane; e < E; e += 32) {
        int tap = e / K, k = e - tap * K;
        float u = wsrc[(size_t)tap * (HID * K) + (size_t)o * K + k] * camax_in[k];
        am = fmaxf(am, fabsf(u));
    }
    am = warp_amax(am);
    if (lane == 0) Ts[o] = am / QDEN;
    float inv = QMAX / fmaxf(am, 1e-20f);
    for (int e = lane; e < E; e += 32) {
        int tap = e / K, k = e - tap * K;
        size_t idx = (size_t)tap * (HID * K) + (size_t)o * K + k;
        float u = wsrc[idx] * camax_in[k];
        int q1, q2; quant2(u, inv, q1, q2);
        wq1[idx] = (int8_t)q1;
        wq2[idx] = (int8_t)q2;
    }
}

// ---------------------------------------------------------------------------
// Activation quantization: bf16 pair -> int8 2-digit planes, per-channel scale
// ---------------------------------------------------------------------------
template<int C>
__global__ void quant_act(const __nv_bfloat16* __restrict__ hi,
                          const __nv_bfloat16* __restrict__ lo,
                          const float* __restrict__ camax,
                          int8_t* __restrict__ q1p, int8_t* __restrict__ q2p) {
    int idx = blockIdx.x * blockDim.x + threadIdx.x;
    if (idx >= HWPIX * C) return;
    int c = idx & (C - 1);
    float v = __bfloat162float(hi[idx]) + __bfloat162float(lo[idx]);
    float inv = QMAX / fmaxf(camax[c], 1e-20f);
    int q1, q2; quant2(v, inv, q1, q2);
    q1p[idx] = (int8_t)q1;
    q2p[idx] = (int8_t)q2;
}

// ---------------------------------------------------------------------------
// MLP int8 two-digit GEMM (unchanged from R7)
// ---------------------------------------------------------------------------
template<int NTHR, int MT, int NT, int K, bool LRELU_, bool QOUT>
__global__ void __launch_bounds__(NTHR)
imma_gemm(const int8_t* __restrict__ Aq1, const int8_t* __restrict__ Aq2,
          const float* __restrict__ As,
          const int8_t* __restrict__ Bq1, const int8_t* __restrict__ Bq2,
          const float* __restrict__ Bs,
          const float* __restrict__ bias,
          int8_t* __restrict__ Oq1, int8_t* __restrict__ Oq2, float* __restrict__ Os,
          float* __restrict__ Of, int OC) {
    extern __shared__ char smem[];
    constexpr int NCH   = K / 64;
    constexpr int ASLAB = MT * 80;
    constexpr int BSLAB = NT * 80;
    constexpr int BOFF  = 2 * ASLAB;
    constexpr int BUF   = 2 * ASLAB + 2 * BSLAB;
    constexpr int NW    = NTHR / 32;
    constexpr int WN    = NT / 32;
    constexpr int WM    = NW / WN;
    constexpr int MI    = MT / (16 * WM);

    const uint32_t sb = smem_u32(smem);
    const int tid = threadIdx.x;
    const int lane = tid & 31, wid = tid >> 5;
    const int wn = wid % WN, wm = wid / WN;
    const int g = lane >> 2, q = lane & 3;
    const int rbase = blockIdx.x * MT;
    const int o0 = blockIdx.y * NT;

    auto load_chunk = [&](int buf, int c) {
        const uint32_t base = sb + buf * BUF;
        const int k0 = c * 64;
        for (int idx = tid; idx < MT * 4; idx += NTHR) {
            const int row = idx >> 2, cc = idx & 3;
            const size_t go = (size_t)(rbase + row) * K + k0 + cc * 16;
            const uint32_t d = base + row * 80 + cc * 16;
            cpa16z(d,         Aq1 + go, 16);
            cpa16z(d + ASLAB, Aq2 + go, 16);
        }
        for (int idx = tid; idx < NT * 4; idx += NTHR) {
            const int row = idx >> 2, cc = idx & 3;
            const size_t go = (size_t)(o0 + row) * K + k0 + cc * 16;
            const uint32_t d = base + BOFF + row * 80 + cc * 16;
            cpa16z(d,         Bq1 + go, 16);
            cpa16z(d + BSLAB, Bq2 + go, 16);
        }
        asm volatile("cp.async.commit_group;" ::: "memory");
    };

    int acc1[MI][4][4], acc2[MI][4][4];
    #pragma unroll
    for (int i = 0; i < MI; i++)
        #pragma unroll
        for (int j = 0; j < 4; j++)
            #pragma unroll
            for (int r = 0; r < 4; r++) { acc1[i][j][r] = 0; acc2[i][j][r] = 0; }

    load_chunk(0, 0);
    for (int c = 0; c < NCH; c++) {
        if (c + 1 < NCH) {
            load_chunk((c + 1) & 1, c + 1);
            asm volatile("cp.async.wait_group 1;" ::: "memory");
        } else {
            asm volatile("cp.async.wait_group 0;" ::: "memory");
        }
        __syncthreads();
        const uint32_t Ab = sb + (c & 1) * BUF;
        const uint32_t Bb = Ab + BOFF;
        #pragma unroll
        for (int kk = 0; kk < 2; kk++) {
            const int koff = kk * 32;
            uint32_t a1[MI][4], a2[MI][4];
            #pragma unroll
            for (int i = 0; i < MI; i++) {
                const uint32_t r0 = ldm_a_addr(Ab + (uint32_t)(wm * MI * 16 + i * 16) * 80 + koff, lane);
                ldm_x4(a1[i], r0);
                ldm_x4(a2[i], r0 + ASLAB);
            }
            uint32_t b1[4][2], b2[4][2];
            #pragma unroll
            for (int jp = 0; jp < 2; jp++) {
                const uint32_t r0 = ldm_b_addr(Bb + (uint32_t)(wn * 32 + jp * 16) * 80 + koff, lane);
                uint32_t t[4];
                ldm_x4(t, r0);
                b1[2 * jp][0] = t[0]; b1[2 * jp][1] = t[1];
                b1[2 * jp + 1][0] = t[2]; b1[2 * jp + 1][1] = t[3];
                ldm_x4(t, r0 + BSLAB);
                b2[2 * jp][0] = t[0]; b2[2 * jp][1] = t[1];
                b2[2 * jp + 1][0] = t[2]; b2[2 * jp + 1][1] = t[3];
            }
            #pragma unroll
            for (int i = 0; i < MI; i++)
                #pragma unroll
                for (int j = 0; j < 4; j++) {
                    imma16832(acc1[i][j], a1[i], b1[j]);
                    imma16832(acc2[i][j], a1[i], b2[j]);
                    imma16832(acc2[i][j], a2[i], b1[j]);
                }
        }
        __syncthreads();
    }

    float* sf = reinterpret_cast<float*>(smem);
    if (QOUT) {
        for (int i2 = tid; i2 < MT; i2 += NTHR) sf[i2] = 0.f;
        __syncthreads();
    }
    float sbv[4][2], bv[4][2];
    #pragma unroll
    for (int j = 0; j < 4; j++) {
        const int col0 = o0 + wn * 32 + j * 8 + q * 2;
        sbv[j][0] = Bs[col0];     sbv[j][1] = Bs[col0 + 1];
        bv[j][0]  = bias[col0];   bv[j][1]  = bias[col0 + 1];
    }
    #pragma unroll
    for (int i = 0; i < MI; i++) {
        #pragma unroll
        for (int h = 0; h < 2; h++) {
            const int lrow = wm * MI * 16 + i * 16 + g + h * 8;
            const float sa = As[rbase + lrow] * (1.f / QDEN);
            float rmax = 0.f;
            #pragma unroll
            for (int j = 0; j < 4; j++) {
                float t0 = 16384.f * (float)acc1[i][j][h * 2 + 0] + 128.f * (float)acc2[i][j][h * 2 + 0];
                float t1 = 16384.f * (float)acc1[i][j][h * 2 + 1] + 128.f * (float)acc2[i][j][h * 2 + 1];
                float v0 = sa * sbv[j][0] * t0 + bv[j][0];
                float v1 = sa * sbv[j][1] * t1 + bv[j][1];
                if (LRELU_) { v0 = lrelu(v0); v1 = lrelu(v1); }
                acc1[i][j][h * 2 + 0] = __float_as_int(v0);
                acc1[i][j][h * 2 + 1] = __float_as_int(v1);
                rmax = fmaxf(rmax, fmaxf(fabsf(v0), fabsf(v1)));
            }
            if (QOUT) amax_atomic(&sf[lrow], rmax);
        }
    }
    if (QOUT) {
        __syncthreads();
        #pragma unroll
        for (int i = 0; i < MI; i++) {
            #pragma unroll
            for (int h = 0; h < 2; h++) {
                const int lrow = wm * MI * 16 + i * 16 + g + h * 8;
                const int grow = rbase + lrow;
                const float mx = sf[lrow];
                const float inv = QMAX / fmaxf(mx, 1e-20f);
                if (wn == 0 && q == 0) Os[grow] = mx;
                #pragma unroll
                for (int j = 0; j < 4; j++) {
                    const int col0 = o0 + wn * 32 + j * 8 + q * 2;
                    float v0 = __int_as_float(acc1[i][j][h * 2 + 0]);
                    float v1 = __int_as_float(acc1[i][j][h * 2 + 1]);
                    int p1, p2, r1, r2;
                    quant2(v0, inv, p1, p2);
                    quant2(v1, inv, r1, r2);
                    char2 o1; o1.x = (char)p1; o1.y = (char)r1;
                    char2 o2; o2.x = (char)p2; o2.y = (char)r2;
                    *reinterpret_cast<char2*>(Oq1 + (size_t)grow * OC + col0) = o1;
                    *reinterpret_cast<char2*>(Oq2 + (size_t)grow * OC + col0) = o2;
                }
            }
        }
    } else {
        #pragma unroll
        for (int i = 0; i < MI; i++) {
            #pragma unroll
            for (int h = 0; h < 2; h++) {
                const int lrow = wm * MI * 16 + i * 16 + g + h * 8;
                const int grow = rbase + lrow;
                #pragma unroll
                for (int j = 0; j < 4; j++) {
                    const int col0 = o0 + wn * 32 + j * 8 + q * 2;
                    float2 v;
                    v.x = __int_as_float(acc1[i][j][h * 2 + 0]);
                    v.y = __int_as_float(acc1[i][j][h * 2 + 1]);
                    *reinterpret_cast<float2*>(Of + (size_t)grow * OC + col0) = v;
                }
            }
        }
    }
}

// ---------------------------------------------------------------------------
// CNN int8 two-digit conv (implicit GEMM over TAPS): 512 threads, 128x128 tile.
// v = Ts[o]*(16384*acc1 + 128*acc2); act scales folded into weights.
// ---------------------------------------------------------------------------
template<int TAPS, int K, bool HAS_BIAS, bool HAS_RES, bool HAS_MOD, bool DO_AMAX>
__global__ void __launch_bounds__(512)
conv_q(const int8_t* __restrict__ Aq1, const int8_t* __restrict__ Aq2,
       const int8_t* __restrict__ Wq1, const int8_t* __restrict__ Wq2,
       const float* __restrict__ Ts, const float* __restrict__ bias,
       const __nv_bfloat16* __restrict__ ResH, const __nv_bfloat16* __restrict__ ResL,
       const float* __restrict__ zc, int modoff,
       __nv_bfloat16* __restrict__ Chi, __nv_bfloat16* __restrict__ Clo,
       float* __restrict__ amax_out) {
    extern __shared__ char smem[];
    constexpr int KCH    = K / 64;
    constexpr int NCHUNK = TAPS * KCH;
    constexpr int ASLAB  = 128 * 80;
    constexpr int BSLAB  = 128 * 80;
    constexpr int BOFF   = 2 * ASLAB;
    constexpr int BUF    = 2 * ASLAB + 2 * BSLAB;
    constexpr int MI     = 2;   // WN=4, WM=4

    const uint32_t sb = smem_u32(smem);
    const int tid = threadIdx.x;
    const int lane = tid & 31, wid = tid >> 5;
    const int wn = wid & 3, wm = wid >> 2;
    const int g = lane >> 2, q = lane & 3;
    const int o0 = blockIdx.y * 128;
    const int py0 = blockIdx.x;          // image row

    auto load_chunk = [&](int buf, int chunk) {
        const int tap = (TAPS == 9) ? (chunk / KCH) : 0;
        const int k0  = ((TAPS == 9) ? (chunk - tap * KCH) : chunk) * 64;
        const uint32_t base = sb + buf * BUF;
        {   // A: 128 rows x 4 16B pieces, 1 per thread
            const int row = tid >> 2, cc = tid & 3;
            uint32_t sz = 16;
            int pix;
            if (TAPS == 9) {
                const int dy = tap / 3 - 1, dx = tap % 3 - 1;
                const int py = py0 + dy, px = row + dx;
                const bool ok = (py >= 0) && (py < HH) && (px >= 0) && (px < WW);
                sz = ok ? 16u : 0u;
                pix = ok ? (py * WW + px) : 0;
            } else {
                pix = py0 * WW + row;
            }
            const size_t go = (size_t)pix * K + k0 + cc * 16;
            const uint32_t d = base + row * 80 + cc * 16;
            cpa16z(d,         Aq1 + go, sz);
            cpa16z(d + ASLAB, Aq2 + go, sz);
        }
        {   // B: 128 rows x 4 pieces
            const int row = tid >> 2, cc = tid & 3;
            const size_t go = (size_t)tap * (HID * K) + (size_t)(o0 + row) * K + k0 + cc * 16;
            const uint32_t d = base + BOFF + row * 80 + cc * 16;
            cpa16z(d,         Wq1 + go, 16);
            cpa16z(d + BSLAB, Wq2 + go, 16);
        }
        asm volatile("cp.async.commit_group;" ::: "memory");
    };

    int acc1[MI][4][4], acc2[MI][4][4];
    #pragma unroll
    for (int i = 0; i < MI; i++)
        #pragma unroll
        for (int j = 0; j < 4; j++)
            #pragma unroll
            for (int r = 0; r < 4; r++) { acc1[i][j][r] = 0; acc2[i][j][r] = 0; }

    load_chunk(0, 0);
    for (int c = 0; c < NCHUNK; c++) {
        if (c + 1 < NCHUNK) {
            load_chunk((c + 1) & 1, c + 1);
            asm volatile("cp.async.wait_group 1;" ::: "memory");
        } else {
            asm volatile("cp.async.wait_group 0;" ::: "memory");
        }
        __syncthreads();
        const uint32_t Ab = sb + (c & 1) * BUF;
        const uint32_t Bb = Ab + BOFF;
        #pragma unroll
        for (int kk = 0; kk < 2; kk++) {
            const int koff = kk * 32;
            uint32_t a1[MI][4], a2[MI][4];
            #pragma unroll
            for (int i = 0; i < MI; i++) {
                const uint32_t r0 = ldm_a_addr(Ab + (uint32_t)(wm * 32 + i * 16) * 80 + koff, lane);
                ldm_x4(a1[i], r0);
                ldm_x4(a2[i], r0 + ASLAB);
            }
            uint32_t b1[4][2], b2[4][2];
            #pragma unroll
            for (int jp = 0; jp < 2; jp++) {
                const uint32_t r0 = ldm_b_addr(Bb + (uint32_t)(wn * 32 + jp * 16) * 80 + koff, lane);
                uint32_t t[4];
                ldm_x4(t, r0);
                b1[2 * jp][0] = t[0]; b1[2 * jp][1] = t[1];
                b1[2 * jp + 1][0] = t[2]; b1[2 * jp + 1][1] = t[3];
                ldm_x4(t, r0 + BSLAB);
                b2[2 * jp][0] = t[0]; b2[2 * jp][1] = t[1];
                b2[2 * jp + 1][0] = t[2]; b2[2 * jp + 1][1] = t[3];
            }
            #pragma unroll
            for (int i = 0; i < MI; i++)
                #pragma unroll
                for (int j = 0; j < 4; j++) {
                    imma16832(acc1[i][j], a1[i], b1[j]);
                    imma16832(acc2[i][j], a1[i], b2[j]);
                    imma16832(acc2[i][j], a2[i], b1[j]);
                }
        }
        __syncthreads();
    }

    // --------------- epilogue ---------------
    float* sch = reinterpret_cast<float*>(smem);
    if (DO_AMAX) {
        if (tid < 128) sch[tid] = 0.f;
        __syncthreads();
    }
    #pragma unroll
    for (int j = 0; j < 4; j++) {
        const int cl = wn * 32 + j * 8 + q * 2;
        const int colg = o0 + cl;
        const float t0 = Ts[colg], t1 = Ts[colg + 1];
        const float b0 = HAS_BIAS ? bias[colg]     : 0.f;
        const float b1 = HAS_BIAS ? bias[colg + 1] : 0.f;
        float sc0 = 1.f, sc1 = 1.f, sh0 = 0.f, sh1 = 0.f;
        if (HAS_MOD) {
            sc0 = zc[modoff + colg] + 1.f;       sc1 = zc[modoff + colg + 1] + 1.f;
            sh0 = zc[modoff + HID + colg];       sh1 = zc[modoff + HID + colg + 1];
        }
        float lm0 = 0.f, lm1 = 0.f;
        #pragma unroll
        for (int i = 0; i < MI; i++) {
            #pragma unroll
            for (int h = 0; h < 2; h++) {
                const int pix = py0 * WW + wm * 32 + i * 16 + g + h * 8;
                float v0 = t0 * (16384.f * (float)acc1[i][j][h * 2 + 0] + 128.f * (float)acc2[i][j][h * 2 + 0]) + b0;
                float v1 = t1 * (16384.f * (float)acc1[i][j][h * 2 + 1] + 128.f * (float)acc2[i][j][h * 2 + 1]) + b1;
                if (HAS_RES) {
                    __nv_bfloat162 rh = *reinterpret_cast<const __nv_bfloat162*>(ResH + (size_t)pix * HID + colg);
                    __nv_bfloat162 rl = *reinterpret_cast<const __nv_bfloat162*>(ResL + (size_t)pix * HID + colg);
                    v0 += __bfloat162float(rh.x) + __bfloat162float(rl.x);
                    v1 += __bfloat162float(rh.y) + __bfloat162float(rl.y);
                }
                if (HAS_MOD) { v0 = v0 * sc0 + sh0; v1 = v1 * sc1 + sh1; }
                v0 = lrelu(v0); v1 = lrelu(v1);
                if (DO_AMAX) { lm0 = fmaxf(lm0, fabsf(v0)); lm1 = fmaxf(lm1, fabsf(v1)); }
                __nv_bfloat162 hp = __floats2bfloat162_rn(v0, v1);
                float r0 = v0 - __bfloat162float(hp.x);
                float r1 = v1 - __bfloat162float(hp.y);
                __nv_bfloat162 lp = __floats2bfloat162_rn(r0, r1);
                *reinterpret_cast<__nv_bfloat162*>(Chi + (size_t)pix * HID + colg) = hp;
                *reinterpret_cast<__nv_bfloat162*>(Clo + (size_t)pix * HID + colg) = lp;
            }
        }
        if (DO_AMAX) {
            amax_atomic(&sch[cl], lm0);
            amax_atomic(&sch[cl + 1], lm1);
        }
    }
    if (DO_AMAX) {
        __syncthreads();
        if (tid < 128) amax_atomic(&amax_out[o0 + tid], sch[tid]);
    }
}

// ---------------------------------------------------------------------------
// sigma (warp per sample)
// ---------------------------------------------------------------------------
__global__ void sigma_q(const int8_t* __restrict__ A1, const int8_t* __restrict__ A2,
                        const float* __restrict__ As, const float* __restrict__ wsig,
                        const float* __restrict__ bsig, float* __restrict__ out) {
    int s = (blockIdx.x * blockDim.x + threadIdx.x) >> 5;
    int lane = threadIdx.x & 31;
    if (s >= S_TOT) return;
    const char4* p1 = reinterpret_cast<const char4*>(A1 + (size_t)s * HID);
    const char4* p2 = reinterpret_cast<const char4*>(A2 + (size_t)s * HID);
    float acc = 0.f;
    #pragma unroll
    for (int t = 0; t < 2; t++) {
        int idx = lane + 32 * t;
        char4 c1 = p1[idx];
        char4 c2 = p2[idx];
        int k = idx * 4;
        acc += (float)(c1.x * 128 + c2.x) * wsig[k + 0];
        acc += (float)(c1.y * 128 + c2.y) * wsig[k + 1];
        acc += (float)(c1.z * 128 + c2.z) * wsig[k + 2];
        acc += (float)(c1.w * 128 + c2.w) * wsig[k + 3];
    }
    #pragma unroll
    for (int off = 16; off; off >>= 1) acc += __shfl_xor_sync(0xFFFFFFFFu, acc, off);
    if (lane == 0) out[s] = acc * (As[s] * (1.f / QMAX)) + bsig[0];
}

// ---------------------------------------------------------------------------
// Compositing: block = image row; writes feat bf16 pair + per-channel amax
// ---------------------------------------------------------------------------
__global__ void composite_kernel(const float* __restrict__ sigma, const float* __restrict__ dists,
                                 const float* __restrict__ cbuf,
                                 __nv_bfloat16* __restrict__ feath,
                                 __nv_bfloat16* __restrict__ featl,
                                 float* __restrict__ amax_out) {
    __shared__ float wgt[WW * MM];
    __shared__ float sch[COL];
    const int row = blockIdx.x;
    const int tid = threadIdx.x;
    if (tid < WW) {
        const int pix = row * WW + tid;
        float T = 1.f;
        #pragma unroll
        for (int m = 0; m < MM; m++) {
            float sg = sigma[pix * MM + m];
            sg = sg > 0.f ? sg : 0.f;
            float a = 1.f - expf(-sg * dists[pix * MM + m]);
            wgt[tid * MM + m] = a * T;
            T *= (1.f - a + 1e-10f);
        }
    }
    if (tid < COL) sch[tid] = 0.f;
    __syncthreads();
    for (int e = tid; e < WW * COL; e += blockDim.x) {
        const int px = e >> 6, c = e & 63;
        const int pix = row * WW + px;
        float acc = 0.f;
        #pragma unroll
        for (int m = 0; m < MM; m++)
            acc += wgt[px * MM + m] * cbuf[(size_t)(pix * MM + m) * COL + c];
        __nv_bfloat16 h = __float2bfloat16(acc);
        feath[(size_t)pix * COL + c] = h;
        featl[(size_t)pix * COL + c] = __float2bfloat16(acc - __bfloat162float(h));
        amax_atomic(&sch[c], fabsf(acc));
    }
    __syncthreads();
    if (tid < COL) amax_atomic(&amax_out[tid], sch[tid]);
}

// ---------------------------------------------------------------------------
// Final 1x1 conv to 3 channels (warp per pixel)
// ---------------------------------------------------------------------------
__global__ void final_conv(const __nv_bfloat16* __restrict__ InH,
                           const __nv_bfloat16* __restrict__ InL,
                           const float* __restrict__ w,
                           const float* __restrict__ b, float* __restrict__ out) {
    int warp = (blockIdx.x * blockDim.x + threadIdx.x) >> 5;
    int lane = threadIdx.x & 31;
    if (warp >= HWPIX) return;
    const __nv_bfloat16* ph = InH + (size_t)warp * HID;
    const __nv_bfloat16* pl = InL + (size_t)warp * HID;
    float a0 = 0.f, a1 = 0.f, a2 = 0.f;
    #pragma unroll
    for (int t = 0; t < 8; t++) {
        int i = lane + 32 * t;
        float v = __bfloat162float(ph[i]) + __bfloat162float(pl[i]);
        a0 += v * w[i];
        a1 += v * w[HID + i];
        a2 += v * w[2 * HID + i];
    }
    #pragma unroll
    for (int off = 16; off; off >>= 1) {
        a0 += __shfl_xor_sync(0xFFFFFFFFu, a0, off);
        a1 += __shfl_xor_sync(0xFFFFFFFFu, a1, off);
        a2 += __shfl_xor_sync(0xFFFFFFFFu, a2, off);
    }
    if (lane == 0) {
        out[warp]             = a0 + b[0];
        out[HWPIX + warp]     = a1 + b[1];
        out[2 * HWPIX + warp] = a2 + b[2];
    }
}

// ---------------------------------------------------------------------------
// Launch
// ---------------------------------------------------------------------------
extern "C" void kernel_launch(void* const* d_in, const int* in_sizes, int n_in,
                              void* d_out, int out_size) {
    const float* x     = (const float*)d_in[0];
    const float* m     = (const float*)d_in[1];
    const float* z     = (const float*)d_in[2];
    const float* dists = (const float*)d_in[3];
    const float* w1    = (const float*)d_in[4];
    const float* b1    = (const float*)d_in[5];
    const float* wma   = (const float*)d_in[6];
    const float* ml_w  = (const float*)d_in[7];
    const float* ml_wa = (const float*)d_in[8];
    const float* ml_ba = (const float*)d_in[9];
    const float* ml_wb = (const float*)d_in[10];
    const float* ml_bb = (const float*)d_in[11];
    const float* wsig  = (const float*)d_in[12];
    const float* bsig  = (const float*)d_in[13];
    const float* wc    = (const float*)d_in[14];
    const float* bc    = (const float*)d_in[15];
    const float* wz    = (const float*)d_in[16];
    const float* bz    = (const float*)d_in[17];
    const float* c1_w  = (const float*)d_in[18];
    const float* c1_b  = (const float*)d_in[19];
    const float* c2a_w = (const float*)d_in[20];
    const float* c2a_b = (const float*)d_in[21];
    const float* c2b_w = (const float*)d_in[22];
    const float* c3a_w = (const float*)d_in[23];
    const float* c3a_b = (const float*)d_in[24];
    const float* c3b_w = (const float*)d_in[25];
    const float* c4a_w = (const float*)d_in[26];
    const float* c4a_b = (const float*)d_in[27];
    const float* c4b_w = (const float*)d_in[28];
    const float* c4b_b = (const float*)d_in[29];
    const float* c4_w  = (const float*)d_in[30];
    const float* c4_b  = (const float*)d_in[31];
    float* out = (float*)d_out;

    int8_t *xq1, *xq2, *aq1, *aq2, *bq1, *bq2;
    int8_t *w1q1, *w1q2, *wmq1, *wmq2, *wcq1, *wcq2, *cq1, *cq2, *cwq1, *cwq2;
    float *xs, *as, *bsc, *w1s, *wms, *wcs, *wt3f, *cts, *camax;
    __nv_bfloat16 *yah, *yal, *ybh, *ybl, *ych, *ycl, *fth, *ftl;
    float *sig, *cb, *zcv, *be;
    cudaGetSymbolAddress((void**)&xq1, d_xq1);
    cudaGetSymbolAddress((void**)&xq2, d_xq2);
    cudaGetSymbolAddress((void**)&xs,  d_xs);
    cudaGetSymbolAddress((void**)&aq1, d_aq1);
    cudaGetSymbolAddress((void**)&aq2, d_aq2);
    cudaGetSymbolAddress((void**)&as,  d_as);
    cudaGetSymbolAddress((void**)&bq1, d_bq1);
    cudaGetSymbolAddress((void**)&bq2, d_bq2);
    cudaGetSymbolAddress((void**)&bsc, d_bsc);
    cudaGetSymbolAddress((void**)&w1q1, d_w1q1);
    cudaGetSymbolAddress((void**)&w1q2, d_w1q2);
    cudaGetSymbolAddress((void**)&w1s,  d_w1s);
    cudaGetSymbolAddress((void**)&wmq1, d_wmq1);
    cudaGetSymbolAddress((void**)&wmq2, d_wmq2);
    cudaGetSymbolAddress((void**)&wms,  d_wms);
    cudaGetSymbolAddress((void**)&wcq1, d_wcq1);
    cudaGetSymbolAddress((void**)&wcq2, d_wcq2);
    cudaGetSymbolAddress((void**)&wcs,  d_wcs);
    cudaGetSymbolAddress((void**)&wt3f, d_wt3f);
    cudaGetSymbolAddress((void**)&cwq1, d_cwq1);
    cudaGetSymbolAddress((void**)&cwq2, d_cwq2);
    cudaGetSymbolAddress((void**)&cts,  d_cts);
    cudaGetSymbolAddress((void**)&camax, d_camax);
    cudaGetSymbolAddress((void**)&cq1, d_cq1);
    cudaGetSymbolAddress((void**)&cq2, d_cq2);
    cudaGetSymbolAddress((void**)&yah, d_yah);
    cudaGetSymbolAddress((void**)&yal, d_yal);
    cudaGetSymbolAddress((void**)&ybh, d_ybh);
    cudaGetSymbolAddress((void**)&ybl, d_ybl);
    cudaGetSymbolAddress((void**)&ych, d_ych);
    cudaGetSymbolAddress((void**)&ycl, d_ycl);
    cudaGetSymbolAddress((void**)&fth, d_feath);
    cudaGetSymbolAddress((void**)&ftl, d_featl);
    cudaGetSymbolAddress((void**)&sig, d_sig);
    cudaGetSymbolAddress((void**)&cb,  d_cbuf);
    cudaGetSymbolAddress((void**)&zcv, d_zc);
    cudaGetSymbolAddress((void**)&be,  d_beta);

    const int TWF = 9 * HID * HID;
    const int SMI_L = 2 * (2 * 64 * 80 + 2 * 256 * 80);   // 102400
    const int SMI_W = 2 * (2 * 128 * 80 + 2 * 64 * 80);   // 61440
    const int SMCV  = 2 * (2 * 128 * 80 + 2 * 128 * 80);  // 81920

    auto L1 = imma_gemm<512, 64, 256, KQ1, true,  true >;
    auto LH = imma_gemm<512, 64, 256, HID, true,  true >;
    auto LW = imma_gemm<256, 128, 64, HID, false, false>;
    auto CV1  = conv_q<1, COL, true,  false, false, true >;  // c1
    auto CVA  = conv_q<9, HID, true,  false, false, true >;  // c2a/c3a
    auto CVB  = conv_q<9, HID, false, true,  true,  true >;  // c2b/c3b
    auto CV4A = conv_q<1, HID, true,  false, false, true >;  // c4a
    auto CV4B = conv_q<1, HID, true,  true,  false, false>;  // c4b

    cudaFuncSetAttribute(L1,   cudaFuncAttributeMaxDynamicSharedMemorySize, SMI_L);
    cudaFuncSetAttribute(LH,   cudaFuncAttributeMaxDynamicSharedMemorySize, SMI_L);
    cudaFuncSetAttribute(LW,   cudaFuncAttributeMaxDynamicSharedMemorySize, SMI_W);
    cudaFuncSetAttribute(CV1,  cudaFuncAttributeMaxDynamicSharedMemorySize, SMCV);
    cudaFuncSetAttribute(CVA,  cudaFuncAttributeMaxDynamicSharedMemorySize, SMCV);
    cudaFuncSetAttribute(CVB,  cudaFuncAttributeMaxDynamicSharedMemorySize, SMCV);
    cudaFuncSetAttribute(CV4A, cudaFuncAttributeMaxDynamicSharedMemorySize, SMCV);
    cudaFuncSetAttribute(CV4B, cudaFuncAttributeMaxDynamicSharedMemorySize, SMCV);

    // --- preps ---
    prep_vec<<<448, 256>>>(z, ml_wa, ml_ba, ml_wb, ml_bb, wz, bz);
    prep_xq<<<S_TOT / 8, 256>>>(x, m);
    prep_w1q<<<HID / 8, 256>>>(w1, wma);
    prep_wmq<<<5 * HID / 8, 256>>>(ml_w);
    prep_wcq<<<COL / 8, 256>>>(wc);
    reset_amax<<<7, 256>>>();
    prep_twf<<<(TWF + 255) / 256, 256>>>(c2a_w, wt3f + 0 * TWF);
    prep_twf<<<(TWF + 255) / 256, 256>>>(c2b_w, wt3f + 1 * TWF);
    prep_twf<<<(TWF + 255) / 256, 256>>>(c3a_w, wt3f + 2 * TWF);
    prep_twf<<<(TWF + 255) / 256, 256>>>(c3b_w, wt3f + 3 * TWF);

    // --- MLP ---
    const int GR = S_TOT / 64;
    L1<<<GR, 512, SMI_L>>>(xq1, xq2, xs, w1q1, w1q2, w1s, b1, aq1, aq2, as, nullptr, HID);
    LH<<<GR, 512, SMI_L>>>(aq1, aq2, as, wmq1 + 0 * 65536, wmq2 + 0 * 65536, wms + 0,
                           be + 0,    bq1, bq2, bsc, nullptr, HID);
    LH<<<GR, 512, SMI_L>>>(bq1, bq2, bsc, wmq1 + 1 * 65536, wmq2 + 1 * 65536, wms + 256,
                           be + 256,  aq1, aq2, as, nullptr, HID);
    LH<<<GR, 512, SMI_L>>>(aq1, aq2, as, wmq1 + 2 * 65536, wmq2 + 2 * 65536, wms + 512,
                           be + 512,  bq1, bq2, bsc, nullptr, HID);
    sigma_q<<<S_TOT / 8, 256>>>(bq1, bq2, bsc, wsig, bsig, sig);
    LH<<<GR, 512, SMI_L>>>(bq1, bq2, bsc, wmq1 + 3 * 65536, wmq2 + 3 * 65536, wms + 768,
                           be + 768,  aq1, aq2, as, nullptr, HID);
    LH<<<GR, 512, SMI_L>>>(aq1, aq2, as, wmq1 + 4 * 65536, wmq2 + 4 * 65536, wms + 1024,
                           be + 1024, bq1, bq2, bsc, nullptr, HID);
    LW<<<S_TOT / 128, 256, SMI_W>>>(bq1, bq2, bsc, wcq1, wcq2, wcs, bc,
                                    nullptr, nullptr, nullptr, cb, COL);

    // --- compositing (+ camax[0]) ---
    composite_kernel<<<HH, 256>>>(sig, dists, cb, fth, ftl, camax + 0 * HID);

    // --- CNN (int8 IMMA with runtime scale folding) ---
    dim3 gC(HH, 2);
    const int NQ = (HWPIX * HID + 255) / 256;
    const int NQF = (HWPIX * COL + 255) / 256;

    quant_act<COL><<<NQF, 256>>>(fth, ftl, camax + 0 * HID, cq1, cq2);
    wreq<1, COL><<<32, 256>>>(c1_w, camax + 0 * HID, cwq1, cwq2, cts);
    CV1<<<gC, 512, SMCV>>>(cq1, cq2, cwq1, cwq2, cts, c1_b, nullptr, nullptr,
                           nullptr, 0, yah, yal, camax + 1 * HID);

    quant_act<HID><<<NQ, 256>>>(yah, yal, camax + 1 * HID, cq1, cq2);
    wreq<9, HID><<<32, 256>>>(wt3f + 0 * TWF, camax + 1 * HID, cwq1, cwq2, cts);
    CVA<<<gC, 512, SMCV>>>(cq1, cq2, cwq1, cwq2, cts, c2a_b, nullptr, nullptr,
                           nullptr, 0, ybh, ybl, camax + 2 * HID);

    quant_act<HID><<<NQ, 256>>>(ybh, ybl, camax + 2 * HID, cq1, cq2);
    wreq<9, HID><<<32, 256>>>(wt3f + 1 * TWF, camax + 2 * HID, cwq1, cwq2, cts);
    CVB<<<gC, 512, SMCV>>>(cq1, cq2, cwq1, cwq2, cts, nullptr, yah, yal,
                           zcv, 0, ych, ycl, camax + 3 * HID);

    quant_act<HID><<<NQ, 256>>>(ych, ycl, camax + 3 * HID, cq1, cq2);
    wreq<9, HID><<<32, 256>>>(wt3f + 2 * TWF, camax + 3 * HID, cwq1, cwq2, cts);
    CVA<<<gC, 512, SMCV>>>(cq1, cq2, cwq1, cwq2, cts, c3a_b, nullptr, nullptr,
                           nullptr, 0, ybh, ybl, camax + 4 * HID);

    quant_act<HID><<<NQ, 256>>>(ybh, ybl, camax + 4 * HID, cq1, cq2);
    wreq<9, HID><<<32, 256>>>(wt3f + 3 * TWF, camax + 4 * HID, cwq1, cwq2, cts);
    CVB<<<gC, 512, SMCV>>>(cq1, cq2, cwq1, cwq2, cts, nullptr, ych, ycl,
                           zcv, 512, yah, yal, camax + 5 * HID);

    quant_act<HID><<<NQ, 256>>>(yah, yal, camax + 5 * HID, cq1, cq2);
    wreq<1, HID><<<32, 256>>>(c4a_w, camax + 5 * HID, cwq1, cwq2, cts);
    CV4A<<<gC, 512, SMCV>>>(cq1, cq2, cwq1, cwq2, cts, c4a_b, nullptr, nullptr,
                            nullptr, 0, ybh, ybl, camax + 6 * HID);

    quant_act<HID><<<NQ, 256>>>(ybh, ybl, camax + 6 * HID, cq1, cq2);
    wreq<1, HID><<<32, 256>>>(c4b_w, camax + 6 * HID, cwq1, cwq2, cts);
    CV4B<<<gC, 512, SMCV>>>(cq1, cq2, cwq1, cwq2, cts, c4b_b, yah, yal,
                            nullptr, 0, ych, ycl, nullptr);

    final_conv<<<HWPIX / 8, 256>>>(ych, ycl, c4_w, c4_b, out);

    (void)in_sizes; (void)n_in; (void)out_size;
}